// round 1
// baseline (speedup 1.0000x reference)
#include <cuda_runtime.h>
#include <cuda_bf16.h>
#include <math.h>

#define H        512
#define IN_DIM   4096
#define POOL     4096
#define N_OBJ    8192
#define N_REL    65536
#define OBJ_CLS  151
#define REL_CLS  51
#define NUM_ITER 3

// ---------------- scratch (device globals; no allocations allowed) ----------
__device__ float g_obj_rep[N_OBJ * H];
__device__ float g_rel_rep[N_REL * H];     // reused as msg buffer in iterations
__device__ float g_vert[N_OBJ * H];
__device__ float g_edgeA[N_REL * H];
__device__ float g_edgeB[N_REL * H];
__device__ float g_vctx[N_OBJ * H];
__device__ float g_gi[N_REL * 3 * H];
__device__ float g_gh[N_REL * 3 * H];

// ---------------- generic NT SGEMM: C[M,N] = A[M,K] * B[N,K]^T + bias -------
// A row-major [M,K], B row-major [N,K]. M % 128 == 0, K % 16 == 0 required.
// N arbitrary (guarded). act: 0 = none, 1 = relu.
#define BM 128
#define BN 128
#define BK 16
#define TM 8
#define TN 8

__global__ __launch_bounds__(256)
void sgemm_nt(const float* __restrict__ A, const float* __restrict__ B,
              const float* __restrict__ bias, float* __restrict__ C,
              int M, int N, int K, int act)
{
    __shared__ float As[BK][BM + 4];
    __shared__ float Bs[BK][BN + 4];

    const int bx  = blockIdx.x;           // N tile
    const int by  = blockIdx.y;           // M tile
    const int tid = threadIdx.x;          // 0..255
    const int tx  = tid & 15;             // N position
    const int ty  = tid >> 4;             // M position

    const int lrow = tid >> 2;            // 0..63 (load row)
    const int lcol = (tid & 3) * 4;       // 0,4,8,12

    const float* Aptr = A + (size_t)(by * BM) * K;
    const float* Bptr = B + (size_t)(bx * BN) * K;

    float acc[TM][TN];
#pragma unroll
    for (int i = 0; i < TM; i++)
#pragma unroll
        for (int j = 0; j < TN; j++) acc[i][j] = 0.f;

    for (int k0 = 0; k0 < K; k0 += BK) {
        // load A tile (M rows always in range)
#pragma unroll
        for (int i = 0; i < 2; i++) {
            int r = lrow + i * 64;
            float4 v = *(const float4*)(Aptr + (size_t)r * K + k0 + lcol);
            As[lcol + 0][r] = v.x; As[lcol + 1][r] = v.y;
            As[lcol + 2][r] = v.z; As[lcol + 3][r] = v.w;
        }
        // load B tile (guard rows >= N)
#pragma unroll
        for (int i = 0; i < 2; i++) {
            int r  = lrow + i * 64;
            int gr = bx * BN + r;
            float4 v = make_float4(0.f, 0.f, 0.f, 0.f);
            if (gr < N) v = *(const float4*)(Bptr + (size_t)r * K + k0 + lcol);
            Bs[lcol + 0][r] = v.x; Bs[lcol + 1][r] = v.y;
            Bs[lcol + 2][r] = v.z; Bs[lcol + 3][r] = v.w;
        }
        __syncthreads();

#pragma unroll
        for (int kk = 0; kk < BK; kk++) {
            float a[TM], b[TN];
            float4 a0 = *(const float4*)&As[kk][ty * TM];
            float4 a1 = *(const float4*)&As[kk][ty * TM + 4];
            a[0]=a0.x; a[1]=a0.y; a[2]=a0.z; a[3]=a0.w;
            a[4]=a1.x; a[5]=a1.y; a[6]=a1.z; a[7]=a1.w;
            float4 b0 = *(const float4*)&Bs[kk][tx * TN];
            float4 b1 = *(const float4*)&Bs[kk][tx * TN + 4];
            b[0]=b0.x; b[1]=b0.y; b[2]=b0.z; b[3]=b0.w;
            b[4]=b1.x; b[5]=b1.y; b[6]=b1.z; b[7]=b1.w;
#pragma unroll
            for (int i = 0; i < TM; i++)
#pragma unroll
                for (int j = 0; j < TN; j++)
                    acc[i][j] = fmaf(a[i], b[j], acc[i][j]);
        }
        __syncthreads();
    }

#pragma unroll
    for (int i = 0; i < TM; i++) {
        int gm = by * BM + ty * TM + i;
#pragma unroll
        for (int j = 0; j < TN; j++) {
            int gn = bx * BN + tx * TN + j;
            if (gn < N) {
                float v = acc[i][j] + bias[gn];
                if (act) v = fmaxf(v, 0.f);
                C[(size_t)gm * N + gn] = v;
            }
        }
    }
}

// ---------------- GRU elementwise combine -----------------------------------
__device__ __forceinline__ float sigm(float x) { return 1.f / (1.f + expf(-x)); }

// out = GRU(gi, gh, h). gi/gh: [N,3H], h/out: [N,H]. n = N*H. out may alias h.
__global__ void gru_combine(const float* __restrict__ gi, const float* __restrict__ gh,
                            const float* __restrict__ h, float* __restrict__ out, int n)
{
    int idx = blockIdx.x * blockDim.x + threadIdx.x;
    if (idx >= n) return;
    int m = idx >> 9;            // /H
    int j = idx & (H - 1);
    size_t base = (size_t)m * (3 * H);
    float ir = gi[base + j], iz = gi[base + H + j], in_ = gi[base + 2 * H + j];
    float hr = gh[base + j], hz = gh[base + H + j], hn  = gh[base + 2 * H + j];
    float r  = sigm(ir + hr);
    float z  = sigm(iz + hz);
    float nn = tanhf(in_ + r * hn);
    out[idx] = (1.f - z) * nn + z * h[idx];
}

// h == 0 case: gh = b_hh (broadcast), out = (1-z)*n
__global__ void gru_combine_h0(const float* __restrict__ gi, const float* __restrict__ b_hh,
                               float* __restrict__ out, int n)
{
    int idx = blockIdx.x * blockDim.x + threadIdx.x;
    if (idx >= n) return;
    int m = idx >> 9;
    int j = idx & (H - 1);
    size_t base = (size_t)m * (3 * H);
    float ir = gi[base + j], iz = gi[base + H + j], in_ = gi[base + 2 * H + j];
    float hr = b_hh[j], hz = b_hh[H + j], hn = b_hh[2 * H + j];
    float r  = sigm(ir + hr);
    float z  = sigm(iz + hz);
    float nn = tanhf(in_ + r * hn);
    out[idx] = (1.f - z) * nn;
}

// ---------------- fused relation kernel --------------------------------------
// Per relation: gather sub/obj rows, 4 gates, msg = gs*sub + go*obj,
// scatter-add gout*edge -> vctx[sub], gin*edge -> vctx[obj].
__device__ __forceinline__ float dot4(float4 a, float4 b) {
    return a.x * b.x + a.y * b.y + a.z * b.z + a.w * b.w;
}

__global__ __launch_bounds__(128)
void relation_kernel(const float* __restrict__ vert, const float* __restrict__ edge,
                     const int* __restrict__ sub_idx, const int* __restrict__ obj_idx,
                     const float* __restrict__ w_sub, const float* __restrict__ b_sub,
                     const float* __restrict__ w_obj, const float* __restrict__ b_obj,
                     const float* __restrict__ w_out, const float* __restrict__ b_out,
                     const float* __restrict__ w_in,  const float* __restrict__ b_in,
                     float* __restrict__ msg, float* __restrict__ vctx)
{
    const int r = blockIdx.x;
    const int t = threadIdx.x;                // 0..127 (H/4 lanes)
    const int si = sub_idx[r];
    const int oi = obj_idx[r];

    float4 s4 = ((const float4*)(vert + (size_t)si * H))[t];
    float4 o4 = ((const float4*)(vert + (size_t)oi * H))[t];
    float4 e4 = ((const float4*)(edge + (size_t)r  * H))[t];

    float4 ws1 = ((const float4*)w_sub)[t];
    float4 ws2 = ((const float4*)(w_sub + H))[t];
    float4 wo1 = ((const float4*)w_obj)[t];
    float4 wo2 = ((const float4*)(w_obj + H))[t];
    float4 wu1 = ((const float4*)w_out)[t];
    float4 wu2 = ((const float4*)(w_out + H))[t];
    float4 wi1 = ((const float4*)w_in)[t];
    float4 wi2 = ((const float4*)(w_in + H))[t];

    float d0 = dot4(s4, ws1) + dot4(e4, ws2);   // sub gate
    float d1 = dot4(o4, wo1) + dot4(e4, wo2);   // obj gate
    float d2 = dot4(s4, wu1) + dot4(e4, wu2);   // out gate
    float d3 = dot4(o4, wi1) + dot4(e4, wi2);   // in gate

#pragma unroll
    for (int off = 16; off > 0; off >>= 1) {
        d0 += __shfl_down_sync(0xFFFFFFFFu, d0, off);
        d1 += __shfl_down_sync(0xFFFFFFFFu, d1, off);
        d2 += __shfl_down_sync(0xFFFFFFFFu, d2, off);
        d3 += __shfl_down_sync(0xFFFFFFFFu, d3, off);
    }
    __shared__ float red[4][4];
    __shared__ float gates[4];
    int warp = t >> 5, lane = t & 31;
    if (lane == 0) {
        red[warp][0] = d0; red[warp][1] = d1; red[warp][2] = d2; red[warp][3] = d3;
    }
    __syncthreads();
    if (t < 4) {
        float v = red[0][t] + red[1][t] + red[2][t] + red[3][t];
        float bb = (t == 0) ? b_sub[0] : (t == 1) ? b_obj[0] : (t == 2) ? b_out[0] : b_in[0];
        gates[t] = sigm(v + bb);
    }
    __syncthreads();

    float gs = gates[0], go = gates[1], gu = gates[2], gn = gates[3];

    float4 m4;
    m4.x = gs * s4.x + go * o4.x;
    m4.y = gs * s4.y + go * o4.y;
    m4.z = gs * s4.z + go * o4.z;
    m4.w = gs * s4.w + go * o4.w;
    ((float4*)(msg + (size_t)r * H))[t] = m4;

    float* vs = vctx + (size_t)si * H + t * 4;
    atomicAdd(vs + 0, gu * e4.x);
    atomicAdd(vs + 1, gu * e4.y);
    atomicAdd(vs + 2, gu * e4.z);
    atomicAdd(vs + 3, gu * e4.w);
    float* vo = vctx + (size_t)oi * H + t * 4;
    atomicAdd(vo + 0, gn * e4.x);
    atomicAdd(vo + 1, gn * e4.y);
    atomicAdd(vo + 2, gn * e4.z);
    atomicAdd(vo + 3, gn * e4.w);
}

// ---------------- host orchestration -----------------------------------------
static float* symaddr(const void* sym) {
    void* p = nullptr;
    cudaGetSymbolAddress(&p, sym);
    return (float*)p;
}

extern "C" void kernel_launch(void* const* d_in, const int* in_sizes, int n_in,
                              void* d_out, int out_size)
{
    const float* x            = (const float*)d_in[0];
    const float* union_feat   = (const float*)d_in[1];
    const int*   sub_idx      = (const int*)d_in[2];
    const int*   obj_idx      = (const int*)d_in[3];
    const float* w_obj_unary  = (const float*)d_in[4];
    const float* b_obj_unary  = (const float*)d_in[5];
    const float* w_edge_unary = (const float*)d_in[6];
    const float* b_edge_unary = (const float*)d_in[7];
    const float* node_w_ih    = (const float*)d_in[8];
    const float* node_w_hh    = (const float*)d_in[9];
    const float* node_b_ih    = (const float*)d_in[10];
    const float* node_b_hh    = (const float*)d_in[11];
    const float* edge_w_ih    = (const float*)d_in[12];
    const float* edge_w_hh    = (const float*)d_in[13];
    const float* edge_b_ih    = (const float*)d_in[14];
    const float* edge_b_hh    = (const float*)d_in[15];
    const float* w_sub_g      = (const float*)d_in[16];
    const float* b_sub_g      = (const float*)d_in[17];
    const float* w_obj_g      = (const float*)d_in[18];
    const float* b_obj_g      = (const float*)d_in[19];
    const float* w_out_g      = (const float*)d_in[20];
    const float* b_out_g      = (const float*)d_in[21];
    const float* w_in_g       = (const float*)d_in[22];
    const float* b_in_g       = (const float*)d_in[23];
    const float* w_obj_fc     = (const float*)d_in[24];
    const float* b_obj_fc     = (const float*)d_in[25];
    const float* w_rel_fc     = (const float*)d_in[26];
    const float* b_rel_fc     = (const float*)d_in[27];

    float* obj_rep = symaddr(g_obj_rep);
    float* rel_rep = symaddr(g_rel_rep);   // reused as msg buffer later
    float* vert    = symaddr(g_vert);
    float* eA      = symaddr(g_edgeA);
    float* eB      = symaddr(g_edgeB);
    float* vctx    = symaddr(g_vctx);
    float* gi      = symaddr(g_gi);
    float* gh      = symaddr(g_gh);

    const int TPB = 256;
    const int nObjH = N_OBJ * H;
    const int nRelH = N_REL * H;

    // unary projections
    sgemm_nt<<<dim3(H / BN, N_OBJ / BM), TPB>>>(x, w_obj_unary, b_obj_unary,
                                                obj_rep, N_OBJ, H, IN_DIM, 0);
    sgemm_nt<<<dim3(H / BN, N_REL / BM), TPB>>>(union_feat, w_edge_unary, b_edge_unary,
                                                rel_rep, N_REL, H, POOL, 1);

    // initial GRUs (h = 0)
    sgemm_nt<<<dim3(3 * H / BN, N_OBJ / BM), TPB>>>(obj_rep, node_w_ih, node_b_ih,
                                                    gi, N_OBJ, 3 * H, H, 0);
    gru_combine_h0<<<(nObjH + TPB - 1) / TPB, TPB>>>(gi, node_b_hh, vert, nObjH);

    sgemm_nt<<<dim3(3 * H / BN, N_REL / BM), TPB>>>(rel_rep, edge_w_ih, edge_b_ih,
                                                    gi, N_REL, 3 * H, H, 0);
    gru_combine_h0<<<(nRelH + TPB - 1) / TPB, TPB>>>(gi, edge_b_hh, eA, nRelH);

    float* msg = rel_rep;   // rel_rep no longer needed

    for (int it = 0; it < NUM_ITER; it++) {
        cudaMemsetAsync(vctx, 0, (size_t)nObjH * sizeof(float));
        relation_kernel<<<N_REL, 128>>>(vert, eA, sub_idx, obj_idx,
                                        w_sub_g, b_sub_g, w_obj_g, b_obj_g,
                                        w_out_g, b_out_g, w_in_g, b_in_g,
                                        msg, vctx);

        // edge GRU: edge_new = GRU(msg, eA) -> eB
        sgemm_nt<<<dim3(3 * H / BN, N_REL / BM), TPB>>>(msg, edge_w_ih, edge_b_ih,
                                                        gi, N_REL, 3 * H, H, 0);
        sgemm_nt<<<dim3(3 * H / BN, N_REL / BM), TPB>>>(eA, edge_w_hh, edge_b_hh,
                                                        gh, N_REL, 3 * H, H, 0);
        gru_combine<<<(nRelH + TPB - 1) / TPB, TPB>>>(gi, gh, eA, eB, nRelH);

        // node GRU: vert = GRU(vctx, vert) in place
        sgemm_nt<<<dim3(3 * H / BN, N_OBJ / BM), TPB>>>(vctx, node_w_ih, node_b_ih,
                                                        gi, N_OBJ, 3 * H, H, 0);
        sgemm_nt<<<dim3(3 * H / BN, N_OBJ / BM), TPB>>>(vert, node_w_hh, node_b_hh,
                                                        gh, N_OBJ, 3 * H, H, 0);
        gru_combine<<<(nObjH + TPB - 1) / TPB, TPB>>>(gi, gh, vert, vert, nObjH);

        // swap edge buffers
        float* tmp = eA; eA = eB; eB = tmp;
    }

    // output heads: [obj_dists | rel_dists] concatenated in d_out
    float* out = (float*)d_out;
    sgemm_nt<<<dim3((OBJ_CLS + BN - 1) / BN, N_OBJ / BM), TPB>>>(
        vert, w_obj_fc, b_obj_fc, out, N_OBJ, OBJ_CLS, H, 0);
    sgemm_nt<<<dim3((REL_CLS + BN - 1) / BN, N_REL / BM), TPB>>>(
        eA, w_rel_fc, b_rel_fc, out + (size_t)N_OBJ * OBJ_CLS, N_REL, REL_CLS, H, 0);
}

// round 3
// speedup vs baseline: 2.4590x; 2.4590x over previous
#include <cuda_runtime.h>
#include <cuda_bf16.h>
#include <math.h>
#include <stdint.h>

#define H        512
#define IN_DIM   4096
#define POOL     4096
#define N_OBJ    8192
#define N_REL    65536
#define OBJ_CLS  151
#define REL_CLS  51
#define NUM_ITER 3

// ======================= scratch (device globals) ============================
__device__ float g_obj_rep[N_OBJ * H];
__device__ float g_rel_rep[N_REL * H];     // reused as msg buffer in iterations
__device__ float g_vert[N_OBJ * H];
__device__ float g_edgeA[N_REL * H];
__device__ float g_edgeB[N_REL * H];
__device__ float g_vctx[N_OBJ * H];
__device__ float g_gi[N_REL * 3 * H];
__device__ float g_gh[N_REL * 3 * H];

// bf16 split buffers (planar hi / lo)
__device__ __nv_bfloat16 g_uh[(size_t)N_REL * POOL];
__device__ __nv_bfloat16 g_ul[(size_t)N_REL * POOL];
__device__ __nv_bfloat16 g_xh[(size_t)N_OBJ * IN_DIM];
__device__ __nv_bfloat16 g_xl[(size_t)N_OBJ * IN_DIM];
__device__ __nv_bfloat16 g_weu_h[H * POOL],   g_weu_l[H * POOL];
__device__ __nv_bfloat16 g_wou_h[H * IN_DIM], g_wou_l[H * IN_DIM];
__device__ __nv_bfloat16 g_wnih_h[3 * H * H], g_wnih_l[3 * H * H];
__device__ __nv_bfloat16 g_wnhh_h[3 * H * H], g_wnhh_l[3 * H * H];
__device__ __nv_bfloat16 g_weih_h[3 * H * H], g_weih_l[3 * H * H];
__device__ __nv_bfloat16 g_wehh_h[3 * H * H], g_wehh_l[3 * H * H];
__device__ __nv_bfloat16 g_m1h[N_REL * H], g_m1l[N_REL * H];   // rel_rep / msg
__device__ __nv_bfloat16 g_m2h[N_REL * H], g_m2l[N_REL * H];   // eA
__device__ __nv_bfloat16 g_m3h[N_OBJ * H], g_m3l[N_OBJ * H];   // obj_rep / vctx
__device__ __nv_bfloat16 g_m4h[N_OBJ * H], g_m4l[N_OBJ * H];   // vert

// ======================= split fp32 -> bf16 hi/lo ============================
__global__ void split_bf16(const float* __restrict__ in, __nv_bfloat16* __restrict__ hi,
                           __nv_bfloat16* __restrict__ lo, long long n4)
{
    long long i = (long long)blockIdx.x * blockDim.x + threadIdx.x;
    if (i >= n4) return;
    float4 v = ((const float4*)in)[i];
    __nv_bfloat162 h01, h23, l01, l23;
    h01.x = __float2bfloat16(v.x); h01.y = __float2bfloat16(v.y);
    h23.x = __float2bfloat16(v.z); h23.y = __float2bfloat16(v.w);
    l01.x = __float2bfloat16(v.x - __bfloat162float(h01.x));
    l01.y = __float2bfloat16(v.y - __bfloat162float(h01.y));
    l23.x = __float2bfloat16(v.z - __bfloat162float(h23.x));
    l23.y = __float2bfloat16(v.w - __bfloat162float(h23.y));
    ((__nv_bfloat162*)hi)[2 * i] = h01; ((__nv_bfloat162*)hi)[2 * i + 1] = h23;
    ((__nv_bfloat162*)lo)[2 * i] = l01; ((__nv_bfloat162*)lo)[2 * i + 1] = l23;
}

// ======================= HMMA split-3 GEMM ===================================
// C[M,N] = A[M,K]*B[N,K]^T + bias; A,B bf16 planar (hi,lo). M%128==0, N%128==0,
// K%64==0. act: 1 = relu.
// CTA tile 128x128, k-chunk 64. SMEM slab per operand: 128 rows x 128B (SW128
// swizzle). 8 warps: warp_m = wid&1 (64 rows), warp_n = wid>>1 (32 cols).
#define NSTAGE 2
#define SLAB_BYTES  16384
#define STAGE_BYTES (4 * SLAB_BYTES)
#define GEMM_SMEM   (NSTAGE * STAGE_BYTES + 1024)

__device__ __forceinline__ uint32_t smem_u32(const void* p) {
    uint32_t a;
    asm("{ .reg .u64 t; cvta.to.shared.u64 t, %1; cvt.u32.u64 %0, t; }" : "=r"(a) : "l"(p));
    return a;
}
__device__ __forceinline__ void cpa16(uint32_t dst, const void* src) {
    asm volatile("cp.async.cg.shared.global [%0], [%1], 16;" :: "r"(dst), "l"(src) : "memory");
}
__device__ __forceinline__ void ldsm4(uint32_t* r, uint32_t addr) {
    asm volatile("ldmatrix.sync.aligned.m8n8.x4.shared.b16 {%0,%1,%2,%3}, [%4];"
        : "=r"(r[0]), "=r"(r[1]), "=r"(r[2]), "=r"(r[3]) : "r"(addr));
}
__device__ __forceinline__ void mma_bf16(float* d, const uint32_t* a, const uint32_t* b) {
    asm volatile("mma.sync.aligned.m16n8k16.row.col.f32.bf16.bf16.f32 "
        "{%0,%1,%2,%3}, {%4,%5,%6,%7}, {%8,%9}, {%0,%1,%2,%3};"
        : "+f"(d[0]), "+f"(d[1]), "+f"(d[2]), "+f"(d[3])
        : "r"(a[0]), "r"(a[1]), "r"(a[2]), "r"(a[3]), "r"(b[0]), "r"(b[1]));
}

// load one 128-row x 64-col bf16 slab (16KB) with SW128 swizzle, 256 threads
__device__ __forceinline__ void load_slab(uint32_t sbase, const __nv_bfloat16* __restrict__ g,
                                          int row0, int K, int k0, int tid)
{
#pragma unroll
    for (int i = 0; i < 4; i++) {
        int c = tid + i * 256;
        int r = c >> 3, c16 = c & 7;
        uint32_t boff = (uint32_t)(r * 128 + c16 * 16);
        uint32_t dst = sbase + (boff ^ ((boff >> 3) & 0x70));
        cpa16(dst, g + (size_t)(row0 + r) * K + k0 + c16 * 8);
    }
}
__device__ __forceinline__ void load_stage(uint32_t st,
        const __nv_bfloat16* Ah, const __nv_bfloat16* Al,
        const __nv_bfloat16* Bh, const __nv_bfloat16* Bl,
        int arow, int brow, int K, int k0, int tid)
{
    load_slab(st,                  Ah, arow, K, k0, tid);
    load_slab(st + SLAB_BYTES,     Al, arow, K, k0, tid);
    load_slab(st + 2 * SLAB_BYTES, Bh, brow, K, k0, tid);
    load_slab(st + 3 * SLAB_BYTES, Bl, brow, K, k0, tid);
}

// one 64-deep K pass over (A-slab, B-slab) accumulating into acc
__device__ __forceinline__ void pass64(uint32_t aBase, uint32_t bBase,
        const uint32_t* aro, const uint32_t* asx, uint32_t akh,
        const uint32_t* bro, const uint32_t* bsx, uint32_t bkh,
        float acc[4][4][4])
{
#pragma unroll
    for (int ks = 0; ks < 4; ks++) {
        uint32_t a[4][4], b[2][4];
        uint32_t ka = (uint32_t)(ks * 32) + akh;
        uint32_t kb = (uint32_t)(ks * 32) + bkh;
#pragma unroll
        for (int mt = 0; mt < 4; mt++)
            ldsm4(a[mt], aBase + aro[mt] + (ka ^ asx[mt]));
#pragma unroll
        for (int p = 0; p < 2; p++)
            ldsm4(b[p], bBase + bro[p] + (kb ^ bsx[p]));
#pragma unroll
        for (int mt = 0; mt < 4; mt++)
#pragma unroll
            for (int nt = 0; nt < 4; nt++)
                mma_bf16(acc[mt][nt], a[mt], &b[nt >> 1][(nt & 1) * 2]);
    }
}

__global__ __launch_bounds__(256, 1)
void gemm_bf3(const __nv_bfloat16* __restrict__ Ah, const __nv_bfloat16* __restrict__ Al,
              const __nv_bfloat16* __restrict__ Bh, const __nv_bfloat16* __restrict__ Bl,
              const float* __restrict__ bias, float* __restrict__ C,
              int M, int N, int K, int act)
{
    extern __shared__ char dsm[];
    const int tid  = threadIdx.x;
    const int wid  = tid >> 5;
    const int lane = tid & 31;
    const int warp_m = wid & 1;
    const int warp_n = wid >> 1;
    uint32_t base = (smem_u32(dsm) + 1023u) & ~1023u;

    const int arow = blockIdx.y * 128;
    const int brow = blockIdx.x * 128;
    const int nch  = K >> 6;

    // ldmatrix lane address precompute (SW128: xor val = (row&7)<<4)
    uint32_t aro[4], asx[4];
#pragma unroll
    for (int mt = 0; mt < 4; mt++) {
        int r = warp_m * 64 + mt * 16 + (lane & 15);
        aro[mt] = (uint32_t)(r * 128);
        asx[mt] = (uint32_t)((r & 7) << 4);
    }
    uint32_t akh = (uint32_t)((lane >> 4) * 16);
    uint32_t bro[2], bsx[2];
#pragma unroll
    for (int p = 0; p < 2; p++) {
        int r = warp_n * 32 + p * 16 + (lane & 7) + ((lane >> 4) << 3);
        bro[p] = (uint32_t)(r * 128);
        bsx[p] = (uint32_t)((r & 7) << 4);
    }
    uint32_t bkh = (uint32_t)(((lane >> 3) & 1) * 16);

    float acc[4][4][4];
#pragma unroll
    for (int i = 0; i < 4; i++)
#pragma unroll
        for (int j = 0; j < 4; j++)
#pragma unroll
            for (int q = 0; q < 4; q++) acc[i][j][q] = 0.f;

    // prologue: preload 2 chunks
    {
        int pre = (nch < NSTAGE) ? nch : NSTAGE;
        for (int i = 0; i < pre; i++) {
            load_stage(base + i * STAGE_BYTES, Ah, Al, Bh, Bl, arow, brow, K, i * 64, tid);
            asm volatile("cp.async.commit_group;" ::: "memory");
        }
    }

    for (int i = 0; i < nch; i++) {
        if (i + 1 < nch) asm volatile("cp.async.wait_group 1;" ::: "memory");
        else             asm volatile("cp.async.wait_group 0;" ::: "memory");
        __syncthreads();

        uint32_t st = base + (uint32_t)(i & 1) * STAGE_BYTES;
        pass64(st,              st + 2 * SLAB_BYTES, aro, asx, akh, bro, bsx, bkh, acc); // Ah*Bh
        pass64(st,              st + 3 * SLAB_BYTES, aro, asx, akh, bro, bsx, bkh, acc); // Ah*Bl
        pass64(st + SLAB_BYTES, st + 2 * SLAB_BYTES, aro, asx, akh, bro, bsx, bkh, acc); // Al*Bh

        __syncthreads();
        if (i + 2 < nch) {
            load_stage(st, Ah, Al, Bh, Bl, arow, brow, K, (i + 2) * 64, tid);
            asm volatile("cp.async.commit_group;" ::: "memory");
        }
    }

    // epilogue: d-frag (mt,nt): rows m+t/4, m+8+t/4; cols n+(t%4)*2
    const int qrow = lane >> 2;
    const int qcol = (lane & 3) * 2;
#pragma unroll
    for (int mt = 0; mt < 4; mt++) {
        int m0 = arow + warp_m * 64 + mt * 16 + qrow;
#pragma unroll
        for (int nt = 0; nt < 4; nt++) {
            int n0 = brow + warp_n * 32 + nt * 8 + qcol;
            float b0 = bias[n0], b1 = bias[n0 + 1];
            float2 v0 = make_float2(acc[mt][nt][0] + b0, acc[mt][nt][1] + b1);
            float2 v1 = make_float2(acc[mt][nt][2] + b0, acc[mt][nt][3] + b1);
            if (act) {
                v0.x = fmaxf(v0.x, 0.f); v0.y = fmaxf(v0.y, 0.f);
                v1.x = fmaxf(v1.x, 0.f); v1.y = fmaxf(v1.y, 0.f);
            }
            *(float2*)(C + (size_t)m0 * N + n0)       = v0;
            *(float2*)(C + (size_t)(m0 + 8) * N + n0) = v1;
        }
    }
}

// ======================= fp32 SGEMM (heads only) =============================
#define BM 128
#define BN 128
#define BK 16
#define TM 8
#define TN 8
__global__ __launch_bounds__(256)
void sgemm_nt(const float* __restrict__ A, const float* __restrict__ B,
              const float* __restrict__ bias, float* __restrict__ C,
              int M, int N, int K, int act)
{
    __shared__ float As[BK][BM + 4];
    __shared__ float Bs[BK][BN + 4];
    const int bx = blockIdx.x, by = blockIdx.y;
    const int tid = threadIdx.x;
    const int tx = tid & 15, ty = tid >> 4;
    const int lrow = tid >> 2, lcol = (tid & 3) * 4;
    const float* Aptr = A + (size_t)(by * BM) * K;
    const float* Bptr = B + (size_t)(bx * BN) * K;
    float acc[TM][TN];
#pragma unroll
    for (int i = 0; i < TM; i++)
#pragma unroll
        for (int j = 0; j < TN; j++) acc[i][j] = 0.f;
    for (int k0 = 0; k0 < K; k0 += BK) {
#pragma unroll
        for (int i = 0; i < 2; i++) {
            int r = lrow + i * 64;
            float4 v = *(const float4*)(Aptr + (size_t)r * K + k0 + lcol);
            As[lcol + 0][r] = v.x; As[lcol + 1][r] = v.y;
            As[lcol + 2][r] = v.z; As[lcol + 3][r] = v.w;
        }
#pragma unroll
        for (int i = 0; i < 2; i++) {
            int r = lrow + i * 64;
            int gr = bx * BN + r;
            float4 v = make_float4(0.f, 0.f, 0.f, 0.f);
            if (gr < N) v = *(const float4*)(Bptr + (size_t)r * K + k0 + lcol);
            Bs[lcol + 0][r] = v.x; Bs[lcol + 1][r] = v.y;
            Bs[lcol + 2][r] = v.z; Bs[lcol + 3][r] = v.w;
        }
        __syncthreads();
#pragma unroll
        for (int kk = 0; kk < BK; kk++) {
            float a[TM], b[TN];
            float4 a0 = *(const float4*)&As[kk][ty * TM];
            float4 a1 = *(const float4*)&As[kk][ty * TM + 4];
            a[0] = a0.x; a[1] = a0.y; a[2] = a0.z; a[3] = a0.w;
            a[4] = a1.x; a[5] = a1.y; a[6] = a1.z; a[7] = a1.w;
            float4 b0 = *(const float4*)&Bs[kk][tx * TN];
            float4 b1 = *(const float4*)&Bs[kk][tx * TN + 4];
            b[0] = b0.x; b[1] = b0.y; b[2] = b0.z; b[3] = b0.w;
            b[4] = b1.x; b[5] = b1.y; b[6] = b1.z; b[7] = b1.w;
#pragma unroll
            for (int i = 0; i < TM; i++)
#pragma unroll
                for (int j = 0; j < TN; j++)
                    acc[i][j] = fmaf(a[i], b[j], acc[i][j]);
        }
        __syncthreads();
    }
#pragma unroll
    for (int i = 0; i < TM; i++) {
        int gm = by * BM + ty * TM + i;
#pragma unroll
        for (int j = 0; j < TN; j++) {
            int gn = bx * BN + tx * TN + j;
            if (gn < N) {
                float v = acc[i][j] + bias[gn];
                if (act) v = fmaxf(v, 0.f);
                C[(size_t)gm * N + gn] = v;
            }
        }
    }
}

// ======================= GRU elementwise =====================================
__device__ __forceinline__ float sigm(float x) { return 1.f / (1.f + expf(-x)); }

__global__ void gru_combine(const float* __restrict__ gi, const float* __restrict__ gh,
                            const float* __restrict__ h, float* __restrict__ out, int n)
{
    int idx = blockIdx.x * blockDim.x + threadIdx.x;
    if (idx >= n) return;
    int m = idx >> 9;
    int j = idx & (H - 1);
    size_t base = (size_t)m * (3 * H);
    float ir = gi[base + j], iz = gi[base + H + j], in_ = gi[base + 2 * H + j];
    float hr = gh[base + j], hz = gh[base + H + j], hn = gh[base + 2 * H + j];
    float r = sigm(ir + hr);
    float z = sigm(iz + hz);
    float nn = tanhf(in_ + r * hn);
    out[idx] = (1.f - z) * nn + z * h[idx];
}

__global__ void gru_combine_h0(const float* __restrict__ gi, const float* __restrict__ b_hh,
                               float* __restrict__ out, int n)
{
    int idx = blockIdx.x * blockDim.x + threadIdx.x;
    if (idx >= n) return;
    int m = idx >> 9;
    int j = idx & (H - 1);
    size_t base = (size_t)m * (3 * H);
    float ir = gi[base + j], iz = gi[base + H + j], in_ = gi[base + 2 * H + j];
    float hr = b_hh[j], hz = b_hh[H + j], hn = b_hh[2 * H + j];
    float r = sigm(ir + hr);
    float z = sigm(iz + hz);
    float nn = tanhf(in_ + r * hn);
    out[idx] = (1.f - z) * nn;
}

// ======================= fused relation kernel ===============================
__device__ __forceinline__ float dot4(float4 a, float4 b) {
    return a.x * b.x + a.y * b.y + a.z * b.z + a.w * b.w;
}

__global__ __launch_bounds__(128)
void relation_kernel(const float* __restrict__ vert, const float* __restrict__ edge,
                     const int* __restrict__ sub_idx, const int* __restrict__ obj_idx,
                     const float* __restrict__ w_sub, const float* __restrict__ b_sub,
                     const float* __restrict__ w_obj, const float* __restrict__ b_obj,
                     const float* __restrict__ w_out, const float* __restrict__ b_out,
                     const float* __restrict__ w_in,  const float* __restrict__ b_in,
                     float* __restrict__ msg, float* __restrict__ vctx)
{
    const int r = blockIdx.x;
    const int t = threadIdx.x;
    const int si = sub_idx[r];
    const int oi = obj_idx[r];

    float4 s4 = ((const float4*)(vert + (size_t)si * H))[t];
    float4 o4 = ((const float4*)(vert + (size_t)oi * H))[t];
    float4 e4 = ((const float4*)(edge + (size_t)r * H))[t];

    float4 ws1 = ((const float4*)w_sub)[t];
    float4 ws2 = ((const float4*)(w_sub + H))[t];
    float4 wo1 = ((const float4*)w_obj)[t];
    float4 wo2 = ((const float4*)(w_obj + H))[t];
    float4 wu1 = ((const float4*)w_out)[t];
    float4 wu2 = ((const float4*)(w_out + H))[t];
    float4 wi1 = ((const float4*)w_in)[t];
    float4 wi2 = ((const float4*)(w_in + H))[t];

    float d0 = dot4(s4, ws1) + dot4(e4, ws2);
    float d1 = dot4(o4, wo1) + dot4(e4, wo2);
    float d2 = dot4(s4, wu1) + dot4(e4, wu2);
    float d3 = dot4(o4, wi1) + dot4(e4, wi2);

#pragma unroll
    for (int off = 16; off > 0; off >>= 1) {
        d0 += __shfl_down_sync(0xFFFFFFFFu, d0, off);
        d1 += __shfl_down_sync(0xFFFFFFFFu, d1, off);
        d2 += __shfl_down_sync(0xFFFFFFFFu, d2, off);
        d3 += __shfl_down_sync(0xFFFFFFFFu, d3, off);
    }
    __shared__ float red[4][4];
    __shared__ float gates[4];
    int warp = t >> 5, lane = t & 31;
    if (lane == 0) {
        red[warp][0] = d0; red[warp][1] = d1; red[warp][2] = d2; red[warp][3] = d3;
    }
    __syncthreads();
    if (t < 4) {
        float v = red[0][t] + red[1][t] + red[2][t] + red[3][t];
        float bb = (t == 0) ? b_sub[0] : (t == 1) ? b_obj[0] : (t == 2) ? b_out[0] : b_in[0];
        gates[t] = sigm(v + bb);
    }
    __syncthreads();

    float gs = gates[0], go = gates[1], gu = gates[2], gn = gates[3];

    float4 m4;
    m4.x = gs * s4.x + go * o4.x;
    m4.y = gs * s4.y + go * o4.y;
    m4.z = gs * s4.z + go * o4.z;
    m4.w = gs * s4.w + go * o4.w;
    ((float4*)(msg + (size_t)r * H))[t] = m4;

    float* vs = vctx + (size_t)si * H + t * 4;
    atomicAdd(vs + 0, gu * e4.x);
    atomicAdd(vs + 1, gu * e4.y);
    atomicAdd(vs + 2, gu * e4.z);
    atomicAdd(vs + 3, gu * e4.w);
    float* vo = vctx + (size_t)oi * H + t * 4;
    atomicAdd(vo + 0, gn * e4.x);
    atomicAdd(vo + 1, gn * e4.y);
    atomicAdd(vo + 2, gn * e4.z);
    atomicAdd(vo + 3, gn * e4.w);
}

// ======================= host orchestration ==================================
template <typename T>
static T* symaddr(const T* sym) {
    void* p = nullptr;
    cudaGetSymbolAddress(&p, (const void*)sym);
    return (T*)p;
}

static void split(const float* in, __nv_bfloat16* hi, __nv_bfloat16* lo, long long n) {
    long long n4 = n >> 2;
    split_bf16<<<(unsigned)((n4 + 255) / 256), 256>>>(in, hi, lo, n4);
}

static void gemm3(const __nv_bfloat16* Ah, const __nv_bfloat16* Al,
                  const __nv_bfloat16* Bh, const __nv_bfloat16* Bl,
                  const float* bias, float* C, int M, int N, int K, int act) {
    gemm_bf3<<<dim3(N / 128, M / 128), 256, GEMM_SMEM>>>(Ah, Al, Bh, Bl, bias, C, M, N, K, act);
}

extern "C" void kernel_launch(void* const* d_in, const int* in_sizes, int n_in,
                              void* d_out, int out_size)
{
    const float* x            = (const float*)d_in[0];
    const float* union_feat   = (const float*)d_in[1];
    const int*   sub_idx      = (const int*)d_in[2];
    const int*   obj_idx      = (const int*)d_in[3];
    const float* w_obj_unary  = (const float*)d_in[4];
    const float* b_obj_unary  = (const float*)d_in[5];
    const float* w_edge_unary = (const float*)d_in[6];
    const float* b_edge_unary = (const float*)d_in[7];
    const float* node_w_ih    = (const float*)d_in[8];
    const float* node_w_hh    = (const float*)d_in[9];
    const float* node_b_ih    = (const float*)d_in[10];
    const float* node_b_hh    = (const float*)d_in[11];
    const float* edge_w_ih    = (const float*)d_in[12];
    const float* edge_w_hh    = (const float*)d_in[13];
    const float* edge_b_ih    = (const float*)d_in[14];
    const float* edge_b_hh    = (const float*)d_in[15];
    const float* w_sub_g      = (const float*)d_in[16];
    const float* b_sub_g      = (const float*)d_in[17];
    const float* w_obj_g      = (const float*)d_in[18];
    const float* b_obj_g      = (const float*)d_in[19];
    const float* w_out_g      = (const float*)d_in[20];
    const float* b_out_g      = (const float*)d_in[21];
    const float* w_in_g       = (const float*)d_in[22];
    const float* b_in_g       = (const float*)d_in[23];
    const float* w_obj_fc     = (const float*)d_in[24];
    const float* b_obj_fc     = (const float*)d_in[25];
    const float* w_rel_fc     = (const float*)d_in[26];
    const float* b_rel_fc     = (const float*)d_in[27];

    static int smem_set = 0;
    if (!smem_set) {
        cudaFuncSetAttribute(gemm_bf3, cudaFuncAttributeMaxDynamicSharedMemorySize, GEMM_SMEM);
        smem_set = 1;
    }

    float* obj_rep = symaddr(g_obj_rep);
    float* rel_rep = symaddr(g_rel_rep);
    float* vert    = symaddr(g_vert);
    float* eA      = symaddr(g_edgeA);
    float* eB      = symaddr(g_edgeB);
    float* vctx    = symaddr(g_vctx);
    float* gi      = symaddr(g_gi);
    float* gh      = symaddr(g_gh);

    __nv_bfloat16* uh  = symaddr(g_uh);   __nv_bfloat16* ul  = symaddr(g_ul);
    __nv_bfloat16* xh  = symaddr(g_xh);   __nv_bfloat16* xl  = symaddr(g_xl);
    __nv_bfloat16* weuh = symaddr(g_weu_h); __nv_bfloat16* weul = symaddr(g_weu_l);
    __nv_bfloat16* wouh = symaddr(g_wou_h); __nv_bfloat16* woul = symaddr(g_wou_l);
    __nv_bfloat16* wnihh = symaddr(g_wnih_h); __nv_bfloat16* wnihl = symaddr(g_wnih_l);
    __nv_bfloat16* wnhhh = symaddr(g_wnhh_h); __nv_bfloat16* wnhhl = symaddr(g_wnhh_l);
    __nv_bfloat16* weihh = symaddr(g_weih_h); __nv_bfloat16* weihl = symaddr(g_weih_l);
    __nv_bfloat16* wehhh = symaddr(g_wehh_h); __nv_bfloat16* wehhl = symaddr(g_wehh_l);
    __nv_bfloat16* m1h = symaddr(g_m1h); __nv_bfloat16* m1l = symaddr(g_m1l);
    __nv_bfloat16* m2h = symaddr(g_m2h); __nv_bfloat16* m2l = symaddr(g_m2l);
    __nv_bfloat16* m3h = symaddr(g_m3h); __nv_bfloat16* m3l = symaddr(g_m3l);
    __nv_bfloat16* m4h = symaddr(g_m4h); __nv_bfloat16* m4l = symaddr(g_m4l);

    const int TPB = 256;
    const int nObjH = N_OBJ * H;
    const int nRelH = N_REL * H;

    // ---- input / weight conversions ----
    split(x, xh, xl, (long long)N_OBJ * IN_DIM);
    split(union_feat, uh, ul, (long long)N_REL * POOL);
    split(w_obj_unary, wouh, woul, (long long)H * IN_DIM);
    split(w_edge_unary, weuh, weul, (long long)H * POOL);
    split(node_w_ih, wnihh, wnihl, 3 * H * H);
    split(node_w_hh, wnhhh, wnhhl, 3 * H * H);
    split(edge_w_ih, weihh, weihl, 3 * H * H);
    split(edge_w_hh, wehhh, wehhl, 3 * H * H);

    // ---- unary projections ----
    gemm3(xh, xl, wouh, woul, b_obj_unary, obj_rep, N_OBJ, H, IN_DIM, 0);
    gemm3(uh, ul, weuh, weul, b_edge_unary, rel_rep, N_REL, H, POOL, 1);

    // ---- initial GRUs (h = 0) ----
    split(obj_rep, m3h, m3l, nObjH);
    gemm3(m3h, m3l, wnihh, wnihl, node_b_ih, gi, N_OBJ, 3 * H, H, 0);
    gru_combine_h0<<<(nObjH + TPB - 1) / TPB, TPB>>>(gi, node_b_hh, vert, nObjH);

    split(rel_rep, m1h, m1l, nRelH);
    gemm3(m1h, m1l, weihh, weihl, edge_b_ih, gi, N_REL, 3 * H, H, 0);
    gru_combine_h0<<<(nRelH + TPB - 1) / TPB, TPB>>>(gi, edge_b_hh, eA, nRelH);

    float* msg = rel_rep;

    for (int it = 0; it < NUM_ITER; it++) {
        cudaMemsetAsync(vctx, 0, (size_t)nObjH * sizeof(float));
        relation_kernel<<<N_REL, 128>>>(vert, eA, sub_idx, obj_idx,
                                        w_sub_g, b_sub_g, w_obj_g, b_obj_g,
                                        w_out_g, b_out_g, w_in_g, b_in_g,
                                        msg, vctx);

        // edge GRU: eB = GRU(msg, eA)
        split(msg, m1h, m1l, nRelH);
        split(eA, m2h, m2l, nRelH);
        gemm3(m1h, m1l, weihh, weihl, edge_b_ih, gi, N_REL, 3 * H, H, 0);
        gemm3(m2h, m2l, wehhh, wehhl, edge_b_hh, gh, N_REL, 3 * H, H, 0);
        gru_combine<<<(nRelH + TPB - 1) / TPB, TPB>>>(gi, gh, eA, eB, nRelH);

        // node GRU: vert = GRU(vctx, vert)
        split(vctx, m3h, m3l, nObjH);
        split(vert, m4h, m4l, nObjH);
        gemm3(m3h, m3l, wnihh, wnihl, node_b_ih, gi, N_OBJ, 3 * H, H, 0);
        gemm3(m4h, m4l, wnhhh, wnhhl, node_b_hh, gh, N_OBJ, 3 * H, H, 0);
        gru_combine<<<(nObjH + TPB - 1) / TPB, TPB>>>(gi, gh, vert, vert, nObjH);

        float* tmp = eA; eA = eB; eB = tmp;
    }

    // ---- output heads (fp32) ----
    float* out = (float*)d_out;
    sgemm_nt<<<dim3((OBJ_CLS + BN - 1) / BN, N_OBJ / BM), TPB>>>(
        vert, w_obj_fc, b_obj_fc, out, N_OBJ, OBJ_CLS, H, 0);
    sgemm_nt<<<dim3((REL_CLS + BN - 1) / BN, N_REL / BM), TPB>>>(
        eA, w_rel_fc, b_rel_fc, out + (size_t)N_OBJ * OBJ_CLS, N_REL, REL_CLS, H, 0);
}

// round 5
// speedup vs baseline: 2.4969x; 1.0154x over previous
#include <cuda_runtime.h>
#include <cuda_bf16.h>
#include <math.h>
#include <stdint.h>

#define H        512
#define IN_DIM   4096
#define POOL     4096
#define N_OBJ    8192
#define N_REL    65536
#define OBJ_CLS  151
#define REL_CLS  51
#define NUM_ITER 3

// ======================= scratch (device globals) ============================
__device__ float g_vert[N_OBJ * H];
__device__ float g_edgeA[N_REL * H];
__device__ float g_edgeB[N_REL * H];
__device__ float g_vctx[N_OBJ * H];
__device__ float g_gi[N_REL * 3 * H];
__device__ float g_gh[N_REL * 3 * H];

__device__ __nv_bfloat16 g_uh[(size_t)N_REL * POOL];
__device__ __nv_bfloat16 g_ul[(size_t)N_REL * POOL];
__device__ __nv_bfloat16 g_xh[(size_t)N_OBJ * IN_DIM];
__device__ __nv_bfloat16 g_xl[(size_t)N_OBJ * IN_DIM];
__device__ __nv_bfloat16 g_weu_h[H * POOL],   g_weu_l[H * POOL];
__device__ __nv_bfloat16 g_wou_h[H * IN_DIM], g_wou_l[H * IN_DIM];
__device__ __nv_bfloat16 g_wnih_h[3 * H * H], g_wnih_l[3 * H * H];
__device__ __nv_bfloat16 g_wnhh_h[3 * H * H], g_wnhh_l[3 * H * H];
__device__ __nv_bfloat16 g_weih_h[3 * H * H], g_weih_l[3 * H * H];
__device__ __nv_bfloat16 g_wehh_h[3 * H * H], g_wehh_l[3 * H * H];
__device__ __nv_bfloat16 g_wof_h[OBJ_CLS * H], g_wof_l[OBJ_CLS * H];
__device__ __nv_bfloat16 g_wrf_h[REL_CLS * H], g_wrf_l[REL_CLS * H];
__device__ __nv_bfloat16 g_m1h[N_REL * H], g_m1l[N_REL * H];  // rel_rep / msg planes
__device__ __nv_bfloat16 g_m2h[N_REL * H], g_m2l[N_REL * H];  // edge planes (buf A)
__device__ __nv_bfloat16 g_m5h[N_REL * H], g_m5l[N_REL * H];  // edge planes (buf B)
__device__ __nv_bfloat16 g_m3h[N_OBJ * H], g_m3l[N_OBJ * H];  // obj_rep / vctx planes
__device__ __nv_bfloat16 g_m4h[N_OBJ * H], g_m4l[N_OBJ * H];  // vert planes

// ======================= split fp32 -> bf16 hi/lo ============================
__global__ void split_bf16(const float* __restrict__ in, __nv_bfloat16* __restrict__ hi,
                           __nv_bfloat16* __restrict__ lo, long long n4)
{
    long long i = (long long)blockIdx.x * blockDim.x + threadIdx.x;
    if (i >= n4) return;
    float4 v = ((const float4*)in)[i];
    __nv_bfloat162 h01, h23, l01, l23;
    h01.x = __float2bfloat16(v.x); h01.y = __float2bfloat16(v.y);
    h23.x = __float2bfloat16(v.z); h23.y = __float2bfloat16(v.w);
    l01.x = __float2bfloat16(v.x - __bfloat162float(h01.x));
    l01.y = __float2bfloat16(v.y - __bfloat162float(h01.y));
    l23.x = __float2bfloat16(v.z - __bfloat162float(h23.x));
    l23.y = __float2bfloat16(v.w - __bfloat162float(h23.y));
    ((__nv_bfloat162*)hi)[2 * i] = h01; ((__nv_bfloat162*)hi)[2 * i + 1] = h23;
    ((__nv_bfloat162*)lo)[2 * i] = l01; ((__nv_bfloat162*)lo)[2 * i + 1] = l23;
}

// ======================= HMMA split-3 GEMM ===================================
// C[M,N] = A[M,K]*B[N,K]^T + bias. M%128==0, K%64==0, N arbitrary (B zero-fill).
// Outputs: Cf (fp32, row stride ldc, col-guarded) and/or Chi/Clo bf16 split
// planes (require N%128==0). act: relu.
#define NSTAGE 3
#define SLAB_BYTES  16384
#define STAGE_BYTES (4 * SLAB_BYTES)
#define GEMM_SMEM   (NSTAGE * STAGE_BYTES + 1024)

__device__ __forceinline__ uint32_t smem_u32(const void* p) {
    uint32_t a;
    asm("{ .reg .u64 t; cvta.to.shared.u64 t, %1; cvt.u32.u64 %0, t; }" : "=r"(a) : "l"(p));
    return a;
}
__device__ __forceinline__ void cpa16z(uint32_t dst, const void* src, uint32_t sz) {
    asm volatile("cp.async.cg.shared.global [%0], [%1], 16, %2;"
                 :: "r"(dst), "l"(src), "r"(sz) : "memory");
}
__device__ __forceinline__ void ldsm4(uint32_t* r, uint32_t addr) {
    asm volatile("ldmatrix.sync.aligned.m8n8.x4.shared.b16 {%0,%1,%2,%3}, [%4];"
        : "=r"(r[0]), "=r"(r[1]), "=r"(r[2]), "=r"(r[3]) : "r"(addr));
}
__device__ __forceinline__ void mma_bf16(float* d, const uint32_t* a, const uint32_t* b) {
    asm volatile("mma.sync.aligned.m16n8k16.row.col.f32.bf16.bf16.f32 "
        "{%0,%1,%2,%3}, {%4,%5,%6,%7}, {%8,%9}, {%0,%1,%2,%3};"
        : "+f"(d[0]), "+f"(d[1]), "+f"(d[2]), "+f"(d[3])
        : "r"(a[0]), "r"(a[1]), "r"(a[2]), "r"(a[3]), "r"(b[0]), "r"(b[1]));
}

// load one 128-row x 64-col bf16 slab (16KB), SW128 swizzle, rows >= limit zero
__device__ __forceinline__ void load_slab(uint32_t sbase, const __nv_bfloat16* __restrict__ g,
                                          int row0, int K, int k0, int tid, int limit)
{
#pragma unroll
    for (int i = 0; i < 4; i++) {
        int c = tid + i * 256;
        int r = c >> 3, c16 = c & 7;
        uint32_t boff = (uint32_t)(r * 128 + c16 * 16);
        uint32_t dst = sbase + (boff ^ ((boff >> 3) & 0x70));
        uint32_t sz = (row0 + r < limit) ? 16u : 0u;
        cpa16z(dst, g + (size_t)(row0 + r) * K + k0 + c16 * 8, sz);
    }
}
__device__ __forceinline__ void load_stage(uint32_t st,
        const __nv_bfloat16* Ah, const __nv_bfloat16* Al,
        const __nv_bfloat16* Bh, const __nv_bfloat16* Bl,
        int arow, int brow, int K, int k0, int tid, int M, int N)
{
    load_slab(st,                  Ah, arow, K, k0, tid, M);
    load_slab(st + SLAB_BYTES,     Al, arow, K, k0, tid, M);
    load_slab(st + 2 * SLAB_BYTES, Bh, brow, K, k0, tid, N);
    load_slab(st + 3 * SLAB_BYTES, Bl, brow, K, k0, tid, N);
}

// fragment-reuse split-3 pass over one 64-K stage: 12 ldsm + 48 mma per ks
__device__ __forceinline__ void pass_all(uint32_t st,
        const uint32_t* aro, const uint32_t* asx, uint32_t akh,
        const uint32_t* bro, const uint32_t* bsx, uint32_t bkh,
        float acc[4][4][4])
{
    uint32_t aH = st, aL = st + SLAB_BYTES;
    uint32_t bH = st + 2 * SLAB_BYTES, bL = st + 3 * SLAB_BYTES;
#pragma unroll
    for (int ks = 0; ks < 4; ks++) {
        uint32_t ka = (uint32_t)(ks * 32) + akh;
        uint32_t kb = (uint32_t)(ks * 32) + bkh;
        uint32_t ah[4][4], al[4][4], bh[2][4], bl[2][4];
#pragma unroll
        for (int mt = 0; mt < 4; mt++) ldsm4(ah[mt], aH + aro[mt] + (ka ^ asx[mt]));
#pragma unroll
        for (int p = 0; p < 2; p++)    ldsm4(bh[p], bH + bro[p] + (kb ^ bsx[p]));
#pragma unroll
        for (int p = 0; p < 2; p++)    ldsm4(bl[p], bL + bro[p] + (kb ^ bsx[p]));
#pragma unroll
        for (int mt = 0; mt < 4; mt++) ldsm4(al[mt], aL + aro[mt] + (ka ^ asx[mt]));
#pragma unroll
        for (int mt = 0; mt < 4; mt++)
#pragma unroll
            for (int nt = 0; nt < 4; nt++)
                mma_bf16(acc[mt][nt], ah[mt], &bh[nt >> 1][(nt & 1) * 2]);
#pragma unroll
        for (int mt = 0; mt < 4; mt++)
#pragma unroll
            for (int nt = 0; nt < 4; nt++)
                mma_bf16(acc[mt][nt], ah[mt], &bl[nt >> 1][(nt & 1) * 2]);
#pragma unroll
        for (int mt = 0; mt < 4; mt++)
#pragma unroll
            for (int nt = 0; nt < 4; nt++)
                mma_bf16(acc[mt][nt], al[mt], &bh[nt >> 1][(nt & 1) * 2]);
    }
}

__global__ __launch_bounds__(256, 1)
void gemm_bf3(const __nv_bfloat16* __restrict__ Ah, const __nv_bfloat16* __restrict__ Al,
              const __nv_bfloat16* __restrict__ Bh, const __nv_bfloat16* __restrict__ Bl,
              const float* __restrict__ bias,
              float* __restrict__ Cf, __nv_bfloat16* __restrict__ Chi,
              __nv_bfloat16* __restrict__ Clo,
              int M, int N, int K, int ldc, int act)
{
    extern __shared__ char dsm[];
    const int tid  = threadIdx.x;
    const int wid  = tid >> 5;
    const int lane = tid & 31;
    const int warp_m = wid & 1;
    const int warp_n = wid >> 1;
    uint32_t base = (smem_u32(dsm) + 1023u) & ~1023u;

    const int arow = blockIdx.y * 128;
    const int brow = blockIdx.x * 128;
    const int nch  = K >> 6;

    uint32_t aro[4], asx[4];
#pragma unroll
    for (int mt = 0; mt < 4; mt++) {
        int r = warp_m * 64 + mt * 16 + (lane & 15);
        aro[mt] = (uint32_t)(r * 128);
        asx[mt] = (uint32_t)((r & 7) << 4);
    }
    uint32_t akh = (uint32_t)((lane >> 4) * 16);
    uint32_t bro[2], bsx[2];
#pragma unroll
    for (int p = 0; p < 2; p++) {
        int r = warp_n * 32 + p * 16 + (lane & 7) + ((lane >> 4) << 3);
        bro[p] = (uint32_t)(r * 128);
        bsx[p] = (uint32_t)((r & 7) << 4);
    }
    uint32_t bkh = (uint32_t)(((lane >> 3) & 1) * 16);

    float acc[4][4][4];
#pragma unroll
    for (int i = 0; i < 4; i++)
#pragma unroll
        for (int j = 0; j < 4; j++)
#pragma unroll
            for (int q = 0; q < 4; q++) acc[i][j][q] = 0.f;

    // prologue
    {
        int pre = (nch < NSTAGE) ? nch : NSTAGE;
        for (int i = 0; i < pre; i++) {
            load_stage(base + i * STAGE_BYTES, Ah, Al, Bh, Bl, arow, brow, K, i * 64, tid, M, N);
            asm volatile("cp.async.commit_group;" ::: "memory");
        }
    }

    for (int i = 0; i < nch; i++) {
        int committed = (nch < i + NSTAGE) ? nch : (i + NSTAGE);
        int pending = committed - i - 1;
        if (pending >= 2)      asm volatile("cp.async.wait_group 2;" ::: "memory");
        else if (pending == 1) asm volatile("cp.async.wait_group 1;" ::: "memory");
        else                   asm volatile("cp.async.wait_group 0;" ::: "memory");
        __syncthreads();

        uint32_t st = base + (uint32_t)(i % NSTAGE) * STAGE_BYTES;
        pass_all(st, aro, asx, akh, bro, bsx, bkh, acc);

        __syncthreads();
        if (i + NSTAGE < nch) {
            load_stage(st, Ah, Al, Bh, Bl, arow, brow, K, (i + NSTAGE) * 64, tid, M, N);
            asm volatile("cp.async.commit_group;" ::: "memory");
        }
    }

    // epilogue
    const int qrow = lane >> 2;
    const int qcol = (lane & 3) * 2;
#pragma unroll
    for (int mt = 0; mt < 4; mt++) {
        int m0 = arow + warp_m * 64 + mt * 16 + qrow;
#pragma unroll
        for (int nt = 0; nt < 4; nt++) {
            int n0 = brow + warp_n * 32 + nt * 8 + qcol;
            float b0 = (n0 < N) ? bias[n0] : 0.f;
            float b1 = (n0 + 1 < N) ? bias[n0 + 1] : 0.f;
            float v00 = acc[mt][nt][0] + b0, v01 = acc[mt][nt][1] + b1;
            float v10 = acc[mt][nt][2] + b0, v11 = acc[mt][nt][3] + b1;
            if (act) {
                v00 = fmaxf(v00, 0.f); v01 = fmaxf(v01, 0.f);
                v10 = fmaxf(v10, 0.f); v11 = fmaxf(v11, 0.f);
            }
            if (Cf) {
                if (n0 < N) {
                    Cf[(size_t)m0 * ldc + n0] = v00;
                    Cf[(size_t)(m0 + 8) * ldc + n0] = v10;
                }
                if (n0 + 1 < N) {
                    Cf[(size_t)m0 * ldc + n0 + 1] = v01;
                    Cf[(size_t)(m0 + 8) * ldc + n0 + 1] = v11;
                }
            }
            if (Chi) {   // requires N % 128 == 0
                __nv_bfloat162 h0, h1, l0, l1;
                h0.x = __float2bfloat16(v00); h0.y = __float2bfloat16(v01);
                h1.x = __float2bfloat16(v10); h1.y = __float2bfloat16(v11);
                l0.x = __float2bfloat16(v00 - __bfloat162float(h0.x));
                l0.y = __float2bfloat16(v01 - __bfloat162float(h0.y));
                l1.x = __float2bfloat16(v10 - __bfloat162float(h1.x));
                l1.y = __float2bfloat16(v11 - __bfloat162float(h1.y));
                *(__nv_bfloat162*)(Chi + (size_t)m0 * N + n0)       = h0;
                *(__nv_bfloat162*)(Chi + (size_t)(m0 + 8) * N + n0) = h1;
                *(__nv_bfloat162*)(Clo + (size_t)m0 * N + n0)       = l0;
                *(__nv_bfloat162*)(Clo + (size_t)(m0 + 8) * N + n0) = l1;
            }
        }
    }
}

// ======================= GRU elementwise (vectorized, fused split) ===========
__device__ __forceinline__ float sigm(float x) { return 1.f / (1.f + __expf(-x)); }
__device__ __forceinline__ float tanh_f(float x) { return 2.f * sigm(2.f * x) - 1.f; }

__device__ __forceinline__ void write_split4(float4 v, __nv_bfloat16* hi, __nv_bfloat16* lo,
                                             size_t idx)
{
    __nv_bfloat162 h0, h1, l0, l1;
    h0.x = __float2bfloat16(v.x); h0.y = __float2bfloat16(v.y);
    h1.x = __float2bfloat16(v.z); h1.y = __float2bfloat16(v.w);
    l0.x = __float2bfloat16(v.x - __bfloat162float(h0.x));
    l0.y = __float2bfloat16(v.y - __bfloat162float(h0.y));
    l1.x = __float2bfloat16(v.z - __bfloat162float(h1.x));
    l1.y = __float2bfloat16(v.w - __bfloat162float(h1.y));
    *(__nv_bfloat162*)(hi + idx)     = h0;
    *(__nv_bfloat162*)(hi + idx + 2) = h1;
    *(__nv_bfloat162*)(lo + idx)     = l0;
    *(__nv_bfloat162*)(lo + idx + 2) = l1;
}

__global__ void gru_combine4(const float* __restrict__ gi, const float* __restrict__ gh,
                             const float* __restrict__ h, float* __restrict__ out,
                             __nv_bfloat16* __restrict__ ohi, __nv_bfloat16* __restrict__ olo,
                             int n4)
{
    int i4 = blockIdx.x * blockDim.x + threadIdx.x;
    if (i4 >= n4) return;
    int idx = i4 * 4;
    int m = idx >> 9;
    int j = idx & (H - 1);
    const float* gib = gi + (size_t)m * (3 * H);
    const float* ghb = gh + (size_t)m * (3 * H);
    float4 ir = *(const float4*)(gib + j);
    float4 iz = *(const float4*)(gib + H + j);
    float4 in_ = *(const float4*)(gib + 2 * H + j);
    float4 hr = *(const float4*)(ghb + j);
    float4 hz = *(const float4*)(ghb + H + j);
    float4 hn = *(const float4*)(ghb + 2 * H + j);
    float4 hv = *(const float4*)(h + idx);
    float4 o;
    {
        float r = sigm(ir.x + hr.x), z = sigm(iz.x + hz.x);
        o.x = (1.f - z) * tanh_f(in_.x + r * hn.x) + z * hv.x;
    }
    {
        float r = sigm(ir.y + hr.y), z = sigm(iz.y + hz.y);
        o.y = (1.f - z) * tanh_f(in_.y + r * hn.y) + z * hv.y;
    }
    {
        float r = sigm(ir.z + hr.z), z = sigm(iz.z + hz.z);
        o.z = (1.f - z) * tanh_f(in_.z + r * hn.z) + z * hv.z;
    }
    {
        float r = sigm(ir.w + hr.w), z = sigm(iz.w + hz.w);
        o.w = (1.f - z) * tanh_f(in_.w + r * hn.w) + z * hv.w;
    }
    *(float4*)(out + idx) = o;
    write_split4(o, ohi, olo, (size_t)idx);
}

__global__ void gru_combine4_h0(const float* __restrict__ gi, const float* __restrict__ b_hh,
                                float* __restrict__ out,
                                __nv_bfloat16* __restrict__ ohi, __nv_bfloat16* __restrict__ olo,
                                int n4)
{
    int i4 = blockIdx.x * blockDim.x + threadIdx.x;
    if (i4 >= n4) return;
    int idx = i4 * 4;
    int m = idx >> 9;
    int j = idx & (H - 1);
    const float* gib = gi + (size_t)m * (3 * H);
    float4 ir = *(const float4*)(gib + j);
    float4 iz = *(const float4*)(gib + H + j);
    float4 in_ = *(const float4*)(gib + 2 * H + j);
    float4 hr = *(const float4*)(b_hh + j);
    float4 hz = *(const float4*)(b_hh + H + j);
    float4 hn = *(const float4*)(b_hh + 2 * H + j);
    float4 o;
    {
        float r = sigm(ir.x + hr.x), z = sigm(iz.x + hz.x);
        o.x = (1.f - z) * tanh_f(in_.x + r * hn.x);
    }
    {
        float r = sigm(ir.y + hr.y), z = sigm(iz.y + hz.y);
        o.y = (1.f - z) * tanh_f(in_.y + r * hn.y);
    }
    {
        float r = sigm(ir.z + hr.z), z = sigm(iz.z + hz.z);
        o.z = (1.f - z) * tanh_f(in_.z + r * hn.z);
    }
    {
        float r = sigm(ir.w + hr.w), z = sigm(iz.w + hz.w);
        o.w = (1.f - z) * tanh_f(in_.w + r * hn.w);
    }
    *(float4*)(out + idx) = o;
    write_split4(o, ohi, olo, (size_t)idx);
}

// ======================= fused relation kernel ===============================
__device__ __forceinline__ float dot4(float4 a, float4 b) {
    return a.x * b.x + a.y * b.y + a.z * b.z + a.w * b.w;
}

__global__ __launch_bounds__(128)
void relation_kernel(const float* __restrict__ vert, const float* __restrict__ edge,
                     const int* __restrict__ sub_idx, const int* __restrict__ obj_idx,
                     const float* __restrict__ w_sub, const float* __restrict__ b_sub,
                     const float* __restrict__ w_obj, const float* __restrict__ b_obj,
                     const float* __restrict__ w_out, const float* __restrict__ b_out,
                     const float* __restrict__ w_in,  const float* __restrict__ b_in,
                     __nv_bfloat16* __restrict__ msg_hi, __nv_bfloat16* __restrict__ msg_lo,
                     float* __restrict__ vctx)
{
    const int r = blockIdx.x;
    const int t = threadIdx.x;
    const int si = sub_idx[r];
    const int oi = obj_idx[r];

    float4 s4 = ((const float4*)(vert + (size_t)si * H))[t];
    float4 o4 = ((const float4*)(vert + (size_t)oi * H))[t];
    float4 e4 = ((const float4*)(edge + (size_t)r * H))[t];

    float4 ws1 = ((const float4*)w_sub)[t];
    float4 ws2 = ((const float4*)(w_sub + H))[t];
    float4 wo1 = ((const float4*)w_obj)[t];
    float4 wo2 = ((const float4*)(w_obj + H))[t];
    float4 wu1 = ((const float4*)w_out)[t];
    float4 wu2 = ((const float4*)(w_out + H))[t];
    float4 wi1 = ((const float4*)w_in)[t];
    float4 wi2 = ((const float4*)(w_in + H))[t];

    float d0 = dot4(s4, ws1) + dot4(e4, ws2);
    float d1 = dot4(o4, wo1) + dot4(e4, wo2);
    float d2 = dot4(s4, wu1) + dot4(e4, wu2);
    float d3 = dot4(o4, wi1) + dot4(e4, wi2);

#pragma unroll
    for (int off = 16; off > 0; off >>= 1) {
        d0 += __shfl_down_sync(0xFFFFFFFFu, d0, off);
        d1 += __shfl_down_sync(0xFFFFFFFFu, d1, off);
        d2 += __shfl_down_sync(0xFFFFFFFFu, d2, off);
        d3 += __shfl_down_sync(0xFFFFFFFFu, d3, off);
    }
    __shared__ float red[4][4];
    __shared__ float gates[4];
    int warp = t >> 5, lane = t & 31;
    if (lane == 0) {
        red[warp][0] = d0; red[warp][1] = d1; red[warp][2] = d2; red[warp][3] = d3;
    }
    __syncthreads();
    if (t < 4) {
        float v = red[0][t] + red[1][t] + red[2][t] + red[3][t];
        float bb = (t == 0) ? b_sub[0] : (t == 1) ? b_obj[0] : (t == 2) ? b_out[0] : b_in[0];
        gates[t] = sigm(v + bb);
    }
    __syncthreads();

    float gs = gates[0], go = gates[1], gu = gates[2], gn = gates[3];

    float4 m4;
    m4.x = gs * s4.x + go * o4.x;
    m4.y = gs * s4.y + go * o4.y;
    m4.z = gs * s4.z + go * o4.z;
    m4.w = gs * s4.w + go * o4.w;
    write_split4(m4, msg_hi, msg_lo, (size_t)r * H + t * 4);

    float* vs = vctx + (size_t)si * H + t * 4;
    atomicAdd(vs + 0, gu * e4.x);
    atomicAdd(vs + 1, gu * e4.y);
    atomicAdd(vs + 2, gu * e4.z);
    atomicAdd(vs + 3, gu * e4.w);
    float* vo = vctx + (size_t)oi * H + t * 4;
    atomicAdd(vo + 0, gn * e4.x);
    atomicAdd(vo + 1, gn * e4.y);
    atomicAdd(vo + 2, gn * e4.z);
    atomicAdd(vo + 3, gn * e4.w);
}

// ======================= host orchestration ==================================
template <typename T>
static T* symaddr(const T* sym) {
    void* p = nullptr;
    cudaGetSymbolAddress(&p, (const void*)sym);
    return (T*)p;
}

static void split(const float* in, __nv_bfloat16* hi, __nv_bfloat16* lo, long long n) {
    long long n4 = n >> 2;
    split_bf16<<<(unsigned)((n4 + 255) / 256), 256>>>(in, hi, lo, n4);
}

static void gemmX(const __nv_bfloat16* Ah, const __nv_bfloat16* Al,
                  const __nv_bfloat16* Bh, const __nv_bfloat16* Bl,
                  const float* bias, float* Cf, __nv_bfloat16* Chi, __nv_bfloat16* Clo,
                  int M, int N, int K, int ldc, int act)
{
    dim3 grid((N + 127) / 128, M / 128);
    gemm_bf3<<<grid, 256, GEMM_SMEM>>>(Ah, Al, Bh, Bl, bias, Cf, Chi, Clo, M, N, K, ldc, act);
}

extern "C" void kernel_launch(void* const* d_in, const int* in_sizes, int n_in,
                              void* d_out, int out_size)
{
    const float* x            = (const float*)d_in[0];
    const float* union_feat   = (const float*)d_in[1];
    const int*   sub_idx      = (const int*)d_in[2];
    const int*   obj_idx      = (const int*)d_in[3];
    const float* w_obj_unary  = (const float*)d_in[4];
    const float* b_obj_unary  = (const float*)d_in[5];
    const float* w_edge_unary = (const float*)d_in[6];
    const float* b_edge_unary = (const float*)d_in[7];
    const float* node_w_ih    = (const float*)d_in[8];
    const float* node_w_hh    = (const float*)d_in[9];
    const float* node_b_ih    = (const float*)d_in[10];
    const float* node_b_hh    = (const float*)d_in[11];
    const float* edge_w_ih    = (const float*)d_in[12];
    const float* edge_w_hh    = (const float*)d_in[13];
    const float* edge_b_ih    = (const float*)d_in[14];
    const float* edge_b_hh    = (const float*)d_in[15];
    const float* w_sub_g      = (const float*)d_in[16];
    const float* b_sub_g      = (const float*)d_in[17];
    const float* w_obj_g      = (const float*)d_in[18];
    const float* b_obj_g      = (const float*)d_in[19];
    const float* w_out_g      = (const float*)d_in[20];
    const float* b_out_g      = (const float*)d_in[21];
    const float* w_in_g       = (const float*)d_in[22];
    const float* b_in_g       = (const float*)d_in[23];
    const float* w_obj_fc     = (const float*)d_in[24];
    const float* b_obj_fc     = (const float*)d_in[25];
    const float* w_rel_fc     = (const float*)d_in[26];
    const float* b_rel_fc     = (const float*)d_in[27];

    static int smem_set = 0;
    if (!smem_set) {
        cudaFuncSetAttribute(gemm_bf3, cudaFuncAttributeMaxDynamicSharedMemorySize, GEMM_SMEM);
        smem_set = 1;
    }

    float* vert = symaddr(g_vert);
    float* eA   = symaddr(g_edgeA);
    float* eB   = symaddr(g_edgeB);
    float* vctx = symaddr(g_vctx);
    float* gi   = symaddr(g_gi);
    float* gh   = symaddr(g_gh);

    __nv_bfloat16* uh = symaddr(g_uh);  __nv_bfloat16* ul = symaddr(g_ul);
    __nv_bfloat16* xh = symaddr(g_xh);  __nv_bfloat16* xl = symaddr(g_xl);
    __nv_bfloat16* weuh = symaddr(g_weu_h); __nv_bfloat16* weul = symaddr(g_weu_l);
    __nv_bfloat16* wouh = symaddr(g_wou_h); __nv_bfloat16* woul = symaddr(g_wou_l);
    __nv_bfloat16* wnihh = symaddr(g_wnih_h); __nv_bfloat16* wnihl = symaddr(g_wnih_l);
    __nv_bfloat16* wnhhh = symaddr(g_wnhh_h); __nv_bfloat16* wnhhl = symaddr(g_wnhh_l);
    __nv_bfloat16* weihh = symaddr(g_weih_h); __nv_bfloat16* weihl = symaddr(g_weih_l);
    __nv_bfloat16* wehhh = symaddr(g_wehh_h); __nv_bfloat16* wehhl = symaddr(g_wehh_l);
    __nv_bfloat16* wofh = symaddr(g_wof_h); __nv_bfloat16* wofl = symaddr(g_wof_l);
    __nv_bfloat16* wrfh = symaddr(g_wrf_h); __nv_bfloat16* wrfl = symaddr(g_wrf_l);
    __nv_bfloat16* m1h = symaddr(g_m1h); __nv_bfloat16* m1l = symaddr(g_m1l);
    __nv_bfloat16* pAh = symaddr(g_m2h); __nv_bfloat16* pAl = symaddr(g_m2l);
    __nv_bfloat16* pBh = symaddr(g_m5h); __nv_bfloat16* pBl = symaddr(g_m5l);
    __nv_bfloat16* m3h = symaddr(g_m3h); __nv_bfloat16* m3l = symaddr(g_m3l);
    __nv_bfloat16* m4h = symaddr(g_m4h); __nv_bfloat16* m4l = symaddr(g_m4l);

    const int TPB = 256;
    const int nObjH = N_OBJ * H;
    const int nRelH = N_REL * H;

    // ---- one-time conversions ----
    split(x, xh, xl, (long long)N_OBJ * IN_DIM);
    split(union_feat, uh, ul, (long long)N_REL * POOL);
    split(w_obj_unary, wouh, woul, (long long)H * IN_DIM);
    split(w_edge_unary, weuh, weul, (long long)H * POOL);
    split(node_w_ih, wnihh, wnihl, 3 * H * H);
    split(node_w_hh, wnhhh, wnhhl, 3 * H * H);
    split(edge_w_ih, weihh, weihl, 3 * H * H);
    split(edge_w_hh, wehhh, wehhl, 3 * H * H);
    split(w_obj_fc, wofh, wofl, OBJ_CLS * H);
    split(w_rel_fc, wrfh, wrfl, REL_CLS * H);

    // ---- unary projections (write split planes directly) ----
    gemmX(xh, xl, wouh, woul, b_obj_unary, nullptr, m3h, m3l, N_OBJ, H, IN_DIM, H, 0);
    gemmX(uh, ul, weuh, weul, b_edge_unary, nullptr, m1h, m1l, N_REL, H, POOL, H, 1);

    // ---- initial GRUs (h = 0) ----
    gemmX(m3h, m3l, wnihh, wnihl, node_b_ih, gi, nullptr, nullptr, N_OBJ, 3 * H, H, 3 * H, 0);
    gru_combine4_h0<<<(nObjH / 4 + TPB - 1) / TPB, TPB>>>(gi, node_b_hh, vert, m4h, m4l, nObjH / 4);

    gemmX(m1h, m1l, weihh, weihl, edge_b_ih, gi, nullptr, nullptr, N_REL, 3 * H, H, 3 * H, 0);
    gru_combine4_h0<<<(nRelH / 4 + TPB - 1) / TPB, TPB>>>(gi, edge_b_hh, eA, pAh, pAl, nRelH / 4);

    for (int it = 0; it < NUM_ITER; it++) {
        cudaMemsetAsync(vctx, 0, (size_t)nObjH * sizeof(float));
        relation_kernel<<<N_REL, 128>>>(vert, eA, sub_idx, obj_idx,
                                        w_sub_g, b_sub_g, w_obj_g, b_obj_g,
                                        w_out_g, b_out_g, w_in_g, b_in_g,
                                        m1h, m1l, vctx);

        // edge GRU: eB = GRU(msg, eA)
        gemmX(m1h, m1l, weihh, weihl, edge_b_ih, gi, nullptr, nullptr, N_REL, 3 * H, H, 3 * H, 0);
        gemmX(pAh, pAl, wehhh, wehhl, edge_b_hh, gh, nullptr, nullptr, N_REL, 3 * H, H, 3 * H, 0);
        gru_combine4<<<(nRelH / 4 + TPB - 1) / TPB, TPB>>>(gi, gh, eA, eB, pBh, pBl, nRelH / 4);

        // node GRU: vert = GRU(vctx, vert)
        split(vctx, m3h, m3l, nObjH);
        gemmX(m3h, m3l, wnihh, wnihl, node_b_ih, gi, nullptr, nullptr, N_OBJ, 3 * H, H, 3 * H, 0);
        gemmX(m4h, m4l, wnhhh, wnhhl, node_b_hh, gh, nullptr, nullptr, N_OBJ, 3 * H, H, 3 * H, 0);
        gru_combine4<<<(nObjH / 4 + TPB - 1) / TPB, TPB>>>(gi, gh, vert, vert, m4h, m4l, nObjH / 4);

        { float* t1 = eA; eA = eB; eB = t1; }
        { __nv_bfloat16* t2 = pAh; pAh = pBh; pBh = t2; }
        { __nv_bfloat16* t3 = pAl; pAl = pBl; pBl = t3; }
    }

    // ---- output heads on tensor cores ----
    float* out = (float*)d_out;
    gemmX(m4h, m4l, wofh, wofl, b_obj_fc, out, nullptr, nullptr,
          N_OBJ, OBJ_CLS, H, OBJ_CLS, 0);
    gemmX(pAh, pAl, wrfh, wrfl, b_rel_fc, out + (size_t)N_OBJ * OBJ_CLS, nullptr, nullptr,
          N_REL, REL_CLS, H, REL_CLS, 0);
}

// round 6
// speedup vs baseline: 2.6703x; 1.0695x over previous
#include <cuda_runtime.h>
#include <cuda_bf16.h>
#include <cuda_fp16.h>
#include <math.h>
#include <stdint.h>

#define H        512
#define IN_DIM   4096
#define POOL     4096
#define N_OBJ    8192
#define N_REL    65536
#define OBJ_CLS  151
#define REL_CLS  51
#define NUM_ITER 3
#define RPB      8     // relations per block in relation_kernel

// ======================= scratch (device globals) ============================
__device__ float g_vert[N_OBJ * H];
__device__ float g_edgeA[N_REL * H];
__device__ float g_edgeB[N_REL * H];
__device__ float g_vctx[N_OBJ * H];
__device__ __half g_gi[N_REL * 3 * H];
__device__ __half g_gh[N_REL * 3 * H];

__device__ __nv_bfloat16 g_uh[(size_t)N_REL * POOL];
__device__ __nv_bfloat16 g_ul[(size_t)N_REL * POOL];
__device__ __nv_bfloat16 g_xh[(size_t)N_OBJ * IN_DIM];
__device__ __nv_bfloat16 g_xl[(size_t)N_OBJ * IN_DIM];
__device__ __nv_bfloat16 g_weu_h[H * POOL],   g_weu_l[H * POOL];
__device__ __nv_bfloat16 g_wou_h[H * IN_DIM], g_wou_l[H * IN_DIM];
__device__ __nv_bfloat16 g_wnih_h[3 * H * H], g_wnih_l[3 * H * H];
__device__ __nv_bfloat16 g_wnhh_h[3 * H * H], g_wnhh_l[3 * H * H];
__device__ __nv_bfloat16 g_weih_h[3 * H * H], g_weih_l[3 * H * H];
__device__ __nv_bfloat16 g_wehh_h[3 * H * H], g_wehh_l[3 * H * H];
__device__ __nv_bfloat16 g_wof_h[OBJ_CLS * H], g_wof_l[OBJ_CLS * H];
__device__ __nv_bfloat16 g_wrf_h[REL_CLS * H], g_wrf_l[REL_CLS * H];
__device__ __nv_bfloat16 g_m1h[N_REL * H], g_m1l[N_REL * H];  // rel_rep / msg planes
__device__ __nv_bfloat16 g_m2h[N_REL * H], g_m2l[N_REL * H];  // edge planes (buf A)
__device__ __nv_bfloat16 g_m5h[N_REL * H], g_m5l[N_REL * H];  // edge planes (buf B)
__device__ __nv_bfloat16 g_m3h[N_OBJ * H], g_m3l[N_OBJ * H];  // obj_rep / vctx planes
__device__ __nv_bfloat16 g_m4h[N_OBJ * H], g_m4l[N_OBJ * H];  // vert planes

// ======================= split fp32 -> bf16 hi/lo ============================
__global__ void split_bf16(const float* __restrict__ in, __nv_bfloat16* __restrict__ hi,
                           __nv_bfloat16* __restrict__ lo, long long n4)
{
    long long i = (long long)blockIdx.x * blockDim.x + threadIdx.x;
    if (i >= n4) return;
    float4 v = ((const float4*)in)[i];
    __nv_bfloat162 h01, h23, l01, l23;
    h01.x = __float2bfloat16(v.x); h01.y = __float2bfloat16(v.y);
    h23.x = __float2bfloat16(v.z); h23.y = __float2bfloat16(v.w);
    l01.x = __float2bfloat16(v.x - __bfloat162float(h01.x));
    l01.y = __float2bfloat16(v.y - __bfloat162float(h01.y));
    l23.x = __float2bfloat16(v.z - __bfloat162float(h23.x));
    l23.y = __float2bfloat16(v.w - __bfloat162float(h23.y));
    ((__nv_bfloat162*)hi)[2 * i] = h01; ((__nv_bfloat162*)hi)[2 * i + 1] = h23;
    ((__nv_bfloat162*)lo)[2 * i] = l01; ((__nv_bfloat162*)lo)[2 * i + 1] = l23;
}

// ======================= HMMA split-3 GEMM ===================================
#define NSTAGE 3
#define SLAB_BYTES  16384
#define STAGE_BYTES (4 * SLAB_BYTES)
#define GEMM_SMEM   (NSTAGE * STAGE_BYTES + 1024)

__device__ __forceinline__ uint32_t smem_u32(const void* p) {
    uint32_t a;
    asm("{ .reg .u64 t; cvta.to.shared.u64 t, %1; cvt.u32.u64 %0, t; }" : "=r"(a) : "l"(p));
    return a;
}
__device__ __forceinline__ void cpa16z(uint32_t dst, const void* src, uint32_t sz) {
    asm volatile("cp.async.cg.shared.global [%0], [%1], 16, %2;"
                 :: "r"(dst), "l"(src), "r"(sz) : "memory");
}
__device__ __forceinline__ void ldsm4(uint32_t* r, uint32_t addr) {
    asm volatile("ldmatrix.sync.aligned.m8n8.x4.shared.b16 {%0,%1,%2,%3}, [%4];"
        : "=r"(r[0]), "=r"(r[1]), "=r"(r[2]), "=r"(r[3]) : "r"(addr));
}
__device__ __forceinline__ void mma_bf16(float* d, const uint32_t* a, const uint32_t* b) {
    asm volatile("mma.sync.aligned.m16n8k16.row.col.f32.bf16.bf16.f32 "
        "{%0,%1,%2,%3}, {%4,%5,%6,%7}, {%8,%9}, {%0,%1,%2,%3};"
        : "+f"(d[0]), "+f"(d[1]), "+f"(d[2]), "+f"(d[3])
        : "r"(a[0]), "r"(a[1]), "r"(a[2]), "r"(a[3]), "r"(b[0]), "r"(b[1]));
}

__device__ __forceinline__ void load_slab(uint32_t sbase, const __nv_bfloat16* __restrict__ g,
                                          int row0, int K, int k0, int tid, int limit)
{
#pragma unroll
    for (int i = 0; i < 4; i++) {
        int c = tid + i * 256;
        int r = c >> 3, c16 = c & 7;
        uint32_t boff = (uint32_t)(r * 128 + c16 * 16);
        uint32_t dst = sbase + (boff ^ ((boff >> 3) & 0x70));
        uint32_t sz = (row0 + r < limit) ? 16u : 0u;
        cpa16z(dst, g + (size_t)(row0 + r) * K + k0 + c16 * 8, sz);
    }
}
__device__ __forceinline__ void load_stage(uint32_t st,
        const __nv_bfloat16* Ah, const __nv_bfloat16* Al,
        const __nv_bfloat16* Bh, const __nv_bfloat16* Bl,
        int arow, int brow, int K, int k0, int tid, int M, int N)
{
    load_slab(st,                  Ah, arow, K, k0, tid, M);
    load_slab(st + SLAB_BYTES,     Al, arow, K, k0, tid, M);
    load_slab(st + 2 * SLAB_BYTES, Bh, brow, K, k0, tid, N);
    load_slab(st + 3 * SLAB_BYTES, Bl, brow, K, k0, tid, N);
}

__device__ __forceinline__ void pass_all(uint32_t st,
        const uint32_t* aro, const uint32_t* asx, uint32_t akh,
        const uint32_t* bro, const uint32_t* bsx, uint32_t bkh,
        float acc[4][4][4])
{
    uint32_t aH = st, aL = st + SLAB_BYTES;
    uint32_t bH = st + 2 * SLAB_BYTES, bL = st + 3 * SLAB_BYTES;
#pragma unroll
    for (int ks = 0; ks < 4; ks++) {
        uint32_t ka = (uint32_t)(ks * 32) + akh;
        uint32_t kb = (uint32_t)(ks * 32) + bkh;
        uint32_t ah[4][4], al[4][4], bh[2][4], bl[2][4];
#pragma unroll
        for (int mt = 0; mt < 4; mt++) ldsm4(ah[mt], aH + aro[mt] + (ka ^ asx[mt]));
#pragma unroll
        for (int p = 0; p < 2; p++)    ldsm4(bh[p], bH + bro[p] + (kb ^ bsx[p]));
#pragma unroll
        for (int p = 0; p < 2; p++)    ldsm4(bl[p], bL + bro[p] + (kb ^ bsx[p]));
#pragma unroll
        for (int mt = 0; mt < 4; mt++) ldsm4(al[mt], aL + aro[mt] + (ka ^ asx[mt]));
#pragma unroll
        for (int mt = 0; mt < 4; mt++)
#pragma unroll
            for (int nt = 0; nt < 4; nt++)
                mma_bf16(acc[mt][nt], ah[mt], &bh[nt >> 1][(nt & 1) * 2]);
#pragma unroll
        for (int mt = 0; mt < 4; mt++)
#pragma unroll
            for (int nt = 0; nt < 4; nt++)
                mma_bf16(acc[mt][nt], ah[mt], &bl[nt >> 1][(nt & 1) * 2]);
#pragma unroll
        for (int mt = 0; mt < 4; mt++)
#pragma unroll
            for (int nt = 0; nt < 4; nt++)
                mma_bf16(acc[mt][nt], al[mt], &bh[nt >> 1][(nt & 1) * 2]);
    }
}

// Outputs (exactly one non-null): Cf fp32 (ldc stride, col guards),
// Chf fp16 (ldc stride, N%2==0), Chi/Clo bf16 split planes (N%128==0).
__global__ __launch_bounds__(256, 1)
void gemm_bf3(const __nv_bfloat16* __restrict__ Ah, const __nv_bfloat16* __restrict__ Al,
              const __nv_bfloat16* __restrict__ Bh, const __nv_bfloat16* __restrict__ Bl,
              const float* __restrict__ bias,
              float* __restrict__ Cf, __half* __restrict__ Chf,
              __nv_bfloat16* __restrict__ Chi, __nv_bfloat16* __restrict__ Clo,
              int M, int N, int K, int ldc, int act)
{
    extern __shared__ char dsm[];
    const int tid  = threadIdx.x;
    const int wid  = tid >> 5;
    const int lane = tid & 31;
    const int warp_m = wid & 1;
    const int warp_n = wid >> 1;
    uint32_t base = (smem_u32(dsm) + 1023u) & ~1023u;

    const int arow = blockIdx.y * 128;
    const int brow = blockIdx.x * 128;
    const int nch  = K >> 6;

    uint32_t aro[4], asx[4];
#pragma unroll
    for (int mt = 0; mt < 4; mt++) {
        int r = warp_m * 64 + mt * 16 + (lane & 15);
        aro[mt] = (uint32_t)(r * 128);
        asx[mt] = (uint32_t)((r & 7) << 4);
    }
    uint32_t akh = (uint32_t)((lane >> 4) * 16);
    uint32_t bro[2], bsx[2];
#pragma unroll
    for (int p = 0; p < 2; p++) {
        int r = warp_n * 32 + p * 16 + (lane & 7) + ((lane >> 4) << 3);
        bro[p] = (uint32_t)(r * 128);
        bsx[p] = (uint32_t)((r & 7) << 4);
    }
    uint32_t bkh = (uint32_t)(((lane >> 3) & 1) * 16);

    float acc[4][4][4];
#pragma unroll
    for (int i = 0; i < 4; i++)
#pragma unroll
        for (int j = 0; j < 4; j++)
#pragma unroll
            for (int q = 0; q < 4; q++) acc[i][j][q] = 0.f;

    {
        int pre = (nch < NSTAGE) ? nch : NSTAGE;
        for (int i = 0; i < pre; i++) {
            load_stage(base + i * STAGE_BYTES, Ah, Al, Bh, Bl, arow, brow, K, i * 64, tid, M, N);
            asm volatile("cp.async.commit_group;" ::: "memory");
        }
    }

    for (int i = 0; i < nch; i++) {
        int committed = (nch < i + NSTAGE) ? nch : (i + NSTAGE);
        int pending = committed - i - 1;
        if (pending >= 2)      asm volatile("cp.async.wait_group 2;" ::: "memory");
        else if (pending == 1) asm volatile("cp.async.wait_group 1;" ::: "memory");
        else                   asm volatile("cp.async.wait_group 0;" ::: "memory");
        __syncthreads();

        uint32_t st = base + (uint32_t)(i % NSTAGE) * STAGE_BYTES;
        pass_all(st, aro, asx, akh, bro, bsx, bkh, acc);

        __syncthreads();
        if (i + NSTAGE < nch) {
            load_stage(st, Ah, Al, Bh, Bl, arow, brow, K, (i + NSTAGE) * 64, tid, M, N);
            asm volatile("cp.async.commit_group;" ::: "memory");
        }
    }

    const int qrow = lane >> 2;
    const int qcol = (lane & 3) * 2;
#pragma unroll
    for (int mt = 0; mt < 4; mt++) {
        int m0 = arow + warp_m * 64 + mt * 16 + qrow;
#pragma unroll
        for (int nt = 0; nt < 4; nt++) {
            int n0 = brow + warp_n * 32 + nt * 8 + qcol;
            float b0 = (n0 < N) ? bias[n0] : 0.f;
            float b1 = (n0 + 1 < N) ? bias[n0 + 1] : 0.f;
            float v00 = acc[mt][nt][0] + b0, v01 = acc[mt][nt][1] + b1;
            float v10 = acc[mt][nt][2] + b0, v11 = acc[mt][nt][3] + b1;
            if (act) {
                v00 = fmaxf(v00, 0.f); v01 = fmaxf(v01, 0.f);
                v10 = fmaxf(v10, 0.f); v11 = fmaxf(v11, 0.f);
            }
            if (Cf) {
                if (n0 < N) {
                    Cf[(size_t)m0 * ldc + n0] = v00;
                    Cf[(size_t)(m0 + 8) * ldc + n0] = v10;
                }
                if (n0 + 1 < N) {
                    Cf[(size_t)m0 * ldc + n0 + 1] = v01;
                    Cf[(size_t)(m0 + 8) * ldc + n0 + 1] = v11;
                }
            } else if (Chf) {  // N % 128 == 0 paths
                *(__half2*)(Chf + (size_t)m0 * ldc + n0)       = __floats2half2_rn(v00, v01);
                *(__half2*)(Chf + (size_t)(m0 + 8) * ldc + n0) = __floats2half2_rn(v10, v11);
            } else if (Chi) {
                __nv_bfloat162 h0, h1, l0, l1;
                h0.x = __float2bfloat16(v00); h0.y = __float2bfloat16(v01);
                h1.x = __float2bfloat16(v10); h1.y = __float2bfloat16(v11);
                l0.x = __float2bfloat16(v00 - __bfloat162float(h0.x));
                l0.y = __float2bfloat16(v01 - __bfloat162float(h0.y));
                l1.x = __float2bfloat16(v10 - __bfloat162float(h1.x));
                l1.y = __float2bfloat16(v11 - __bfloat162float(h1.y));
                *(__nv_bfloat162*)(Chi + (size_t)m0 * N + n0)       = h0;
                *(__nv_bfloat162*)(Chi + (size_t)(m0 + 8) * N + n0) = h1;
                *(__nv_bfloat162*)(Clo + (size_t)m0 * N + n0)       = l0;
                *(__nv_bfloat162*)(Clo + (size_t)(m0 + 8) * N + n0) = l1;
            }
        }
    }
}

// ======================= GRU elementwise (fp16 gates, fused split) ===========
__device__ __forceinline__ float sigm(float x) { return 1.f / (1.f + __expf(-x)); }
__device__ __forceinline__ float tanh_f(float x) { return 2.f * sigm(2.f * x) - 1.f; }

__device__ __forceinline__ float4 ld4h(const __half* p) {
    __half2 a = *(const __half2*)p;
    __half2 b = *(const __half2*)(p + 2);
    float2 fa = __half22float2(a), fb = __half22float2(b);
    return make_float4(fa.x, fa.y, fb.x, fb.y);
}

__device__ __forceinline__ void write_split4(float4 v, __nv_bfloat16* hi, __nv_bfloat16* lo,
                                             size_t idx)
{
    __nv_bfloat162 h0, h1, l0, l1;
    h0.x = __float2bfloat16(v.x); h0.y = __float2bfloat16(v.y);
    h1.x = __float2bfloat16(v.z); h1.y = __float2bfloat16(v.w);
    l0.x = __float2bfloat16(v.x - __bfloat162float(h0.x));
    l0.y = __float2bfloat16(v.y - __bfloat162float(h0.y));
    l1.x = __float2bfloat16(v.z - __bfloat162float(h1.x));
    l1.y = __float2bfloat16(v.w - __bfloat162float(h1.y));
    *(__nv_bfloat162*)(hi + idx)     = h0;
    *(__nv_bfloat162*)(hi + idx + 2) = h1;
    *(__nv_bfloat162*)(lo + idx)     = l0;
    *(__nv_bfloat162*)(lo + idx + 2) = l1;
}

__global__ void gru_combine4(const __half* __restrict__ gi, const __half* __restrict__ gh,
                             const float* __restrict__ h, float* __restrict__ out,
                             __nv_bfloat16* __restrict__ ohi, __nv_bfloat16* __restrict__ olo,
                             int n4)
{
    int i4 = blockIdx.x * blockDim.x + threadIdx.x;
    if (i4 >= n4) return;
    int idx = i4 * 4;
    int m = idx >> 9;
    int j = idx & (H - 1);
    const __half* gib = gi + (size_t)m * (3 * H);
    const __half* ghb = gh + (size_t)m * (3 * H);
    float4 ir = ld4h(gib + j);
    float4 iz = ld4h(gib + H + j);
    float4 in_ = ld4h(gib + 2 * H + j);
    float4 hr = ld4h(ghb + j);
    float4 hz = ld4h(ghb + H + j);
    float4 hn = ld4h(ghb + 2 * H + j);
    float4 hv = *(const float4*)(h + idx);
    float4 o;
    { float r = sigm(ir.x + hr.x), z = sigm(iz.x + hz.x);
      o.x = (1.f - z) * tanh_f(in_.x + r * hn.x) + z * hv.x; }
    { float r = sigm(ir.y + hr.y), z = sigm(iz.y + hz.y);
      o.y = (1.f - z) * tanh_f(in_.y + r * hn.y) + z * hv.y; }
    { float r = sigm(ir.z + hr.z), z = sigm(iz.z + hz.z);
      o.z = (1.f - z) * tanh_f(in_.z + r * hn.z) + z * hv.z; }
    { float r = sigm(ir.w + hr.w), z = sigm(iz.w + hz.w);
      o.w = (1.f - z) * tanh_f(in_.w + r * hn.w) + z * hv.w; }
    *(float4*)(out + idx) = o;
    write_split4(o, ohi, olo, (size_t)idx);
}

__global__ void gru_combine4_h0(const __half* __restrict__ gi, const float* __restrict__ b_hh,
                                float* __restrict__ out,
                                __nv_bfloat16* __restrict__ ohi, __nv_bfloat16* __restrict__ olo,
                                int n4)
{
    int i4 = blockIdx.x * blockDim.x + threadIdx.x;
    if (i4 >= n4) return;
    int idx = i4 * 4;
    int m = idx >> 9;
    int j = idx & (H - 1);
    const __half* gib = gi + (size_t)m * (3 * H);
    float4 ir = ld4h(gib + j);
    float4 iz = ld4h(gib + H + j);
    float4 in_ = ld4h(gib + 2 * H + j);
    float4 hr = *(const float4*)(b_hh + j);
    float4 hz = *(const float4*)(b_hh + H + j);
    float4 hn = *(const float4*)(b_hh + 2 * H + j);
    float4 o;
    { float r = sigm(ir.x + hr.x), z = sigm(iz.x + hz.x);
      o.x = (1.f - z) * tanh_f(in_.x + r * hn.x); }
    { float r = sigm(ir.y + hr.y), z = sigm(iz.y + hz.y);
      o.y = (1.f - z) * tanh_f(in_.y + r * hn.y); }
    { float r = sigm(ir.z + hr.z), z = sigm(iz.z + hz.z);
      o.z = (1.f - z) * tanh_f(in_.z + r * hn.z); }
    { float r = sigm(ir.w + hr.w), z = sigm(iz.w + hz.w);
      o.w = (1.f - z) * tanh_f(in_.w + r * hn.w); }
    *(float4*)(out + idx) = o;
    write_split4(o, ohi, olo, (size_t)idx);
}

// ======================= fused relation kernel (batched) =====================
__device__ __forceinline__ float dot4(float4 a, float4 b) {
    return a.x * b.x + a.y * b.y + a.z * b.z + a.w * b.w;
}

__global__ __launch_bounds__(128)
void relation_kernel(const float* __restrict__ vert, const float* __restrict__ edge,
                     const int* __restrict__ sub_idx, const int* __restrict__ obj_idx,
                     const float* __restrict__ w_sub, const float* __restrict__ b_sub,
                     const float* __restrict__ w_obj, const float* __restrict__ b_obj,
                     const float* __restrict__ w_out, const float* __restrict__ b_out,
                     const float* __restrict__ w_in,  const float* __restrict__ b_in,
                     __nv_bfloat16* __restrict__ msg_hi, __nv_bfloat16* __restrict__ msg_lo,
                     float* __restrict__ vctx)
{
    const int t = threadIdx.x;
    const int warp = t >> 5, lane = t & 31;

    // hoist gate weights (per-thread float4 slices) and biases
    float4 ws1 = ((const float4*)w_sub)[t];
    float4 ws2 = ((const float4*)(w_sub + H))[t];
    float4 wo1 = ((const float4*)w_obj)[t];
    float4 wo2 = ((const float4*)(w_obj + H))[t];
    float4 wu1 = ((const float4*)w_out)[t];
    float4 wu2 = ((const float4*)(w_out + H))[t];
    float4 wi1 = ((const float4*)w_in)[t];
    float4 wi2 = ((const float4*)(w_in + H))[t];
    float bb4 = (t == 0) ? b_sub[0] : (t == 1) ? b_obj[0] : (t == 2) ? b_out[0] :
                (t == 3) ? b_in[0] : 0.f;

    __shared__ float red[4][4];
    __shared__ float gates[4];

    const int rbase = blockIdx.x * RPB;
#pragma unroll 1
    for (int rr = 0; rr < RPB; rr++) {
        const int r = rbase + rr;
        const int si = sub_idx[r];
        const int oi = obj_idx[r];

        float4 s4 = ((const float4*)(vert + (size_t)si * H))[t];
        float4 o4 = ((const float4*)(vert + (size_t)oi * H))[t];
        float4 e4 = ((const float4*)(edge + (size_t)r * H))[t];

        float d0 = dot4(s4, ws1) + dot4(e4, ws2);
        float d1 = dot4(o4, wo1) + dot4(e4, wo2);
        float d2 = dot4(s4, wu1) + dot4(e4, wu2);
        float d3 = dot4(o4, wi1) + dot4(e4, wi2);

#pragma unroll
        for (int off = 16; off > 0; off >>= 1) {
            d0 += __shfl_down_sync(0xFFFFFFFFu, d0, off);
            d1 += __shfl_down_sync(0xFFFFFFFFu, d1, off);
            d2 += __shfl_down_sync(0xFFFFFFFFu, d2, off);
            d3 += __shfl_down_sync(0xFFFFFFFFu, d3, off);
        }
        if (lane == 0) {
            red[warp][0] = d0; red[warp][1] = d1; red[warp][2] = d2; red[warp][3] = d3;
        }
        __syncthreads();
        if (t < 4) {
            float v = red[0][t] + red[1][t] + red[2][t] + red[3][t];
            gates[t] = sigm(v + bb4);
        }
        __syncthreads();

        float gs = gates[0], go = gates[1], gu = gates[2], gn = gates[3];
        __syncthreads();   // protect gates[] before next iteration overwrites

        float4 m4;
        m4.x = gs * s4.x + go * o4.x;
        m4.y = gs * s4.y + go * o4.y;
        m4.z = gs * s4.z + go * o4.z;
        m4.w = gs * s4.w + go * o4.w;
        write_split4(m4, msg_hi, msg_lo, (size_t)r * H + t * 4);

        float* vs = vctx + (size_t)si * H + t * 4;
        atomicAdd(vs + 0, gu * e4.x);
        atomicAdd(vs + 1, gu * e4.y);
        atomicAdd(vs + 2, gu * e4.z);
        atomicAdd(vs + 3, gu * e4.w);
        float* vo = vctx + (size_t)oi * H + t * 4;
        atomicAdd(vo + 0, gn * e4.x);
        atomicAdd(vo + 1, gn * e4.y);
        atomicAdd(vo + 2, gn * e4.z);
        atomicAdd(vo + 3, gn * e4.w);
    }
}

// ======================= host orchestration ==================================
template <typename T>
static T* symaddr(const T* sym) {
    void* p = nullptr;
    cudaGetSymbolAddress(&p, (const void*)sym);
    return (T*)p;
}

static void split(const float* in, __nv_bfloat16* hi, __nv_bfloat16* lo, long long n) {
    long long n4 = n >> 2;
    split_bf16<<<(unsigned)((n4 + 255) / 256), 256>>>(in, hi, lo, n4);
}

static void gemmX(const __nv_bfloat16* Ah, const __nv_bfloat16* Al,
                  const __nv_bfloat16* Bh, const __nv_bfloat16* Bl,
                  const float* bias, float* Cf, __half* Chf,
                  __nv_bfloat16* Chi, __nv_bfloat16* Clo,
                  int M, int N, int K, int ldc, int act)
{
    dim3 grid((N + 127) / 128, M / 128);
    gemm_bf3<<<grid, 256, GEMM_SMEM>>>(Ah, Al, Bh, Bl, bias, Cf, Chf, Chi, Clo,
                                       M, N, K, ldc, act);
}

extern "C" void kernel_launch(void* const* d_in, const int* in_sizes, int n_in,
                              void* d_out, int out_size)
{
    const float* x            = (const float*)d_in[0];
    const float* union_feat   = (const float*)d_in[1];
    const int*   sub_idx      = (const int*)d_in[2];
    const int*   obj_idx      = (const int*)d_in[3];
    const float* w_obj_unary  = (const float*)d_in[4];
    const float* b_obj_unary  = (const float*)d_in[5];
    const float* w_edge_unary = (const float*)d_in[6];
    const float* b_edge_unary = (const float*)d_in[7];
    const float* node_w_ih    = (const float*)d_in[8];
    const float* node_w_hh    = (const float*)d_in[9];
    const float* node_b_ih    = (const float*)d_in[10];
    const float* node_b_hh    = (const float*)d_in[11];
    const float* edge_w_ih    = (const float*)d_in[12];
    const float* edge_w_hh    = (const float*)d_in[13];
    const float* edge_b_ih    = (const float*)d_in[14];
    const float* edge_b_hh    = (const float*)d_in[15];
    const float* w_sub_g      = (const float*)d_in[16];
    const float* b_sub_g      = (const float*)d_in[17];
    const float* w_obj_g      = (const float*)d_in[18];
    const float* b_obj_g      = (const float*)d_in[19];
    const float* w_out_g      = (const float*)d_in[20];
    const float* b_out_g      = (const float*)d_in[21];
    const float* w_in_g       = (const float*)d_in[22];
    const float* b_in_g       = (const float*)d_in[23];
    const float* w_obj_fc     = (const float*)d_in[24];
    const float* b_obj_fc     = (const float*)d_in[25];
    const float* w_rel_fc     = (const float*)d_in[26];
    const float* b_rel_fc     = (const float*)d_in[27];

    static int smem_set = 0;
    if (!smem_set) {
        cudaFuncSetAttribute(gemm_bf3, cudaFuncAttributeMaxDynamicSharedMemorySize, GEMM_SMEM);
        smem_set = 1;
    }

    float* vert = symaddr(g_vert);
    float* eA   = symaddr(g_edgeA);
    float* eB   = symaddr(g_edgeB);
    float* vctx = symaddr(g_vctx);
    __half* gi  = symaddr(g_gi);
    __half* gh  = symaddr(g_gh);

    __nv_bfloat16* uh = symaddr(g_uh);  __nv_bfloat16* ul = symaddr(g_ul);
    __nv_bfloat16* xh = symaddr(g_xh);  __nv_bfloat16* xl = symaddr(g_xl);
    __nv_bfloat16* weuh = symaddr(g_weu_h); __nv_bfloat16* weul = symaddr(g_weu_l);
    __nv_bfloat16* wouh = symaddr(g_wou_h); __nv_bfloat16* woul = symaddr(g_wou_l);
    __nv_bfloat16* wnihh = symaddr(g_wnih_h); __nv_bfloat16* wnihl = symaddr(g_wnih_l);
    __nv_bfloat16* wnhhh = symaddr(g_wnhh_h); __nv_bfloat16* wnhhl = symaddr(g_wnhh_l);
    __nv_bfloat16* weihh = symaddr(g_weih_h); __nv_bfloat16* weihl = symaddr(g_weih_l);
    __nv_bfloat16* wehhh = symaddr(g_wehh_h); __nv_bfloat16* wehhl = symaddr(g_wehh_l);
    __nv_bfloat16* wofh = symaddr(g_wof_h); __nv_bfloat16* wofl = symaddr(g_wof_l);
    __nv_bfloat16* wrfh = symaddr(g_wrf_h); __nv_bfloat16* wrfl = symaddr(g_wrf_l);
    __nv_bfloat16* m1h = symaddr(g_m1h); __nv_bfloat16* m1l = symaddr(g_m1l);
    __nv_bfloat16* pAh = symaddr(g_m2h); __nv_bfloat16* pAl = symaddr(g_m2l);
    __nv_bfloat16* pBh = symaddr(g_m5h); __nv_bfloat16* pBl = symaddr(g_m5l);
    __nv_bfloat16* m3h = symaddr(g_m3h); __nv_bfloat16* m3l = symaddr(g_m3l);
    __nv_bfloat16* m4h = symaddr(g_m4h); __nv_bfloat16* m4l = symaddr(g_m4l);

    const int TPB = 256;
    const int nObjH = N_OBJ * H;
    const int nRelH = N_REL * H;

    // launches 0-3: splits needed for the first two GEMMs
    split(x, xh, xl, (long long)N_OBJ * IN_DIM);            // 0
    split(union_feat, uh, ul, (long long)N_REL * POOL);     // 1
    split(w_obj_unary, wouh, woul, (long long)H * IN_DIM);  // 2
    split(w_edge_unary, weuh, weul, (long long)H * POOL);   // 3

    // launch 4: obj unary projection; launch 5: union projection (ncu target)
    gemmX(xh, xl, wouh, woul, b_obj_unary, nullptr, nullptr, m3h, m3l,
          N_OBJ, H, IN_DIM, H, 0);                          // 4
    gemmX(uh, ul, weuh, weul, b_edge_unary, nullptr, nullptr, m1h, m1l,
          N_REL, H, POOL, H, 1);                            // 5

    // remaining one-time weight conversions
    split(node_w_ih, wnihh, wnihl, 3 * H * H);
    split(node_w_hh, wnhhh, wnhhl, 3 * H * H);
    split(edge_w_ih, weihh, weihl, 3 * H * H);
    split(edge_w_hh, wehhh, wehhl, 3 * H * H);
    split(w_obj_fc, wofh, wofl, OBJ_CLS * H);
    split(w_rel_fc, wrfh, wrfl, REL_CLS * H);

    // ---- initial GRUs (h = 0) ----
    gemmX(m3h, m3l, wnihh, wnihl, node_b_ih, nullptr, gi, nullptr, nullptr,
          N_OBJ, 3 * H, H, 3 * H, 0);
    gru_combine4_h0<<<(nObjH / 4 + TPB - 1) / TPB, TPB>>>(gi, node_b_hh, vert, m4h, m4l, nObjH / 4);

    gemmX(m1h, m1l, weihh, weihl, edge_b_ih, nullptr, gi, nullptr, nullptr,
          N_REL, 3 * H, H, 3 * H, 0);
    gru_combine4_h0<<<(nRelH / 4 + TPB - 1) / TPB, TPB>>>(gi, edge_b_hh, eA, pAh, pAl, nRelH / 4);

    for (int it = 0; it < NUM_ITER; it++) {
        cudaMemsetAsync(vctx, 0, (size_t)nObjH * sizeof(float));
        relation_kernel<<<N_REL / RPB, 128>>>(vert, eA, sub_idx, obj_idx,
                                              w_sub_g, b_sub_g, w_obj_g, b_obj_g,
                                              w_out_g, b_out_g, w_in_g, b_in_g,
                                              m1h, m1l, vctx);

        // edge GRU: eB = GRU(msg, eA)
        gemmX(m1h, m1l, weihh, weihl, edge_b_ih, nullptr, gi, nullptr, nullptr,
              N_REL, 3 * H, H, 3 * H, 0);
        gemmX(pAh, pAl, wehhh, wehhl, edge_b_hh, nullptr, gh, nullptr, nullptr,
              N_REL, 3 * H, H, 3 * H, 0);
        gru_combine4<<<(nRelH / 4 + TPB - 1) / TPB, TPB>>>(gi, gh, eA, eB, pBh, pBl, nRelH / 4);

        // node GRU: vert = GRU(vctx, vert)
        split(vctx, m3h, m3l, nObjH);
        gemmX(m3h, m3l, wnihh, wnihl, node_b_ih, nullptr, gi, nullptr, nullptr,
              N_OBJ, 3 * H, H, 3 * H, 0);
        gemmX(m4h, m4l, wnhhh, wnhhl, node_b_hh, nullptr, gh, nullptr, nullptr,
              N_OBJ, 3 * H, H, 3 * H, 0);
        gru_combine4<<<(nObjH / 4 + TPB - 1) / TPB, TPB>>>(gi, gh, vert, vert, m4h, m4l, nObjH / 4);

        { float* t1 = eA; eA = eB; eB = t1; }
        { __nv_bfloat16* t2 = pAh; pAh = pBh; pBh = t2; }
        { __nv_bfloat16* t3 = pAl; pAl = pBl; pBl = t3; }
    }

    // ---- output heads on tensor cores (fp32 out) ----
    float* out = (float*)d_out;
    gemmX(m4h, m4l, wofh, wofl, b_obj_fc, out, nullptr, nullptr, nullptr,
          N_OBJ, OBJ_CLS, H, OBJ_CLS, 0);
    gemmX(pAh, pAl, wrfh, wrfl, b_rel_fc, out + (size_t)N_OBJ * OBJ_CLS, nullptr, nullptr, nullptr,
          N_REL, REL_CLS, H, REL_CLS, 0);
}

// round 8
// speedup vs baseline: 3.6414x; 1.3637x over previous
#include <cuda_runtime.h>
#include <cuda_bf16.h>
#include <cuda_fp16.h>
#include <math.h>
#include <stdint.h>

#define H        512
#define IN_DIM   4096
#define POOL     4096
#define N_OBJ    8192
#define N_REL    65536
#define OBJ_CLS  151
#define REL_CLS  51
#define NUM_ITER 3
#define RPB      8     // relations per block in relation_kernel

// ======================= scratch (device globals) ============================
__device__ float g_vert[N_OBJ * H];
__device__ float g_edgeA[N_REL * H];
__device__ float g_edgeB[N_REL * H];
__device__ float g_vctx[N_OBJ * H];
__device__ __half g_gi[N_REL * 3 * H];
__device__ __half g_gh[N_REL * 3 * H];

// activations: fp16 hi/lo planes
__device__ __half g_uh[(size_t)N_REL * POOL];
__device__ __half g_ul[(size_t)N_REL * POOL];
__device__ __half g_xh[(size_t)N_OBJ * IN_DIM];
__device__ __half g_xl[(size_t)N_OBJ * IN_DIM];
__device__ __half g_m1h[N_REL * H], g_m1l[N_REL * H];  // rel_rep / msg planes
__device__ __half g_m2h[N_REL * H], g_m2l[N_REL * H];  // edge planes (buf A)
__device__ __half g_m5h[N_REL * H], g_m5l[N_REL * H];  // edge planes (buf B)
__device__ __half g_m3h[N_OBJ * H], g_m3l[N_OBJ * H];  // obj_rep / vctx planes
__device__ __half g_m4h[N_OBJ * H], g_m4l[N_OBJ * H];  // vert planes
// weights: single fp16 plane
__device__ __half g_weu[H * POOL];
__device__ __half g_wou[H * IN_DIM];
__device__ __half g_wnih[3 * H * H];
__device__ __half g_wnhh[3 * H * H];
__device__ __half g_weih[3 * H * H];
__device__ __half g_wehh[3 * H * H];
__device__ __half g_wof[OBJ_CLS * H];
__device__ __half g_wrf[REL_CLS * H];

// ======================= conversion kernels ==================================
__global__ void split2_fp16(const float* __restrict__ in, __half* __restrict__ hi,
                            __half* __restrict__ lo, long long n4)
{
    long long i = (long long)blockIdx.x * blockDim.x + threadIdx.x;
    if (i >= n4) return;
    float4 v = ((const float4*)in)[i];
    __half2 h01, h23, l01, l23;
    h01.x = __float2half_rn(v.x); h01.y = __float2half_rn(v.y);
    h23.x = __float2half_rn(v.z); h23.y = __float2half_rn(v.w);
    l01.x = __float2half_rn(v.x - __half2float(h01.x));
    l01.y = __float2half_rn(v.y - __half2float(h01.y));
    l23.x = __float2half_rn(v.z - __half2float(h23.x));
    l23.y = __float2half_rn(v.w - __half2float(h23.y));
    ((__half2*)hi)[2 * i] = h01; ((__half2*)hi)[2 * i + 1] = h23;
    ((__half2*)lo)[2 * i] = l01; ((__half2*)lo)[2 * i + 1] = l23;
}

__global__ void cvt_fp16(const float* __restrict__ in, __half* __restrict__ out, long long n4)
{
    long long i = (long long)blockIdx.x * blockDim.x + threadIdx.x;
    if (i >= n4) return;
    float4 v = ((const float4*)in)[i];
    __half2 a, b;
    a.x = __float2half_rn(v.x); a.y = __float2half_rn(v.y);
    b.x = __float2half_rn(v.z); b.y = __float2half_rn(v.w);
    ((__half2*)out)[2 * i] = a; ((__half2*)out)[2 * i + 1] = b;
}

// ======================= HMMA fp16 2-pass GEMM ===============================
// C[M,N] = (Ah+Al)[M,K] * B[N,K]^T + bias. M%128==0, K%64==0, N arbitrary.
#define NSTAGE 4
#define SLAB_BYTES  16384
#define STAGE_BYTES (3 * SLAB_BYTES)
#define GEMM_SMEM   (NSTAGE * STAGE_BYTES + 1024)

__device__ __forceinline__ uint32_t smem_u32(const void* p) {
    uint32_t a;
    asm("{ .reg .u64 t; cvta.to.shared.u64 t, %1; cvt.u32.u64 %0, t; }" : "=r"(a) : "l"(p));
    return a;
}
__device__ __forceinline__ void cpa16z(uint32_t dst, const void* src, uint32_t sz) {
    asm volatile("cp.async.cg.shared.global [%0], [%1], 16, %2;"
                 :: "r"(dst), "l"(src), "r"(sz) : "memory");
}
__device__ __forceinline__ void ldsm4(uint32_t* r, uint32_t addr) {
    asm volatile("ldmatrix.sync.aligned.m8n8.x4.shared.b16 {%0,%1,%2,%3}, [%4];"
        : "=r"(r[0]), "=r"(r[1]), "=r"(r[2]), "=r"(r[3]) : "r"(addr));
}
__device__ __forceinline__ void mma_f16(float* d, const uint32_t* a, const uint32_t* b) {
    asm volatile("mma.sync.aligned.m16n8k16.row.col.f32.f16.f16.f32 "
        "{%0,%1,%2,%3}, {%4,%5,%6,%7}, {%8,%9}, {%0,%1,%2,%3};"
        : "+f"(d[0]), "+f"(d[1]), "+f"(d[2]), "+f"(d[3])
        : "r"(a[0]), "r"(a[1]), "r"(a[2]), "r"(a[3]), "r"(b[0]), "r"(b[1]));
}

__device__ __forceinline__ void load_slab(uint32_t sbase, const __half* __restrict__ g,
                                          int row0, int K, int k0, int tid, int limit)
{
#pragma unroll
    for (int i = 0; i < 4; i++) {
        int c = tid + i * 256;
        int r = c >> 3, c16 = c & 7;
        uint32_t boff = (uint32_t)(r * 128 + c16 * 16);
        uint32_t dst = sbase + (boff ^ ((boff >> 3) & 0x70));
        uint32_t sz = (row0 + r < limit) ? 16u : 0u;
        cpa16z(dst, g + (size_t)(row0 + r) * K + k0 + c16 * 8, sz);
    }
}
__device__ __forceinline__ void load_stage(uint32_t st,
        const __half* Ah, const __half* Al, const __half* B,
        int arow, int brow, int K, int k0, int tid, int M, int N)
{
    load_slab(st,                  Ah, arow, K, k0, tid, M);
    load_slab(st + SLAB_BYTES,     Al, arow, K, k0, tid, M);
    load_slab(st + 2 * SLAB_BYTES, B,  brow, K, k0, tid, N);
}

// 2-pass over one 64-K stage: 10 ldsm + 32 mma per ks
__device__ __forceinline__ void pass_all(uint32_t st,
        const uint32_t* aro, const uint32_t* asx, uint32_t akh,
        const uint32_t* bro, const uint32_t* bsx, uint32_t bkh,
        float acc[4][4][4])
{
    uint32_t aH = st, aL = st + SLAB_BYTES, bB = st + 2 * SLAB_BYTES;
#pragma unroll
    for (int ks = 0; ks < 4; ks++) {
        uint32_t ka = (uint32_t)(ks * 32) + akh;
        uint32_t kb = (uint32_t)(ks * 32) + bkh;
        uint32_t ah[4][4], al[4][4], b[2][4];
#pragma unroll
        for (int mt = 0; mt < 4; mt++) ldsm4(ah[mt], aH + aro[mt] + (ka ^ asx[mt]));
#pragma unroll
        for (int p = 0; p < 2; p++)    ldsm4(b[p], bB + bro[p] + (kb ^ bsx[p]));
#pragma unroll
        for (int mt = 0; mt < 4; mt++) ldsm4(al[mt], aL + aro[mt] + (ka ^ asx[mt]));
#pragma unroll
        for (int mt = 0; mt < 4; mt++)
#pragma unroll
            for (int nt = 0; nt < 4; nt++)
                mma_f16(acc[mt][nt], ah[mt], &b[nt >> 1][(nt & 1) * 2]);
#pragma unroll
        for (int mt = 0; mt < 4; mt++)
#pragma unroll
            for (int nt = 0; nt < 4; nt++)
                mma_f16(acc[mt][nt], al[mt], &b[nt >> 1][(nt & 1) * 2]);
    }
}

// Outputs (exactly one non-null): Cf fp32 (ldc stride, col guards),
// Chf fp16 (ldc stride, N%128==0), Chi/Clo fp16 split planes (N%128==0).
__global__ __launch_bounds__(256, 1)
void gemm_f16(const __half* __restrict__ Ah, const __half* __restrict__ Al,
              const __half* __restrict__ B, const float* __restrict__ bias,
              float* __restrict__ Cf, __half* __restrict__ Chf,
              __half* __restrict__ Chi, __half* __restrict__ Clo,
              int M, int N, int K, int ldc, int act)
{
    extern __shared__ char dsm[];
    const int tid  = threadIdx.x;
    const int wid  = tid >> 5;
    const int lane = tid & 31;
    const int warp_m = wid & 1;
    const int warp_n = wid >> 1;
    uint32_t base = (smem_u32(dsm) + 1023u) & ~1023u;

    const int arow = blockIdx.y * 128;
    const int brow = blockIdx.x * 128;
    const int nch  = K >> 6;

    uint32_t aro[4], asx[4];
#pragma unroll
    for (int mt = 0; mt < 4; mt++) {
        int r = warp_m * 64 + mt * 16 + (lane & 15);
        aro[mt] = (uint32_t)(r * 128);
        asx[mt] = (uint32_t)((r & 7) << 4);
    }
    uint32_t akh = (uint32_t)((lane >> 4) * 16);
    uint32_t bro[2], bsx[2];
#pragma unroll
    for (int p = 0; p < 2; p++) {
        int r = warp_n * 32 + p * 16 + (lane & 7) + ((lane >> 4) << 3);
        bro[p] = (uint32_t)(r * 128);
        bsx[p] = (uint32_t)((r & 7) << 4);
    }
    uint32_t bkh = (uint32_t)(((lane >> 3) & 1) * 16);

    float acc[4][4][4];
#pragma unroll
    for (int i = 0; i < 4; i++)
#pragma unroll
        for (int j = 0; j < 4; j++)
#pragma unroll
            for (int q = 0; q < 4; q++) acc[i][j][q] = 0.f;

    {
        int pre = (nch < NSTAGE) ? nch : NSTAGE;
        for (int i = 0; i < pre; i++) {
            load_stage(base + i * STAGE_BYTES, Ah, Al, B, arow, brow, K, i * 64, tid, M, N);
            asm volatile("cp.async.commit_group;" ::: "memory");
        }
    }

    for (int i = 0; i < nch; i++) {
        int committed = (nch < i + NSTAGE) ? nch : (i + NSTAGE);
        int pending = committed - i - 1;
        if (pending >= 3)      asm volatile("cp.async.wait_group 3;" ::: "memory");
        else if (pending == 2) asm volatile("cp.async.wait_group 2;" ::: "memory");
        else if (pending == 1) asm volatile("cp.async.wait_group 1;" ::: "memory");
        else                   asm volatile("cp.async.wait_group 0;" ::: "memory");
        __syncthreads();

        uint32_t st = base + (uint32_t)(i % NSTAGE) * STAGE_BYTES;
        pass_all(st, aro, asx, akh, bro, bsx, bkh, acc);

        __syncthreads();
        if (i + NSTAGE < nch) {
            load_stage(st, Ah, Al, B, arow, brow, K, (i + NSTAGE) * 64, tid, M, N);
            asm volatile("cp.async.commit_group;" ::: "memory");
        }
    }

    const int qrow = lane >> 2;
    const int qcol = (lane & 3) * 2;
#pragma unroll
    for (int mt = 0; mt < 4; mt++) {
        int m0 = arow + warp_m * 64 + mt * 16 + qrow;
#pragma unroll
        for (int nt = 0; nt < 4; nt++) {
            int n0 = brow + warp_n * 32 + nt * 8 + qcol;
            float b0 = (n0 < N) ? bias[n0] : 0.f;
            float b1 = (n0 + 1 < N) ? bias[n0 + 1] : 0.f;
            float v00 = acc[mt][nt][0] + b0, v01 = acc[mt][nt][1] + b1;
            float v10 = acc[mt][nt][2] + b0, v11 = acc[mt][nt][3] + b1;
            if (act) {
                v00 = fmaxf(v00, 0.f); v01 = fmaxf(v01, 0.f);
                v10 = fmaxf(v10, 0.f); v11 = fmaxf(v11, 0.f);
            }
            if (Cf) {
                if (n0 < N) {
                    Cf[(size_t)m0 * ldc + n0] = v00;
                    Cf[(size_t)(m0 + 8) * ldc + n0] = v10;
                }
                if (n0 + 1 < N) {
                    Cf[(size_t)m0 * ldc + n0 + 1] = v01;
                    Cf[(size_t)(m0 + 8) * ldc + n0 + 1] = v11;
                }
            } else if (Chf) {
                *(__half2*)(Chf + (size_t)m0 * ldc + n0)       = __floats2half2_rn(v00, v01);
                *(__half2*)(Chf + (size_t)(m0 + 8) * ldc + n0) = __floats2half2_rn(v10, v11);
            } else if (Chi) {
                __half2 h0, h1, l0, l1;
                h0.x = __float2half_rn(v00); h0.y = __float2half_rn(v01);
                h1.x = __float2half_rn(v10); h1.y = __float2half_rn(v11);
                l0.x = __float2half_rn(v00 - __half2float(h0.x));
                l0.y = __float2half_rn(v01 - __half2float(h0.y));
                l1.x = __float2half_rn(v10 - __half2float(h1.x));
                l1.y = __float2half_rn(v11 - __half2float(h1.y));
                *(__half2*)(Chi + (size_t)m0 * N + n0)       = h0;
                *(__half2*)(Chi + (size_t)(m0 + 8) * N + n0) = h1;
                *(__half2*)(Clo + (size_t)m0 * N + n0)       = l0;
                *(__half2*)(Clo + (size_t)(m0 + 8) * N + n0) = l1;
            }
        }
    }
}

// ======================= GRU elementwise (fp16 gates, fused split) ===========
__device__ __forceinline__ float sigm(float x) { return 1.f / (1.f + __expf(-x)); }
__device__ __forceinline__ float tanh_f(float x) { return 2.f * sigm(2.f * x) - 1.f; }

__device__ __forceinline__ float4 ld4h(const __half* p) {
    __half2 a = *(const __half2*)p;
    __half2 b = *(const __half2*)(p + 2);
    float2 fa = __half22float2(a), fb = __half22float2(b);
    return make_float4(fa.x, fa.y, fb.x, fb.y);
}

__device__ __forceinline__ void write_split4h(float4 v, __half* hi, __half* lo, size_t idx)
{
    __half2 h0, h1, l0, l1;
    h0.x = __float2half_rn(v.x); h0.y = __float2half_rn(v.y);
    h1.x = __float2half_rn(v.z); h1.y = __float2half_rn(v.w);
    l0.x = __float2half_rn(v.x - __half2float(h0.x));
    l0.y = __float2half_rn(v.y - __half2float(h0.y));
    l1.x = __float2half_rn(v.z - __half2float(h1.x));
    l1.y = __float2half_rn(v.w - __half2float(h1.y));
    *(__half2*)(hi + idx)     = h0;
    *(__half2*)(hi + idx + 2) = h1;
    *(__half2*)(lo + idx)     = l0;
    *(__half2*)(lo + idx + 2) = l1;
}

__global__ void gru_combine4(const __half* __restrict__ gi, const __half* __restrict__ gh,
                             const float* __restrict__ h, float* __restrict__ out,
                             __half* __restrict__ ohi, __half* __restrict__ olo, int n4)
{
    int i4 = blockIdx.x * blockDim.x + threadIdx.x;
    if (i4 >= n4) return;
    int idx = i4 * 4;
    int m = idx >> 9;
    int j = idx & (H - 1);
    const __half* gib = gi + (size_t)m * (3 * H);
    const __half* ghb = gh + (size_t)m * (3 * H);
    float4 ir = ld4h(gib + j);
    float4 iz = ld4h(gib + H + j);
    float4 in_ = ld4h(gib + 2 * H + j);
    float4 hr = ld4h(ghb + j);
    float4 hz = ld4h(ghb + H + j);
    float4 hn = ld4h(ghb + 2 * H + j);
    float4 hv = *(const float4*)(h + idx);
    float4 o;
    { float r = sigm(ir.x + hr.x), z = sigm(iz.x + hz.x);
      o.x = (1.f - z) * tanh_f(in_.x + r * hn.x) + z * hv.x; }
    { float r = sigm(ir.y + hr.y), z = sigm(iz.y + hz.y);
      o.y = (1.f - z) * tanh_f(in_.y + r * hn.y) + z * hv.y; }
    { float r = sigm(ir.z + hr.z), z = sigm(iz.z + hz.z);
      o.z = (1.f - z) * tanh_f(in_.z + r * hn.z) + z * hv.z; }
    { float r = sigm(ir.w + hr.w), z = sigm(iz.w + hz.w);
      o.w = (1.f - z) * tanh_f(in_.w + r * hn.w) + z * hv.w; }
    *(float4*)(out + idx) = o;
    write_split4h(o, ohi, olo, (size_t)idx);
}

__global__ void gru_combine4_h0(const __half* __restrict__ gi, const float* __restrict__ b_hh,
                                float* __restrict__ out,
                                __half* __restrict__ ohi, __half* __restrict__ olo, int n4)
{
    int i4 = blockIdx.x * blockDim.x + threadIdx.x;
    if (i4 >= n4) return;
    int idx = i4 * 4;
    int m = idx >> 9;
    int j = idx & (H - 1);
    const __half* gib = gi + (size_t)m * (3 * H);
    float4 ir = ld4h(gib + j);
    float4 iz = ld4h(gib + H + j);
    float4 in_ = ld4h(gib + 2 * H + j);
    float4 hr = *(const float4*)(b_hh + j);
    float4 hz = *(const float4*)(b_hh + H + j);
    float4 hn = *(const float4*)(b_hh + 2 * H + j);
    float4 o;
    { float r = sigm(ir.x + hr.x), z = sigm(iz.x + hz.x);
      o.x = (1.f - z) * tanh_f(in_.x + r * hn.x); }
    { float r = sigm(ir.y + hr.y), z = sigm(iz.y + hz.y);
      o.y = (1.f - z) * tanh_f(in_.y + r * hn.y); }
    { float r = sigm(ir.z + hr.z), z = sigm(iz.z + hz.z);
      o.z = (1.f - z) * tanh_f(in_.z + r * hn.z); }
    { float r = sigm(ir.w + hr.w), z = sigm(iz.w + hz.w);
      o.w = (1.f - z) * tanh_f(in_.w + r * hn.w); }
    *(float4*)(out + idx) = o;
    write_split4h(o, ohi, olo, (size_t)idx);
}

// ======================= fused relation kernel (batched) =====================
__device__ __forceinline__ float dot4(float4 a, float4 b) {
    return a.x * b.x + a.y * b.y + a.z * b.z + a.w * b.w;
}

__global__ __launch_bounds__(128)
void relation_kernel(const float* __restrict__ vert, const float* __restrict__ edge,
                     const int* __restrict__ sub_idx, const int* __restrict__ obj_idx,
                     const float* __restrict__ w_sub, const float* __restrict__ b_sub,
                     const float* __restrict__ w_obj, const float* __restrict__ b_obj,
                     const float* __restrict__ w_out, const float* __restrict__ b_out,
                     const float* __restrict__ w_in,  const float* __restrict__ b_in,
                     __half* __restrict__ msg_hi, __half* __restrict__ msg_lo,
                     float* __restrict__ vctx)
{
    const int t = threadIdx.x;
    const int warp = t >> 5, lane = t & 31;

    float4 ws1 = ((const float4*)w_sub)[t];
    float4 ws2 = ((const float4*)(w_sub + H))[t];
    float4 wo1 = ((const float4*)w_obj)[t];
    float4 wo2 = ((const float4*)(w_obj + H))[t];
    float4 wu1 = ((const float4*)w_out)[t];
    float4 wu2 = ((const float4*)(w_out + H))[t];
    float4 wi1 = ((const float4*)w_in)[t];
    float4 wi2 = ((const float4*)(w_in + H))[t];
    float bb4 = (t == 0) ? b_sub[0] : (t == 1) ? b_obj[0] : (t == 2) ? b_out[0] :
                (t == 3) ? b_in[0] : 0.f;

    __shared__ float red[4][4];
    __shared__ float gates[4];

    const int rbase = blockIdx.x * RPB;
#pragma unroll 1
    for (int rr = 0; rr < RPB; rr++) {
        const int r = rbase + rr;
        const int si = sub_idx[r];
        const int oi = obj_idx[r];

        float4 s4 = ((const float4*)(vert + (size_t)si * H))[t];
        float4 o4 = ((const float4*)(vert + (size_t)oi * H))[t];
        float4 e4 = ((const float4*)(edge + (size_t)r * H))[t];

        float d0 = dot4(s4, ws1) + dot4(e4, ws2);
        float d1 = dot4(o4, wo1) + dot4(e4, wo2);
        float d2 = dot4(s4, wu1) + dot4(e4, wu2);
        float d3 = dot4(o4, wi1) + dot4(e4, wi2);

#pragma unroll
        for (int off = 16; off > 0; off >>= 1) {
            d0 += __shfl_down_sync(0xFFFFFFFFu, d0, off);
            d1 += __shfl_down_sync(0xFFFFFFFFu, d1, off);
            d2 += __shfl_down_sync(0xFFFFFFFFu, d2, off);
            d3 += __shfl_down_sync(0xFFFFFFFFu, d3, off);
        }
        if (lane == 0) {
            red[warp][0] = d0; red[warp][1] = d1; red[warp][2] = d2; red[warp][3] = d3;
        }
        __syncthreads();
        if (t < 4) {
            float v = red[0][t] + red[1][t] + red[2][t] + red[3][t];
            gates[t] = sigm(v + bb4);
        }
        __syncthreads();

        float gs = gates[0], go = gates[1], gu = gates[2], gn = gates[3];
        __syncthreads();

        float4 m4;
        m4.x = gs * s4.x + go * o4.x;
        m4.y = gs * s4.y + go * o4.y;
        m4.z = gs * s4.z + go * o4.z;
        m4.w = gs * s4.w + go * o4.w;
        write_split4h(m4, msg_hi, msg_lo, (size_t)r * H + t * 4);

        float* vs = vctx + (size_t)si * H + t * 4;
        atomicAdd(vs + 0, gu * e4.x);
        atomicAdd(vs + 1, gu * e4.y);
        atomicAdd(vs + 2, gu * e4.z);
        atomicAdd(vs + 3, gu * e4.w);
        float* vo = vctx + (size_t)oi * H + t * 4;
        atomicAdd(vo + 0, gn * e4.x);
        atomicAdd(vo + 1, gn * e4.y);
        atomicAdd(vo + 2, gn * e4.z);
        atomicAdd(vo + 3, gn * e4.w);
    }
}

// ======================= host orchestration ==================================
template <typename T>
static T* symaddr(const T* sym) {
    void* p = nullptr;
    cudaGetSymbolAddress(&p, (const void*)sym);
    return (T*)p;
}

static void split2(const float* in, __half* hi, __half* lo, long long n) {
    long long n4 = n >> 2;
    split2_fp16<<<(unsigned)((n4 + 255) / 256), 256>>>(in, hi, lo, n4);
}
static void cvt(const float* in, __half* out, long long n) {
    long long n4 = n >> 2;
    cvt_fp16<<<(unsigned)((n4 + 255) / 256), 256>>>(in, out, n4);
}

static void gemmX(const __half* Ah, const __half* Al, const __half* B,
                  const float* bias, float* Cf, __half* Chf, __half* Chi, __half* Clo,
                  int M, int N, int K, int ldc, int act)
{
    dim3 grid((N + 127) / 128, M / 128);
    gemm_f16<<<grid, 256, GEMM_SMEM>>>(Ah, Al, B, bias, Cf, Chf, Chi, Clo,
                                       M, N, K, ldc, act);
}

extern "C" void kernel_launch(void* const* d_in, const int* in_sizes, int n_in,
                              void* d_out, int out_size)
{
    const float* x            = (const float*)d_in[0];
    const float* union_feat   = (const float*)d_in[1];
    const int*   sub_idx      = (const int*)d_in[2];
    const int*   obj_idx      = (const int*)d_in[3];
    const float* w_obj_unary  = (const float*)d_in[4];
    const float* b_obj_unary  = (const float*)d_in[5];
    const float* w_edge_unary = (const float*)d_in[6];
    const float* b_edge_unary = (const float*)d_in[7];
    const float* node_w_ih    = (const float*)d_in[8];
    const float* node_w_hh    = (const float*)d_in[9];
    const float* node_b_ih    = (const float*)d_in[10];
    const float* node_b_hh    = (const float*)d_in[11];
    const float* edge_w_ih    = (const float*)d_in[12];
    const float* edge_w_hh    = (const float*)d_in[13];
    const float* edge_b_ih    = (const float*)d_in[14];
    const float* edge_b_hh    = (const float*)d_in[15];
    const float* w_sub_g      = (const float*)d_in[16];
    const float* b_sub_g      = (const float*)d_in[17];
    const float* w_obj_g      = (const float*)d_in[18];
    const float* b_obj_g      = (const float*)d_in[19];
    const float* w_out_g      = (const float*)d_in[20];
    const float* b_out_g      = (const float*)d_in[21];
    const float* w_in_g       = (const float*)d_in[22];
    const float* b_in_g       = (const float*)d_in[23];
    const float* w_obj_fc     = (const float*)d_in[24];
    const float* b_obj_fc     = (const float*)d_in[25];
    const float* w_rel_fc     = (const float*)d_in[26];
    const float* b_rel_fc     = (const float*)d_in[27];

    static int smem_set = 0;
    if (!smem_set) {
        cudaFuncSetAttribute(gemm_f16, cudaFuncAttributeMaxDynamicSharedMemorySize, GEMM_SMEM);
        smem_set = 1;
    }

    float* vert = symaddr(g_vert);
    float* eA   = symaddr(g_edgeA);
    float* eB   = symaddr(g_edgeB);
    float* vctx = symaddr(g_vctx);
    __half* gi  = symaddr(g_gi);
    __half* gh  = symaddr(g_gh);

    __half* uh = symaddr(g_uh);  __half* ul = symaddr(g_ul);
    __half* xh = symaddr(g_xh);  __half* xl = symaddr(g_xl);
    __half* weu = symaddr(g_weu);
    __half* wou = symaddr(g_wou);
    __half* wnih = symaddr(g_wnih);
    __half* wnhh = symaddr(g_wnhh);
    __half* weih = symaddr(g_weih);
    __half* wehh = symaddr(g_wehh);
    __half* wof = symaddr(g_wof);
    __half* wrf = symaddr(g_wrf);
    __half* m1h = symaddr(g_m1h); __half* m1l = symaddr(g_m1l);
    __half* pAh = symaddr(g_m2h); __half* pAl = symaddr(g_m2l);
    __half* pBh = symaddr(g_m5h); __half* pBl = symaddr(g_m5l);
    __half* m3h = symaddr(g_m3h); __half* m3l = symaddr(g_m3l);
    __half* m4h = symaddr(g_m4h); __half* m4l = symaddr(g_m4l);

    const int TPB = 256;
    const int nObjH = N_OBJ * H;
    const int nRelH = N_REL * H;

    // launches 0-3
    split2(x, xh, xl, (long long)N_OBJ * IN_DIM);           // 0
    split2(union_feat, uh, ul, (long long)N_REL * POOL);    // 1
    cvt(w_obj_unary, wou, (long long)H * IN_DIM);           // 2
    cvt(w_edge_unary, weu, (long long)H * POOL);            // 3

    // launch 4: obj unary; launch 5: union projection (ncu target)
    gemmX(xh, xl, wou, b_obj_unary, nullptr, nullptr, m3h, m3l,
          N_OBJ, H, IN_DIM, H, 0);                          // 4
    gemmX(uh, ul, weu, b_edge_unary, nullptr, nullptr, m1h, m1l,
          N_REL, H, POOL, H, 1);                            // 5

    cvt(node_w_ih, wnih, 3 * H * H);
    cvt(node_w_hh, wnhh, 3 * H * H);
    cvt(edge_w_ih, weih, 3 * H * H);
    cvt(edge_w_hh, wehh, 3 * H * H);
    cvt(w_obj_fc, wof, (long long)OBJ_CLS * H);
    cvt(w_rel_fc, wrf, (long long)REL_CLS * H);

    // ---- initial GRUs (h = 0) ----
    gemmX(m3h, m3l, wnih, node_b_ih, nullptr, gi, nullptr, nullptr,
          N_OBJ, 3 * H, H, 3 * H, 0);
    gru_combine4_h0<<<(nObjH / 4 + TPB - 1) / TPB, TPB>>>(gi, node_b_hh, vert, m4h, m4l, nObjH / 4);

    gemmX(m1h, m1l, weih, edge_b_ih, nullptr, gi, nullptr, nullptr,
          N_REL, 3 * H, H, 3 * H, 0);
    gru_combine4_h0<<<(nRelH / 4 + TPB - 1) / TPB, TPB>>>(gi, edge_b_hh, eA, pAh, pAl, nRelH / 4);

    for (int it = 0; it < NUM_ITER; it++) {
        cudaMemsetAsync(vctx, 0, (size_t)nObjH * sizeof(float));
        relation_kernel<<<N_REL / RPB, 128>>>(vert, eA, sub_idx, obj_idx,
                                              w_sub_g, b_sub_g, w_obj_g, b_obj_g,
                                              w_out_g, b_out_g, w_in_g, b_in_g,
                                              m1h, m1l, vctx);

        // edge GRU: eB = GRU(msg, eA)
        gemmX(m1h, m1l, weih, edge_b_ih, nullptr, gi, nullptr, nullptr,
              N_REL, 3 * H, H, 3 * H, 0);
        gemmX(pAh, pAl, wehh, edge_b_hh, nullptr, gh, nullptr, nullptr,
              N_REL, 3 * H, H, 3 * H, 0);
        gru_combine4<<<(nRelH / 4 + TPB - 1) / TPB, TPB>>>(gi, gh, eA, eB, pBh, pBl, nRelH / 4);

        // node GRU: vert = GRU(vctx, vert)
        split2(vctx, m3h, m3l, nObjH);
        gemmX(m3h, m3l, wnih, node_b_ih, nullptr, gi, nullptr, nullptr,
              N_OBJ, 3 * H, H, 3 * H, 0);
        gemmX(m4h, m4l, wnhh, node_b_hh, nullptr, gh, nullptr, nullptr,
              N_OBJ, 3 * H, H, 3 * H, 0);
        gru_combine4<<<(nObjH / 4 + TPB - 1) / TPB, TPB>>>(gi, gh, vert, vert, m4h, m4l, nObjH / 4);

        { float* t1 = eA; eA = eB; eB = t1; }
        { __half* t2 = pAh; pAh = pBh; pBh = t2; }
        { __half* t3 = pAl; pAl = pBl; pBl = t3; }
    }

    // ---- output heads (fp32 out) ----
    float* out = (float*)d_out;
    gemmX(m4h, m4l, wof, b_obj_fc, out, nullptr, nullptr, nullptr,
          N_OBJ, OBJ_CLS, H, OBJ_CLS, 0);
    gemmX(pAh, pAl, wrf, b_rel_fc, out + (size_t)N_OBJ * OBJ_CLS, nullptr, nullptr, nullptr,
          N_REL, REL_CLS, H, REL_CLS, 0);
}

// round 9
// speedup vs baseline: 4.5392x; 1.2466x over previous
#include <cuda_runtime.h>
#include <cuda_fp16.h>
#include <math.h>
#include <stdint.h>

#define H        512
#define IN_DIM   4096
#define POOL     4096
#define N_OBJ    8192
#define N_REL    65536
#define OBJ_CLS  151
#define REL_CLS  51
#define NUM_ITER 3
#define RPB      8

// ======================= scratch (device globals) ============================
__device__ float g_vert[N_OBJ * H];
__device__ float g_edgeA[N_REL * H];
__device__ float g_edgeB[N_REL * H];
__device__ float g_vctx[N_OBJ * H];
__device__ __half g_gi[N_REL * 3 * H];
__device__ __half g_gh[N_REL * 3 * H];

// split-2 inputs (unary projections only)
__device__ __half g_uh[(size_t)N_REL * POOL];
__device__ __half g_ul[(size_t)N_REL * POOL];
__device__ __half g_xh[(size_t)N_OBJ * IN_DIM];
__device__ __half g_xl[(size_t)N_OBJ * IN_DIM];
// single fp16 planes
__device__ __half g_rep1[N_REL * H];             // rel_rep / msg
__device__ __half g_sA[N_REL * H];               // edge plane buf A
__device__ __half g_sB[N_REL * H];               // edge plane buf B
__device__ __half g_vh[N_OBJ * H];               // vert plane
__device__ __half g_vch[N_OBJ * H];              // obj_rep / vctx plane
// weights single fp16
__device__ __half g_weu[H * POOL];
__device__ __half g_wou[H * IN_DIM];
__device__ __half g_wnih[3 * H * H];
__device__ __half g_wnhh[3 * H * H];
__device__ __half g_weih[3 * H * H];
__device__ __half g_wehh[3 * H * H];
__device__ __half g_wof[OBJ_CLS * H];
__device__ __half g_wrf[REL_CLS * H];

// ======================= conversion kernels ==================================
__global__ void split2_fp16(const float* __restrict__ in, __half* __restrict__ hi,
                            __half* __restrict__ lo, long long n4)
{
    long long i = (long long)blockIdx.x * blockDim.x + threadIdx.x;
    if (i >= n4) return;
    float4 v = ((const float4*)in)[i];
    __half2 h01, h23, l01, l23;
    h01.x = __float2half_rn(v.x); h01.y = __float2half_rn(v.y);
    h23.x = __float2half_rn(v.z); h23.y = __float2half_rn(v.w);
    l01.x = __float2half_rn(v.x - __half2float(h01.x));
    l01.y = __float2half_rn(v.y - __half2float(h01.y));
    l23.x = __float2half_rn(v.z - __half2float(h23.x));
    l23.y = __float2half_rn(v.w - __half2float(h23.y));
    ((__half2*)hi)[2 * i] = h01; ((__half2*)hi)[2 * i + 1] = h23;
    ((__half2*)lo)[2 * i] = l01; ((__half2*)lo)[2 * i + 1] = l23;
}

__global__ void cvt_fp16(const float* __restrict__ in, __half* __restrict__ out, long long n4)
{
    long long i = (long long)blockIdx.x * blockDim.x + threadIdx.x;
    if (i >= n4) return;
    float4 v = ((const float4*)in)[i];
    __half2 a, b;
    a.x = __float2half_rn(v.x); a.y = __float2half_rn(v.y);
    b.x = __float2half_rn(v.z); b.y = __float2half_rn(v.w);
    ((__half2*)out)[2 * i] = a; ((__half2*)out)[2 * i + 1] = b;
}

// ======================= HMMA fp16 GEMM (1- or 2-pass A) =====================
// C[M,N] = (Ah[+Al])[M,K] * B[N,K]^T + bias. M%128==0, K%64==0.
#define NSTAGE 4
#define SLAB_BYTES 16384

__device__ __forceinline__ uint32_t smem_u32(const void* p) {
    uint32_t a;
    asm("{ .reg .u64 t; cvta.to.shared.u64 t, %1; cvt.u32.u64 %0, t; }" : "=r"(a) : "l"(p));
    return a;
}
__device__ __forceinline__ void cpa16z(uint32_t dst, const void* src, uint32_t sz) {
    asm volatile("cp.async.cg.shared.global [%0], [%1], 16, %2;"
                 :: "r"(dst), "l"(src), "r"(sz) : "memory");
}
__device__ __forceinline__ void ldsm4(uint32_t* r, uint32_t addr) {
    asm volatile("ldmatrix.sync.aligned.m8n8.x4.shared.b16 {%0,%1,%2,%3}, [%4];"
        : "=r"(r[0]), "=r"(r[1]), "=r"(r[2]), "=r"(r[3]) : "r"(addr));
}
__device__ __forceinline__ void mma_f16(float* d, const uint32_t* a, const uint32_t* b) {
    asm volatile("mma.sync.aligned.m16n8k16.row.col.f32.f16.f16.f32 "
        "{%0,%1,%2,%3}, {%4,%5,%6,%7}, {%8,%9}, {%0,%1,%2,%3};"
        : "+f"(d[0]), "+f"(d[1]), "+f"(d[2]), "+f"(d[3])
        : "r"(a[0]), "r"(a[1]), "r"(a[2]), "r"(a[3]), "r"(b[0]), "r"(b[1]));
}

__device__ __forceinline__ void load_slab(uint32_t sbase, const __half* __restrict__ g,
                                          int row0, int K, int k0, int tid, int limit)
{
#pragma unroll
    for (int i = 0; i < 4; i++) {
        int c = tid + i * 256;
        int r = c >> 3, c16 = c & 7;
        uint32_t boff = (uint32_t)(r * 128 + c16 * 16);
        uint32_t dst = sbase + (boff ^ ((boff >> 3) & 0x70));
        uint32_t sz = (row0 + r < limit) ? 16u : 0u;
        cpa16z(dst, g + (size_t)(row0 + r) * K + k0 + c16 * 8, sz);
    }
}

template <int NPASS>
__global__ __launch_bounds__(256, 1)
void gemm_f16(const __half* __restrict__ Ah, const __half* __restrict__ Al,
              const __half* __restrict__ B, const float* __restrict__ bias,
              float* __restrict__ Cf, __half* __restrict__ Chf,
              int M, int N, int K, int ldc, int act)
{
    constexpr int STB = (NPASS + 1) * SLAB_BYTES;
    extern __shared__ char dsm[];
    const int tid  = threadIdx.x;
    const int wid  = tid >> 5;
    const int lane = tid & 31;
    const int warp_m = wid & 1;
    const int warp_n = wid >> 1;
    uint32_t base = (smem_u32(dsm) + 1023u) & ~1023u;

    const int arow = blockIdx.y * 128;
    const int brow = blockIdx.x * 128;
    const int nch  = K >> 6;

    uint32_t aro[4], asx[4];
#pragma unroll
    for (int mt = 0; mt < 4; mt++) {
        int r = warp_m * 64 + mt * 16 + (lane & 15);
        aro[mt] = (uint32_t)(r * 128);
        asx[mt] = (uint32_t)((r & 7) << 4);
    }
    uint32_t akh = (uint32_t)((lane >> 4) * 16);
    uint32_t bro[2], bsx[2];
#pragma unroll
    for (int p = 0; p < 2; p++) {
        int r = warp_n * 32 + p * 16 + (lane & 7) + ((lane >> 4) << 3);
        bro[p] = (uint32_t)(r * 128);
        bsx[p] = (uint32_t)((r & 7) << 4);
    }
    uint32_t bkh = (uint32_t)(((lane >> 3) & 1) * 16);

    float acc[4][4][4];
#pragma unroll
    for (int i = 0; i < 4; i++)
#pragma unroll
        for (int j = 0; j < 4; j++)
#pragma unroll
            for (int q = 0; q < 4; q++) acc[i][j][q] = 0.f;

    {
        int pre = (nch < NSTAGE) ? nch : NSTAGE;
        for (int i = 0; i < pre; i++) {
            uint32_t st = base + i * STB;
            load_slab(st, Ah, arow, K, i * 64, tid, M);
            if (NPASS == 2) load_slab(st + SLAB_BYTES, Al, arow, K, i * 64, tid, M);
            load_slab(st + NPASS * SLAB_BYTES, B, brow, K, i * 64, tid, N);
            asm volatile("cp.async.commit_group;" ::: "memory");
        }
    }

    for (int i = 0; i < nch; i++) {
        int committed = (nch < i + NSTAGE) ? nch : (i + NSTAGE);
        int pending = committed - i - 1;
        if (pending >= 3)      asm volatile("cp.async.wait_group 3;" ::: "memory");
        else if (pending == 2) asm volatile("cp.async.wait_group 2;" ::: "memory");
        else if (pending == 1) asm volatile("cp.async.wait_group 1;" ::: "memory");
        else                   asm volatile("cp.async.wait_group 0;" ::: "memory");
        __syncthreads();

        uint32_t st = base + (uint32_t)(i % NSTAGE) * STB;
        uint32_t aH = st, bB = st + NPASS * SLAB_BYTES;
#pragma unroll
        for (int ks = 0; ks < 4; ks++) {
            uint32_t ka = (uint32_t)(ks * 32) + akh;
            uint32_t kb = (uint32_t)(ks * 32) + bkh;
            uint32_t ah[4][4], b[2][4];
#pragma unroll
            for (int mt = 0; mt < 4; mt++) ldsm4(ah[mt], aH + aro[mt] + (ka ^ asx[mt]));
#pragma unroll
            for (int p = 0; p < 2; p++)    ldsm4(b[p], bB + bro[p] + (kb ^ bsx[p]));
#pragma unroll
            for (int mt = 0; mt < 4; mt++)
#pragma unroll
                for (int nt = 0; nt < 4; nt++)
                    mma_f16(acc[mt][nt], ah[mt], &b[nt >> 1][(nt & 1) * 2]);
            if (NPASS == 2) {
                uint32_t al[4][4];
                uint32_t aL = st + SLAB_BYTES;
#pragma unroll
                for (int mt = 0; mt < 4; mt++) ldsm4(al[mt], aL + aro[mt] + (ka ^ asx[mt]));
#pragma unroll
                for (int mt = 0; mt < 4; mt++)
#pragma unroll
                    for (int nt = 0; nt < 4; nt++)
                        mma_f16(acc[mt][nt], al[mt], &b[nt >> 1][(nt & 1) * 2]);
            }
        }

        __syncthreads();
        if (i + NSTAGE < nch) {
            int j = i + NSTAGE;
            load_slab(st, Ah, arow, K, j * 64, tid, M);
            if (NPASS == 2) load_slab(st + SLAB_BYTES, Al, arow, K, j * 64, tid, M);
            load_slab(st + NPASS * SLAB_BYTES, B, brow, K, j * 64, tid, N);
            asm volatile("cp.async.commit_group;" ::: "memory");
        }
    }

    const int qrow = lane >> 2;
    const int qcol = (lane & 3) * 2;
#pragma unroll
    for (int mt = 0; mt < 4; mt++) {
        int m0 = arow + warp_m * 64 + mt * 16 + qrow;
#pragma unroll
        for (int nt = 0; nt < 4; nt++) {
            int n0 = brow + warp_n * 32 + nt * 8 + qcol;
            float b0 = (n0 < N) ? bias[n0] : 0.f;
            float b1 = (n0 + 1 < N) ? bias[n0 + 1] : 0.f;
            float v00 = acc[mt][nt][0] + b0, v01 = acc[mt][nt][1] + b1;
            float v10 = acc[mt][nt][2] + b0, v11 = acc[mt][nt][3] + b1;
            if (act) {
                v00 = fmaxf(v00, 0.f); v01 = fmaxf(v01, 0.f);
                v10 = fmaxf(v10, 0.f); v11 = fmaxf(v11, 0.f);
            }
            if (Cf) {
                if (n0 < N) {
                    Cf[(size_t)m0 * ldc + n0] = v00;
                    Cf[(size_t)(m0 + 8) * ldc + n0] = v10;
                }
                if (n0 + 1 < N) {
                    Cf[(size_t)m0 * ldc + n0 + 1] = v01;
                    Cf[(size_t)(m0 + 8) * ldc + n0 + 1] = v11;
                }
            } else {   // fp16 out; all such N are multiples of 128
                *(__half2*)(Chf + (size_t)m0 * ldc + n0)       = __floats2half2_rn(v00, v01);
                *(__half2*)(Chf + (size_t)(m0 + 8) * ldc + n0) = __floats2half2_rn(v10, v11);
            }
        }
    }
}

// ======================= GRU elementwise =====================================
__device__ __forceinline__ float sigm(float x) { return 1.f / (1.f + __expf(-x)); }
__device__ __forceinline__ float tanh_f(float x) { return 2.f * sigm(2.f * x) - 1.f; }

__device__ __forceinline__ float4 ld4h(const __half* p) {
    __half2 a = *(const __half2*)p;
    __half2 b = *(const __half2*)(p + 2);
    float2 fa = __half22float2(a), fb = __half22float2(b);
    return make_float4(fa.x, fa.y, fb.x, fb.y);
}
__device__ __forceinline__ void st4h(float4 v, __half* p) {
    *(__half2*)p       = __floats2half2_rn(v.x, v.y);
    *(__half2*)(p + 2) = __floats2half2_rn(v.z, v.w);
}

__global__ void gru_combine4(const __half* __restrict__ gi, const __half* __restrict__ gh,
                             const float* __restrict__ h, float* __restrict__ out,
                             __half* __restrict__ ohi, int n4)
{
    int i4 = blockIdx.x * blockDim.x + threadIdx.x;
    if (i4 >= n4) return;
    int idx = i4 * 4;
    int m = idx >> 9;
    int j = idx & (H - 1);
    const __half* gib = gi + (size_t)m * (3 * H);
    const __half* ghb = gh + (size_t)m * (3 * H);
    float4 ir = ld4h(gib + j);
    float4 iz = ld4h(gib + H + j);
    float4 in_ = ld4h(gib + 2 * H + j);
    float4 hr = ld4h(ghb + j);
    float4 hz = ld4h(ghb + H + j);
    float4 hn = ld4h(ghb + 2 * H + j);
    float4 hv = *(const float4*)(h + idx);
    float4 o;
    { float r = sigm(ir.x + hr.x), z = sigm(iz.x + hz.x);
      o.x = (1.f - z) * tanh_f(in_.x + r * hn.x) + z * hv.x; }
    { float r = sigm(ir.y + hr.y), z = sigm(iz.y + hz.y);
      o.y = (1.f - z) * tanh_f(in_.y + r * hn.y) + z * hv.y; }
    { float r = sigm(ir.z + hr.z), z = sigm(iz.z + hz.z);
      o.z = (1.f - z) * tanh_f(in_.z + r * hn.z) + z * hv.z; }
    { float r = sigm(ir.w + hr.w), z = sigm(iz.w + hz.w);
      o.w = (1.f - z) * tanh_f(in_.w + r * hn.w) + z * hv.w; }
    *(float4*)(out + idx) = o;
    st4h(o, ohi + idx);
}

__global__ void gru_combine4_h0(const __half* __restrict__ gi, const float* __restrict__ b_hh,
                                float* __restrict__ out, __half* __restrict__ ohi, int n4)
{
    int i4 = blockIdx.x * blockDim.x + threadIdx.x;
    if (i4 >= n4) return;
    int idx = i4 * 4;
    int m = idx >> 9;
    int j = idx & (H - 1);
    const __half* gib = gi + (size_t)m * (3 * H);
    float4 ir = ld4h(gib + j);
    float4 iz = ld4h(gib + H + j);
    float4 in_ = ld4h(gib + 2 * H + j);
    float4 hr = *(const float4*)(b_hh + j);
    float4 hz = *(const float4*)(b_hh + H + j);
    float4 hn = *(const float4*)(b_hh + 2 * H + j);
    float4 o;
    { float r = sigm(ir.x + hr.x), z = sigm(iz.x + hz.x);
      o.x = (1.f - z) * tanh_f(in_.x + r * hn.x); }
    { float r = sigm(ir.y + hr.y), z = sigm(iz.y + hz.y);
      o.y = (1.f - z) * tanh_f(in_.y + r * hn.y); }
    { float r = sigm(ir.z + hr.z), z = sigm(iz.z + hz.z);
      o.z = (1.f - z) * tanh_f(in_.z + r * hn.z); }
    { float r = sigm(ir.w + hr.w), z = sigm(iz.w + hz.w);
      o.w = (1.f - z) * tanh_f(in_.w + r * hn.w); }
    *(float4*)(out + idx) = o;
    st4h(o, ohi + idx);
}

// ======================= fused relation kernel ===============================
__device__ __forceinline__ float dot4(float4 a, float4 b) {
    return a.x * b.x + a.y * b.y + a.z * b.z + a.w * b.w;
}

__global__ __launch_bounds__(128)
void relation_kernel(const float* __restrict__ vert, const float* __restrict__ edge,
                     const int* __restrict__ sub_idx, const int* __restrict__ obj_idx,
                     const float* __restrict__ w_sub, const float* __restrict__ b_sub,
                     const float* __restrict__ w_obj, const float* __restrict__ b_obj,
                     const float* __restrict__ w_out, const float* __restrict__ b_out,
                     const float* __restrict__ w_in,  const float* __restrict__ b_in,
                     __half* __restrict__ msg, float* __restrict__ vctx)
{
    const int t = threadIdx.x;
    const int warp = t >> 5, lane = t & 31;

    float4 ws1 = ((const float4*)w_sub)[t];
    float4 ws2 = ((const float4*)(w_sub + H))[t];
    float4 wo1 = ((const float4*)w_obj)[t];
    float4 wo2 = ((const float4*)(w_obj + H))[t];
    float4 wu1 = ((const float4*)w_out)[t];
    float4 wu2 = ((const float4*)(w_out + H))[t];
    float4 wi1 = ((const float4*)w_in)[t];
    float4 wi2 = ((const float4*)(w_in + H))[t];
    float bb4 = (t == 0) ? b_sub[0] : (t == 1) ? b_obj[0] : (t == 2) ? b_out[0] :
                (t == 3) ? b_in[0] : 0.f;

    __shared__ float red[4][4];
    __shared__ float gates[4];

    const int rbase = blockIdx.x * RPB;
#pragma unroll 1
    for (int rr = 0; rr < RPB; rr++) {
        const int r = rbase + rr;
        const int si = sub_idx[r];
        const int oi = obj_idx[r];

        float4 s4 = ((const float4*)(vert + (size_t)si * H))[t];
        float4 o4 = ((const float4*)(vert + (size_t)oi * H))[t];
        float4 e4 = ((const float4*)(edge + (size_t)r * H))[t];

        float d0 = dot4(s4, ws1) + dot4(e4, ws2);
        float d1 = dot4(o4, wo1) + dot4(e4, wo2);
        float d2 = dot4(s4, wu1) + dot4(e4, wu2);
        float d3 = dot4(o4, wi1) + dot4(e4, wi2);

#pragma unroll
        for (int off = 16; off > 0; off >>= 1) {
            d0 += __shfl_down_sync(0xFFFFFFFFu, d0, off);
            d1 += __shfl_down_sync(0xFFFFFFFFu, d1, off);
            d2 += __shfl_down_sync(0xFFFFFFFFu, d2, off);
            d3 += __shfl_down_sync(0xFFFFFFFFu, d3, off);
        }
        if (lane == 0) {
            red[warp][0] = d0; red[warp][1] = d1; red[warp][2] = d2; red[warp][3] = d3;
        }
        __syncthreads();
        if (t < 4) {
            float v = red[0][t] + red[1][t] + red[2][t] + red[3][t];
            gates[t] = sigm(v + bb4);
        }
        __syncthreads();

        float gs = gates[0], go = gates[1], gu = gates[2], gn = gates[3];
        __syncthreads();

        float4 m4;
        m4.x = gs * s4.x + go * o4.x;
        m4.y = gs * s4.y + go * o4.y;
        m4.z = gs * s4.z + go * o4.z;
        m4.w = gs * s4.w + go * o4.w;
        st4h(m4, msg + (size_t)r * H + t * 4);

        float* vs = vctx + (size_t)si * H + t * 4;
        atomicAdd(vs + 0, gu * e4.x);
        atomicAdd(vs + 1, gu * e4.y);
        atomicAdd(vs + 2, gu * e4.z);
        atomicAdd(vs + 3, gu * e4.w);
        float* vo = vctx + (size_t)oi * H + t * 4;
        atomicAdd(vo + 0, gn * e4.x);
        atomicAdd(vo + 1, gn * e4.y);
        atomicAdd(vo + 2, gn * e4.z);
        atomicAdd(vo + 3, gn * e4.w);
    }
}

// ======================= host orchestration ==================================
template <typename T>
static T* symaddr(const T* sym) {
    void* p = nullptr;
    cudaGetSymbolAddress(&p, (const void*)sym);
    return (T*)p;
}

static void split2(const float* in, __half* hi, __half* lo, long long n) {
    long long n4 = n >> 2;
    split2_fp16<<<(unsigned)((n4 + 255) / 256), 256>>>(in, hi, lo, n4);
}
static void cvt(const float* in, __half* out, long long n) {
    long long n4 = n >> 2;
    cvt_fp16<<<(unsigned)((n4 + 255) / 256), 256>>>(in, out, n4);
}

#define SMEM1 (NSTAGE * 2 * SLAB_BYTES + 1024)
#define SMEM2 (NSTAGE * 3 * SLAB_BYTES + 1024)

static void gemm1(const __half* A, const __half* B, const float* bias,
                  float* Cf, __half* Chf, int M, int N, int K, int ldc, int act)
{
    dim3 grid((N + 127) / 128, M / 128);
    gemm_f16<1><<<grid, 256, SMEM1>>>(A, nullptr, B, bias, Cf, Chf, M, N, K, ldc, act);
}
static void gemm2(const __half* Ah, const __half* Al, const __half* B, const float* bias,
                  __half* Chf, int M, int N, int K, int ldc, int act)
{
    dim3 grid((N + 127) / 128, M / 128);
    gemm_f16<2><<<grid, 256, SMEM2>>>(Ah, Al, B, bias, nullptr, Chf, M, N, K, ldc, act);
}

extern "C" void kernel_launch(void* const* d_in, const int* in_sizes, int n_in,
                              void* d_out, int out_size)
{
    const float* x            = (const float*)d_in[0];
    const float* union_feat   = (const float*)d_in[1];
    const int*   sub_idx      = (const int*)d_in[2];
    const int*   obj_idx      = (const int*)d_in[3];
    const float* w_obj_unary  = (const float*)d_in[4];
    const float* b_obj_unary  = (const float*)d_in[5];
    const float* w_edge_unary = (const float*)d_in[6];
    const float* b_edge_unary = (const float*)d_in[7];
    const float* node_w_ih    = (const float*)d_in[8];
    const float* node_w_hh    = (const float*)d_in[9];
    const float* node_b_ih    = (const float*)d_in[10];
    const float* node_b_hh    = (const float*)d_in[11];
    const float* edge_w_ih    = (const float*)d_in[12];
    const float* edge_w_hh    = (const float*)d_in[13];
    const float* edge_b_ih    = (const float*)d_in[14];
    const float* edge_b_hh    = (const float*)d_in[15];
    const float* w_sub_g      = (const float*)d_in[16];
    const float* b_sub_g      = (const float*)d_in[17];
    const float* w_obj_g      = (const float*)d_in[18];
    const float* b_obj_g      = (const float*)d_in[19];
    const float* w_out_g      = (const float*)d_in[20];
    const float* b_out_g      = (const float*)d_in[21];
    const float* w_in_g       = (const float*)d_in[22];
    const float* b_in_g       = (const float*)d_in[23];
    const float* w_obj_fc     = (const float*)d_in[24];
    const float* b_obj_fc     = (const float*)d_in[25];
    const float* w_rel_fc     = (const float*)d_in[26];
    const float* b_rel_fc     = (const float*)d_in[27];

    static int smem_set = 0;
    if (!smem_set) {
        cudaFuncSetAttribute(gemm_f16<1>, cudaFuncAttributeMaxDynamicSharedMemorySize, SMEM1);
        cudaFuncSetAttribute(gemm_f16<2>, cudaFuncAttributeMaxDynamicSharedMemorySize, SMEM2);
        smem_set = 1;
    }

    float* vert = symaddr(g_vert);
    float* eA   = symaddr(g_edgeA);
    float* eB   = symaddr(g_edgeB);
    float* vctx = symaddr(g_vctx);
    __half* gi  = symaddr(g_gi);
    __half* gh  = symaddr(g_gh);

    __half* uh = symaddr(g_uh);  __half* ul = symaddr(g_ul);
    __half* xh = symaddr(g_xh);  __half* xl = symaddr(g_xl);
    __half* rep1 = symaddr(g_rep1);
    __half* sA = symaddr(g_sA);
    __half* sB = symaddr(g_sB);
    __half* vh = symaddr(g_vh);
    __half* vch = symaddr(g_vch);
    __half* weu = symaddr(g_weu);
    __half* wou = symaddr(g_wou);
    __half* wnih = symaddr(g_wnih);
    __half* wnhh = symaddr(g_wnhh);
    __half* weih = symaddr(g_weih);
    __half* wehh = symaddr(g_wehh);
    __half* wof = symaddr(g_wof);
    __half* wrf = symaddr(g_wrf);

    const int TPB = 256;
    const int nObjH = N_OBJ * H;
    const int nRelH = N_REL * H;

    // launch 0,1: inputs for union GEMM; launch 2: union GEMM (ncu -s lands here)
    split2(union_feat, uh, ul, (long long)N_REL * POOL);    // 0
    cvt(w_edge_unary, weu, (long long)H * POOL);            // 1
    gemm2(uh, ul, weu, b_edge_unary, rep1, N_REL, H, POOL, H, 1);   // 2

    split2(x, xh, xl, (long long)N_OBJ * IN_DIM);
    cvt(w_obj_unary, wou, (long long)H * IN_DIM);
    gemm2(xh, xl, wou, b_obj_unary, vch, N_OBJ, H, IN_DIM, H, 0);

    cvt(node_w_ih, wnih, 3 * H * H);
    cvt(node_w_hh, wnhh, 3 * H * H);
    cvt(edge_w_ih, weih, 3 * H * H);
    cvt(edge_w_hh, wehh, 3 * H * H);
    cvt(w_obj_fc, wof, (long long)OBJ_CLS * H);
    cvt(w_rel_fc, wrf, (long long)REL_CLS * H);

    // ---- initial GRUs (h = 0) ----
    gemm1(vch, wnih, node_b_ih, nullptr, gi, N_OBJ, 3 * H, H, 3 * H, 0);
    gru_combine4_h0<<<(nObjH / 4 + TPB - 1) / TPB, TPB>>>(gi, node_b_hh, vert, vh, nObjH / 4);

    gemm1(rep1, weih, edge_b_ih, nullptr, gi, N_REL, 3 * H, H, 3 * H, 0);
    gru_combine4_h0<<<(nRelH / 4 + TPB - 1) / TPB, TPB>>>(gi, edge_b_hh, eA, sA, nRelH / 4);

    for (int it = 0; it < NUM_ITER; it++) {
        cudaMemsetAsync(vctx, 0, (size_t)nObjH * sizeof(float));
        relation_kernel<<<N_REL / RPB, 128>>>(vert, eA, sub_idx, obj_idx,
                                              w_sub_g, b_sub_g, w_obj_g, b_obj_g,
                                              w_out_g, b_out_g, w_in_g, b_in_g,
                                              rep1, vctx);

        // edge GRU: eB = GRU(msg, eA)
        gemm1(rep1, weih, edge_b_ih, nullptr, gi, N_REL, 3 * H, H, 3 * H, 0);
        gemm1(sA, wehh, edge_b_hh, nullptr, gh, N_REL, 3 * H, H, 3 * H, 0);
        gru_combine4<<<(nRelH / 4 + TPB - 1) / TPB, TPB>>>(gi, gh, eA, eB, sB, nRelH / 4);

        // node GRU: vert = GRU(vctx, vert)
        cvt(vctx, vch, nObjH);
        gemm1(vch, wnih, node_b_ih, nullptr, gi, N_OBJ, 3 * H, H, 3 * H, 0);
        gemm1(vh, wnhh, node_b_hh, nullptr, gh, N_OBJ, 3 * H, H, 3 * H, 0);
        gru_combine4<<<(nObjH / 4 + TPB - 1) / TPB, TPB>>>(gi, gh, vert, vert, vh, nObjH / 4);

        { float* t1 = eA; eA = eB; eB = t1; }
        { __half* t2 = sA; sA = sB; sB = t2; }
    }

    // ---- output heads (fp32 out) ----
    float* out = (float*)d_out;
    gemm1(vh, wof, b_obj_fc, out, nullptr, N_OBJ, OBJ_CLS, H, OBJ_CLS, 0);
    gemm1(sA, wrf, b_rel_fc, out + (size_t)N_OBJ * OBJ_CLS, nullptr,
          N_REL, REL_CLS, H, REL_CLS, 0);
}

// round 13
// speedup vs baseline: 5.0075x; 1.1032x over previous
#include <cuda_runtime.h>
#include <cuda_fp16.h>
#include <math.h>
#include <stdint.h>

#define H        512
#define IN_DIM   4096
#define POOL     4096
#define N_OBJ    8192
#define N_REL    65536
#define OBJ_CLS  151
#define REL_CLS  51
#define NUM_ITER 3
#define RPB      16

// ======================= scratch (device globals) ============================
__device__ float g_vert[N_OBJ * H];
__device__ float g_edgeA[N_REL * H];
__device__ float g_edgeB[N_REL * H];
__device__ float g_vctx[N_OBJ * H];
__device__ __half g_gi[N_REL * 3 * H];
__device__ __half g_gh[N_REL * 3 * H];

// union features: single fp16 plane; x: split-2
__device__ __half g_uh[(size_t)N_REL * POOL];
__device__ __half g_xh[(size_t)N_OBJ * IN_DIM];
__device__ __half g_xl[(size_t)N_OBJ * IN_DIM];
// single fp16 planes
__device__ __half g_rep1[N_REL * H];             // rel_rep / msg
__device__ __half g_sA[N_REL * H];               // edge plane buf A
__device__ __half g_sB[N_REL * H];               // edge plane buf B
__device__ __half g_vh[N_OBJ * H];               // vert plane
__device__ __half g_vch[N_OBJ * H];              // obj_rep / vctx plane
// weights single fp16
__device__ __half g_weu[H * POOL];
__device__ __half g_wou[H * IN_DIM];
__device__ __half g_wnih[3 * H * H];
__device__ __half g_wnhh[3 * H * H];
__device__ __half g_weih[3 * H * H];
__device__ __half g_wehh[3 * H * H];
__device__ __half g_wof[OBJ_CLS * H];
__device__ __half g_wrf[REL_CLS * H];

// ======================= conversion kernels ==================================
__global__ void split2_fp16(const float* __restrict__ in, __half* __restrict__ hi,
                            __half* __restrict__ lo, long long n4)
{
    long long i = (long long)blockIdx.x * blockDim.x + threadIdx.x;
    if (i >= n4) return;
    float4 v = ((const float4*)in)[i];
    __half2 h01, h23, l01, l23;
    h01.x = __float2half_rn(v.x); h01.y = __float2half_rn(v.y);
    h23.x = __float2half_rn(v.z); h23.y = __float2half_rn(v.w);
    l01.x = __float2half_rn(v.x - __half2float(h01.x));
    l01.y = __float2half_rn(v.y - __half2float(h01.y));
    l23.x = __float2half_rn(v.z - __half2float(h23.x));
    l23.y = __float2half_rn(v.w - __half2float(h23.y));
    ((__half2*)hi)[2 * i] = h01; ((__half2*)hi)[2 * i + 1] = h23;
    ((__half2*)lo)[2 * i] = l01; ((__half2*)lo)[2 * i + 1] = l23;
}

__global__ void cvt_fp16(const float* __restrict__ in, __half* __restrict__ out, long long n4)
{
    long long i = (long long)blockIdx.x * blockDim.x + threadIdx.x;
    if (i >= n4) return;
    float4 v = ((const float4*)in)[i];
    __half2 a, b;
    a.x = __float2half_rn(v.x); a.y = __float2half_rn(v.y);
    b.x = __float2half_rn(v.z); b.y = __float2half_rn(v.w);
    ((__half2*)out)[2 * i] = a; ((__half2*)out)[2 * i + 1] = b;
}

// ======================= HMMA fp16 GEMM (1- or 2-pass A) =====================
#define NSTAGE 4
#define SLAB_BYTES 16384

__device__ __forceinline__ uint32_t smem_u32(const void* p) {
    uint32_t a;
    asm("{ .reg .u64 t; cvta.to.shared.u64 t, %1; cvt.u32.u64 %0, t; }" : "=r"(a) : "l"(p));
    return a;
}
__device__ __forceinline__ void cpa16z(uint32_t dst, const void* src, uint32_t sz) {
    asm volatile("cp.async.cg.shared.global [%0], [%1], 16, %2;"
                 :: "r"(dst), "l"(src), "r"(sz) : "memory");
}
__device__ __forceinline__ void ldsm4(uint32_t* r, uint32_t addr) {
    asm volatile("ldmatrix.sync.aligned.m8n8.x4.shared.b16 {%0,%1,%2,%3}, [%4];"
        : "=r"(r[0]), "=r"(r[1]), "=r"(r[2]), "=r"(r[3]) : "r"(addr));
}
__device__ __forceinline__ void mma_f16(float* d, const uint32_t* a, const uint32_t* b) {
    asm volatile("mma.sync.aligned.m16n8k16.row.col.f32.f16.f16.f32 "
        "{%0,%1,%2,%3}, {%4,%5,%6,%7}, {%8,%9}, {%0,%1,%2,%3};"
        : "+f"(d[0]), "+f"(d[1]), "+f"(d[2]), "+f"(d[3])
        : "r"(a[0]), "r"(a[1]), "r"(a[2]), "r"(a[3]), "r"(b[0]), "r"(b[1]));
}

__device__ __forceinline__ void load_slab(uint32_t sbase, const __half* __restrict__ g,
                                          int row0, int K, int k0, int tid, int limit)
{
#pragma unroll
    for (int i = 0; i < 4; i++) {
        int c = tid + i * 256;
        int r = c >> 3, c16 = c & 7;
        uint32_t boff = (uint32_t)(r * 128 + c16 * 16);
        uint32_t dst = sbase + (boff ^ ((boff >> 3) & 0x70));
        uint32_t sz = (row0 + r < limit) ? 16u : 0u;
        cpa16z(dst, g + (size_t)(row0 + r) * K + k0 + c16 * 8, sz);
    }
}

template <int NPASS>
__global__ __launch_bounds__(256, 1)
void gemm_f16(const __half* __restrict__ Ah, const __half* __restrict__ Al,
              const __half* __restrict__ B, const float* __restrict__ bias,
              float* __restrict__ Cf, __half* __restrict__ Chf,
              int M, int N, int K, int ldc, int act)
{
    constexpr int STB = (NPASS + 1) * SLAB_BYTES;
    extern __shared__ char dsm[];
    const int tid  = threadIdx.x;
    const int wid  = tid >> 5;
    const int lane = tid & 31;
    const int warp_m = wid & 1;
    const int warp_n = wid >> 1;
    uint32_t base = (smem_u32(dsm) + 1023u) & ~1023u;

    const int arow = blockIdx.y * 128;
    const int brow = blockIdx.x * 128;
    const int nch  = K >> 6;

    uint32_t aro[4], asx[4];
#pragma unroll
    for (int mt = 0; mt < 4; mt++) {
        int r = warp_m * 64 + mt * 16 + (lane & 15);
        aro[mt] = (uint32_t)(r * 128);
        asx[mt] = (uint32_t)((r & 7) << 4);
    }
    uint32_t akh = (uint32_t)((lane >> 4) * 16);
    uint32_t bro[2], bsx[2];
#pragma unroll
    for (int p = 0; p < 2; p++) {
        int r = warp_n * 32 + p * 16 + (lane & 7) + ((lane >> 4) << 3);
        bro[p] = (uint32_t)(r * 128);
        bsx[p] = (uint32_t)((r & 7) << 4);
    }
    uint32_t bkh = (uint32_t)(((lane >> 3) & 1) * 16);

    float acc[4][4][4];
#pragma unroll
    for (int i = 0; i < 4; i++)
#pragma unroll
        for (int j = 0; j < 4; j++)
#pragma unroll
            for (int q = 0; q < 4; q++) acc[i][j][q] = 0.f;

    {
        int pre = (nch < NSTAGE) ? nch : NSTAGE;
        for (int i = 0; i < pre; i++) {
            uint32_t st = base + i * STB;
            load_slab(st, Ah, arow, K, i * 64, tid, M);
            if (NPASS == 2) load_slab(st + SLAB_BYTES, Al, arow, K, i * 64, tid, M);
            load_slab(st + NPASS * SLAB_BYTES, B, brow, K, i * 64, tid, N);
            asm volatile("cp.async.commit_group;" ::: "memory");
        }
    }

    for (int i = 0; i < nch; i++) {
        int committed = (nch < i + NSTAGE) ? nch : (i + NSTAGE);
        int pending = committed - i - 1;
        if (pending >= 3)      asm volatile("cp.async.wait_group 3;" ::: "memory");
        else if (pending == 2) asm volatile("cp.async.wait_group 2;" ::: "memory");
        else if (pending == 1) asm volatile("cp.async.wait_group 1;" ::: "memory");
        else                   asm volatile("cp.async.wait_group 0;" ::: "memory");
        __syncthreads();

        uint32_t st = base + (uint32_t)(i % NSTAGE) * STB;
        uint32_t aH = st, bB = st + NPASS * SLAB_BYTES;
#pragma unroll
        for (int ks = 0; ks < 4; ks++) {
            uint32_t ka = (uint32_t)(ks * 32) + akh;
            uint32_t kb = (uint32_t)(ks * 32) + bkh;
            uint32_t ah[4][4], b[2][4];
#pragma unroll
            for (int mt = 0; mt < 4; mt++) ldsm4(ah[mt], aH + aro[mt] + (ka ^ asx[mt]));
#pragma unroll
            for (int p = 0; p < 2; p++)    ldsm4(b[p], bB + bro[p] + (kb ^ bsx[p]));
#pragma unroll
            for (int mt = 0; mt < 4; mt++)
#pragma unroll
                for (int nt = 0; nt < 4; nt++)
                    mma_f16(acc[mt][nt], ah[mt], &b[nt >> 1][(nt & 1) * 2]);
            if (NPASS == 2) {
                uint32_t al[4][4];
                uint32_t aL = st + SLAB_BYTES;
#pragma unroll
                for (int mt = 0; mt < 4; mt++) ldsm4(al[mt], aL + aro[mt] + (ka ^ asx[mt]));
#pragma unroll
                for (int mt = 0; mt < 4; mt++)
#pragma unroll
                    for (int nt = 0; nt < 4; nt++)
                        mma_f16(acc[mt][nt], al[mt], &b[nt >> 1][(nt & 1) * 2]);
            }
        }

        __syncthreads();
        if (i + NSTAGE < nch) {
            int j = i + NSTAGE;
            load_slab(st, Ah, arow, K, j * 64, tid, M);
            if (NPASS == 2) load_slab(st + SLAB_BYTES, Al, arow, K, j * 64, tid, M);
            load_slab(st + NPASS * SLAB_BYTES, B, brow, K, j * 64, tid, N);
            asm volatile("cp.async.commit_group;" ::: "memory");
        }
    }

    const int qrow = lane >> 2;
    const int qcol = (lane & 3) * 2;
#pragma unroll
    for (int mt = 0; mt < 4; mt++) {
        int m0 = arow + warp_m * 64 + mt * 16 + qrow;
#pragma unroll
        for (int nt = 0; nt < 4; nt++) {
            int n0 = brow + warp_n * 32 + nt * 8 + qcol;
            float b0 = (n0 < N) ? bias[n0] : 0.f;
            float b1 = (n0 + 1 < N) ? bias[n0 + 1] : 0.f;
            float v00 = acc[mt][nt][0] + b0, v01 = acc[mt][nt][1] + b1;
            float v10 = acc[mt][nt][2] + b0, v11 = acc[mt][nt][3] + b1;
            if (act) {
                v00 = fmaxf(v00, 0.f); v01 = fmaxf(v01, 0.f);
                v10 = fmaxf(v10, 0.f); v11 = fmaxf(v11, 0.f);
            }
            if (Cf) {
                if (n0 < N) {
                    Cf[(size_t)m0 * ldc + n0] = v00;
                    Cf[(size_t)(m0 + 8) * ldc + n0] = v10;
                }
                if (n0 + 1 < N) {
                    Cf[(size_t)m0 * ldc + n0 + 1] = v01;
                    Cf[(size_t)(m0 + 8) * ldc + n0 + 1] = v11;
                }
            } else {
                *(__half2*)(Chf + (size_t)m0 * ldc + n0)       = __floats2half2_rn(v00, v01);
                *(__half2*)(Chf + (size_t)(m0 + 8) * ldc + n0) = __floats2half2_rn(v10, v11);
            }
        }
    }
}

// ======================= GRU elementwise =====================================
__device__ __forceinline__ float sigm(float x) { return 1.f / (1.f + __expf(-x)); }
__device__ __forceinline__ float tanh_f(float x) { return 2.f * sigm(2.f * x) - 1.f; }

__device__ __forceinline__ float4 ld4h(const __half* p) {
    __half2 a = *(const __half2*)p;
    __half2 b = *(const __half2*)(p + 2);
    float2 fa = __half22float2(a), fb = __half22float2(b);
    return make_float4(fa.x, fa.y, fb.x, fb.y);
}
__device__ __forceinline__ void st4h(float4 v, __half* p) {
    *(__half2*)p       = __floats2half2_rn(v.x, v.y);
    *(__half2*)(p + 2) = __floats2half2_rn(v.z, v.w);
}

__global__ void gru_combine4(const __half* __restrict__ gi, const __half* __restrict__ gh,
                             const float* __restrict__ h, float* __restrict__ out,
                             __half* __restrict__ ohi, int n4)
{
    int i4 = blockIdx.x * blockDim.x + threadIdx.x;
    if (i4 >= n4) return;
    int idx = i4 * 4;
    int m = idx >> 9;
    int j = idx & (H - 1);
    const __half* gib = gi + (size_t)m * (3 * H);
    const __half* ghb = gh + (size_t)m * (3 * H);
    float4 ir = ld4h(gib + j);
    float4 iz = ld4h(gib + H + j);
    float4 in_ = ld4h(gib + 2 * H + j);
    float4 hr = ld4h(ghb + j);
    float4 hz = ld4h(ghb + H + j);
    float4 hn = ld4h(ghb + 2 * H + j);
    float4 hv = *(const float4*)(h + idx);
    float4 o;
    { float r = sigm(ir.x + hr.x), z = sigm(iz.x + hz.x);
      o.x = (1.f - z) * tanh_f(in_.x + r * hn.x) + z * hv.x; }
    { float r = sigm(ir.y + hr.y), z = sigm(iz.y + hz.y);
      o.y = (1.f - z) * tanh_f(in_.y + r * hn.y) + z * hv.y; }
    { float r = sigm(ir.z + hr.z), z = sigm(iz.z + hz.z);
      o.z = (1.f - z) * tanh_f(in_.z + r * hn.z) + z * hv.z; }
    { float r = sigm(ir.w + hr.w), z = sigm(iz.w + hz.w);
      o.w = (1.f - z) * tanh_f(in_.w + r * hn.w) + z * hv.w; }
    *(float4*)(out + idx) = o;
    st4h(o, ohi + idx);
}

__global__ void gru_combine4_h0(const __half* __restrict__ gi, const float* __restrict__ b_hh,
                                float* __restrict__ out, __half* __restrict__ ohi, int n4)
{
    int i4 = blockIdx.x * blockDim.x + threadIdx.x;
    if (i4 >= n4) return;
    int idx = i4 * 4;
    int m = idx >> 9;
    int j = idx & (H - 1);
    const __half* gib = gi + (size_t)m * (3 * H);
    float4 ir = ld4h(gib + j);
    float4 iz = ld4h(gib + H + j);
    float4 in_ = ld4h(gib + 2 * H + j);
    float4 hr = *(const float4*)(b_hh + j);
    float4 hz = *(const float4*)(b_hh + H + j);
    float4 hn = *(const float4*)(b_hh + 2 * H + j);
    float4 o;
    { float r = sigm(ir.x + hr.x), z = sigm(iz.x + hz.x);
      o.x = (1.f - z) * tanh_f(in_.x + r * hn.x); }
    { float r = sigm(ir.y + hr.y), z = sigm(iz.y + hz.y);
      o.y = (1.f - z) * tanh_f(in_.y + r * hn.y); }
    { float r = sigm(ir.z + hr.z), z = sigm(iz.z + hz.z);
      o.z = (1.f - z) * tanh_f(in_.z + r * hn.z); }
    { float r = sigm(ir.w + hr.w), z = sigm(iz.w + hz.w);
      o.w = (1.f - z) * tanh_f(in_.w + r * hn.w); }
    *(float4*)(out + idx) = o;
    st4h(o, ohi + idx);
}

// ======================= fused relation kernel ===============================
__device__ __forceinline__ float dot4(float4 a, float4 b) {
    return a.x * b.x + a.y * b.y + a.z * b.z + a.w * b.w;
}

__global__ __launch_bounds__(128)
void relation_kernel(const float* __restrict__ vert, const float* __restrict__ edge,
                     const int* __restrict__ sub_idx, const int* __restrict__ obj_idx,
                     const float* __restrict__ w_sub, const float* __restrict__ b_sub,
                     const float* __restrict__ w_obj, const float* __restrict__ b_obj,
                     const float* __restrict__ w_out, const float* __restrict__ b_out,
                     const float* __restrict__ w_in,  const float* __restrict__ b_in,
                     __half* __restrict__ msg, float* __restrict__ vctx)
{
    const int t = threadIdx.x;
    const int warp = t >> 5, lane = t & 31;

    float4 ws1 = ((const float4*)w_sub)[t];
    float4 ws2 = ((const float4*)(w_sub + H))[t];
    float4 wo1 = ((const float4*)w_obj)[t];
    float4 wo2 = ((const float4*)(w_obj + H))[t];
    float4 wu1 = ((const float4*)w_out)[t];
    float4 wu2 = ((const float4*)(w_out + H))[t];
    float4 wi1 = ((const float4*)w_in)[t];
    float4 wi2 = ((const float4*)(w_in + H))[t];
    float bb4 = (t == 0) ? b_sub[0] : (t == 1) ? b_obj[0] : (t == 2) ? b_out[0] :
                (t == 3) ? b_in[0] : 0.f;

    __shared__ float red[4][4];
    __shared__ float gates[4];

    const int rbase = blockIdx.x * RPB;
#pragma unroll 1
    for (int rr = 0; rr < RPB; rr++) {
        const int r = rbase + rr;
        const int si = sub_idx[r];
        const int oi = obj_idx[r];

        float4 s4 = ((const float4*)(vert + (size_t)si * H))[t];
        float4 o4 = ((const float4*)(vert + (size_t)oi * H))[t];
        float4 e4 = ((const float4*)(edge + (size_t)r * H))[t];

        float d0 = dot4(s4, ws1) + dot4(e4, ws2);
        float d1 = dot4(o4, wo1) + dot4(e4, wo2);
        float d2 = dot4(s4, wu1) + dot4(e4, wu2);
        float d3 = dot4(o4, wi1) + dot4(e4, wi2);

#pragma unroll
        for (int off = 16; off > 0; off >>= 1) {
            d0 += __shfl_down_sync(0xFFFFFFFFu, d0, off);
            d1 += __shfl_down_sync(0xFFFFFFFFu, d1, off);
            d2 += __shfl_down_sync(0xFFFFFFFFu, d2, off);
            d3 += __shfl_down_sync(0xFFFFFFFFu, d3, off);
        }
        if (lane == 0) {
            red[warp][0] = d0; red[warp][1] = d1; red[warp][2] = d2; red[warp][3] = d3;
        }
        __syncthreads();
        if (t < 4) {
            float v = red[0][t] + red[1][t] + red[2][t] + red[3][t];
            gates[t] = sigm(v + bb4);
        }
        __syncthreads();

        float gs = gates[0], go = gates[1], gu = gates[2], gn = gates[3];
        __syncthreads();

        float4 m4;
        m4.x = gs * s4.x + go * o4.x;
        m4.y = gs * s4.y + go * o4.y;
        m4.z = gs * s4.z + go * o4.z;
        m4.w = gs * s4.w + go * o4.w;
        st4h(m4, msg + (size_t)r * H + t * 4);

        float* vs = vctx + (size_t)si * H + t * 4;
        atomicAdd(vs + 0, gu * e4.x);
        atomicAdd(vs + 1, gu * e4.y);
        atomicAdd(vs + 2, gu * e4.z);
        atomicAdd(vs + 3, gu * e4.w);
        float* vo = vctx + (size_t)oi * H + t * 4;
        atomicAdd(vo + 0, gn * e4.x);
        atomicAdd(vo + 1, gn * e4.y);
        atomicAdd(vo + 2, gn * e4.z);
        atomicAdd(vo + 3, gn * e4.w);
    }
}

// ======================= host orchestration ==================================
template <typename T>
static T* symaddr(const T* sym) {
    void* p = nullptr;
    cudaGetSymbolAddress(&p, (const void*)sym);
    return (T*)p;
}

static void split2(const float* in, __half* hi, __half* lo, long long n) {
    long long n4 = n >> 2;
    split2_fp16<<<(unsigned)((n4 + 255) / 256), 256>>>(in, hi, lo, n4);
}
static void cvt(const float* in, __half* out, long long n) {
    long long n4 = n >> 2;
    cvt_fp16<<<(unsigned)((n4 + 255) / 256), 256>>>(in, out, n4);
}

#define SMEM1 (NSTAGE * 2 * SLAB_BYTES + 1024)
#define SMEM2 (NSTAGE * 3 * SLAB_BYTES + 1024)

static void gemm1(const __half* A, const __half* B, const float* bias,
                  float* Cf, __half* Chf, int M, int N, int K, int ldc, int act)
{
    dim3 grid((N + 127) / 128, M / 128);
    gemm_f16<1><<<grid, 256, SMEM1>>>(A, nullptr, B, bias, Cf, Chf, M, N, K, ldc, act);
}
static void gemm2(const __half* Ah, const __half* Al, const __half* B, const float* bias,
                  __half* Chf, int M, int N, int K, int ldc, int act)
{
    dim3 grid((N + 127) / 128, M / 128);
    gemm_f16<2><<<grid, 256, SMEM2>>>(Ah, Al, B, bias, nullptr, Chf, M, N, K, ldc, act);
}

extern "C" void kernel_launch(void* const* d_in, const int* in_sizes, int n_in,
                              void* d_out, int out_size)
{
    const float* x            = (const float*)d_in[0];
    const float* union_feat   = (const float*)d_in[1];
    const int*   sub_idx      = (const int*)d_in[2];
    const int*   obj_idx      = (const int*)d_in[3];
    const float* w_obj_unary  = (const float*)d_in[4];
    const float* b_obj_unary  = (const float*)d_in[5];
    const float* w_edge_unary = (const float*)d_in[6];
    const float* b_edge_unary = (const float*)d_in[7];
    const float* node_w_ih    = (const float*)d_in[8];
    const float* node_w_hh    = (const float*)d_in[9];
    const float* node_b_ih    = (const float*)d_in[10];
    const float* node_b_hh    = (const float*)d_in[11];
    const float* edge_w_ih    = (const float*)d_in[12];
    const float* edge_w_hh    = (const float*)d_in[13];
    const float* edge_b_ih    = (const float*)d_in[14];
    const float* edge_b_hh    = (const float*)d_in[15];
    const float* w_sub_g      = (const float*)d_in[16];
    const float* b_sub_g      = (const float*)d_in[17];
    const float* w_obj_g      = (const float*)d_in[18];
    const float* b_obj_g      = (const float*)d_in[19];
    const float* w_out_g      = (const float*)d_in[20];
    const float* b_out_g      = (const float*)d_in[21];
    const float* w_in_g       = (const float*)d_in[22];
    const float* b_in_g       = (const float*)d_in[23];
    const float* w_obj_fc     = (const float*)d_in[24];
    const float* b_obj_fc     = (const float*)d_in[25];
    const float* w_rel_fc     = (const float*)d_in[26];
    const float* b_rel_fc     = (const float*)d_in[27];

    static int smem_set = 0;
    if (!smem_set) {
        cudaFuncSetAttribute(gemm_f16<1>, cudaFuncAttributeMaxDynamicSharedMemorySize, SMEM1);
        cudaFuncSetAttribute(gemm_f16<2>, cudaFuncAttributeMaxDynamicSharedMemorySize, SMEM2);
        smem_set = 1;
    }

    float* vert = symaddr(g_vert);
    float* eA   = symaddr(g_edgeA);
    float* eB   = symaddr(g_edgeB);
    float* vctx = symaddr(g_vctx);
    __half* gi  = symaddr(g_gi);
    __half* gh  = symaddr(g_gh);

    __half* uh = symaddr(g_uh);
    __half* xh = symaddr(g_xh);  __half* xl = symaddr(g_xl);
    __half* rep1 = symaddr(g_rep1);
    __half* sA = symaddr(g_sA);
    __half* sB = symaddr(g_sB);
    __half* vh = symaddr(g_vh);
    __half* vch = symaddr(g_vch);
    __half* weu = symaddr(g_weu);
    __half* wou = symaddr(g_wou);
    __half* wnih = symaddr(g_wnih);
    __half* wnhh = symaddr(g_wnhh);
    __half* weih = symaddr(g_weih);
    __half* wehh = symaddr(g_wehh);
    __half* wof = symaddr(g_wof);
    __half* wrf = symaddr(g_wrf);

    const int TPB = 256;
    const int nObjH = N_OBJ * H;
    const int nRelH = N_REL * H;

    // union projection: single fp16 plane now
    cvt(union_feat, uh, (long long)N_REL * POOL);
    cvt(w_edge_unary, weu, (long long)H * POOL);
    gemm1(uh, weu, b_edge_unary, nullptr, rep1, N_REL, H, POOL, H, 1);

    split2(x, xh, xl, (long long)N_OBJ * IN_DIM);
    cvt(w_obj_unary, wou, (long long)H * IN_DIM);
    gemm2(xh, xl, wou, b_obj_unary, vch, N_OBJ, H, IN_DIM, H, 0);

    cvt(node_w_ih, wnih, 3 * H * H);
    cvt(node_w_hh, wnhh, 3 * H * H);
    cvt(edge_w_ih, weih, 3 * H * H);
    cvt(edge_w_hh, wehh, 3 * H * H);
    cvt(w_obj_fc, wof, (long long)OBJ_CLS * H);
    cvt(w_rel_fc, wrf, (long long)REL_CLS * H);

    // ---- initial GRUs (h = 0) ----
    gemm1(vch, wnih, node_b_ih, nullptr, gi, N_OBJ, 3 * H, H, 3 * H, 0);
    gru_combine4_h0<<<(nObjH / 4 + TPB - 1) / TPB, TPB>>>(gi, node_b_hh, vert, vh, nObjH / 4);

    gemm1(rep1, weih, edge_b_ih, nullptr, gi, N_REL, 3 * H, H, 3 * H, 0);
    gru_combine4_h0<<<(nRelH / 4 + TPB - 1) / TPB, TPB>>>(gi, edge_b_hh, eA, sA, nRelH / 4);

    for (int it = 0; it < NUM_ITER; it++) {
        cudaMemsetAsync(vctx, 0, (size_t)nObjH * sizeof(float));
        relation_kernel<<<N_REL / RPB, 128>>>(vert, eA, sub_idx, obj_idx,
                                              w_sub_g, b_sub_g, w_obj_g, b_obj_g,
                                              w_out_g, b_out_g, w_in_g, b_in_g,
                                              rep1, vctx);

        // edge GRU: eB = GRU(msg, eA)
        gemm1(rep1, weih, edge_b_ih, nullptr, gi, N_REL, 3 * H, H, 3 * H, 0);
        gemm1(sA, wehh, edge_b_hh, nullptr, gh, N_REL, 3 * H, H, 3 * H, 0);
        gru_combine4<<<(nRelH / 4 + TPB - 1) / TPB, TPB>>>(gi, gh, eA, eB, sB, nRelH / 4);

        // node GRU: vert = GRU(vctx, vert)
        cvt(vctx, vch, nObjH);
        gemm1(vch, wnih, node_b_ih, nullptr, gi, N_OBJ, 3 * H, H, 3 * H, 0);
        gemm1(vh, wnhh, node_b_hh, nullptr, gh, N_OBJ, 3 * H, H, 3 * H, 0);
        gru_combine4<<<(nObjH / 4 + TPB - 1) / TPB, TPB>>>(gi, gh, vert, vert, vh, nObjH / 4);

        { float* t1 = eA; eA = eB; eB = t1; }
        { __half* t2 = sA; sA = sB; sB = t2; }
    }

    // ---- output heads (fp32 out) ----
    float* out = (float*)d_out;
    gemm1(vh, wof, b_obj_fc, out, nullptr, N_OBJ, OBJ_CLS, H, OBJ_CLS, 0);
    gemm1(sA, wrf, b_rel_fc, out + (size_t)N_OBJ * OBJ_CLS, nullptr,
          N_REL, REL_CLS, H, REL_CLS, 0);
}

// round 16
// speedup vs baseline: 5.5383x; 1.1060x over previous
#include <cuda_runtime.h>
#include <cuda_fp16.h>
#include <math.h>
#include <stdint.h>

#define H        512
#define IN_DIM   4096
#define POOL     4096
#define N_OBJ    8192
#define N_REL    65536
#define OBJ_CLS  151
#define REL_CLS  51
#define NUM_ITER 3
#define RPB      16
#define EW       1024          // interleaved activation row width (msg|edge)

// ======================= scratch (device globals) ============================
__device__ float g_vert[N_OBJ * H];
__device__ float g_edgeA[N_REL * H];
__device__ float g_edgeB[N_REL * H];
__device__ float g_vctx[N_OBJ * H];

// interleaved activation buffers: cols [0,512)=input half, [512,1024)=state half
__device__ __half g_EA[(size_t)N_REL * EW];
__device__ __half g_EB[(size_t)N_REL * EW];
__device__ __half g_EN[(size_t)N_OBJ * EW];

// GEMM outputs
__device__ __half g_rz[(size_t)N_REL * EW];    // edge rz sums
__device__ __half g_ihn[(size_t)N_REL * EW];   // edge in|hn
__device__ __half g_rzN[N_OBJ * EW];
__device__ __half g_ihnN[N_OBJ * EW];
__device__ __half g_gi[N_REL * 3 * H];         // init gi (edge)
__device__ __half g_giN[N_OBJ * 3 * H];        // init gi (node)

// inputs fp16
__device__ __half g_uh[(size_t)N_REL * POOL];
__device__ __half g_xh[(size_t)N_OBJ * IN_DIM];
__device__ __half g_xl[(size_t)N_OBJ * IN_DIM];
// weights fp16
__device__ __half g_weu[H * POOL];
__device__ __half g_wou[H * IN_DIM];
__device__ __half g_wnih[3 * H * H];           // full node W_ih (init + n-part)
__device__ __half g_wnhh[3 * H * H];           // full node W_hh (n-part)
__device__ __half g_weih[3 * H * H];
__device__ __half g_wehh[3 * H * H];
__device__ __half g_werz[EW * EW];             // packed edge rz weight [1024 x 1024]
__device__ __half g_wnrz[EW * EW];             // packed node rz weight
__device__ float  g_brz_e[EW];
__device__ float  g_brz_n[EW];
__device__ __half g_wof[OBJ_CLS * H];
__device__ __half g_wrf[REL_CLS * H];

// ======================= conversion / packing kernels ========================
__global__ void split2_fp16(const float* __restrict__ in, __half* __restrict__ hi,
                            __half* __restrict__ lo, long long n4)
{
    long long i = (long long)blockIdx.x * blockDim.x + threadIdx.x;
    if (i >= n4) return;
    float4 v = ((const float4*)in)[i];
    __half2 h01, h23, l01, l23;
    h01.x = __float2half_rn(v.x); h01.y = __float2half_rn(v.y);
    h23.x = __float2half_rn(v.z); h23.y = __float2half_rn(v.w);
    l01.x = __float2half_rn(v.x - __half2float(h01.x));
    l01.y = __float2half_rn(v.y - __half2float(h01.y));
    l23.x = __float2half_rn(v.z - __half2float(h23.x));
    l23.y = __float2half_rn(v.w - __half2float(h23.y));
    ((__half2*)hi)[2 * i] = h01; ((__half2*)hi)[2 * i + 1] = h23;
    ((__half2*)lo)[2 * i] = l01; ((__half2*)lo)[2 * i + 1] = l23;
}

__global__ void cvt_fp16(const float* __restrict__ in, __half* __restrict__ out, long long n4)
{
    long long i = (long long)blockIdx.x * blockDim.x + threadIdx.x;
    if (i >= n4) return;
    float4 v = ((const float4*)in)[i];
    ((__half2*)out)[2 * i]     = __floats2half2_rn(v.x, v.y);
    ((__half2*)out)[2 * i + 1] = __floats2half2_rn(v.z, v.w);
}

// fp32 [m*512+j] -> fp16 at out[m*1024 + j]
__global__ void cvt_plane(const float* __restrict__ in, __half* __restrict__ out, int n4)
{
    int i4 = blockIdx.x * blockDim.x + threadIdx.x;
    if (i4 >= n4) return;
    int idx = i4 * 4;
    int m = idx >> 9, j = idx & (H - 1);
    float4 v = *(const float4*)(in + idx);
    __half* p = out + (size_t)m * EW + j;
    *(__half2*)p       = __floats2half2_rn(v.x, v.y);
    *(__half2*)(p + 2) = __floats2half2_rn(v.z, v.w);
}

// pack rz weight: wrz[n*1024+k] = k<512 ? wih[n*512+k] : whh[n*512+k-512], n<1024
__global__ void pack_rz(const float* __restrict__ wih, const float* __restrict__ whh,
                        const float* __restrict__ bih, const float* __restrict__ bhh,
                        __half* __restrict__ wrz, float* __restrict__ brz)
{
    int i = blockIdx.x * blockDim.x + threadIdx.x;   // 1024*1024
    int n = i >> 10, k = i & 1023;
    float v = (k < 512) ? wih[n * 512 + k] : whh[n * 512 + (k - 512)];
    wrz[i] = __float2half_rn(v);
    if (k == 0) brz[n] = bih[n] + bhh[n];
}

// ======================= HMMA fp16 GEMM ======================================
#define NSTAGE 4
#define SLAB_BYTES 16384

__device__ __forceinline__ uint32_t smem_u32(const void* p) {
    uint32_t a;
    asm("{ .reg .u64 t; cvta.to.shared.u64 t, %1; cvt.u32.u64 %0, t; }" : "=r"(a) : "l"(p));
    return a;
}
__device__ __forceinline__ void cpa16z(uint32_t dst, const void* src, uint32_t sz) {
    asm volatile("cp.async.cg.shared.global [%0], [%1], 16, %2;"
                 :: "r"(dst), "l"(src), "r"(sz) : "memory");
}
__device__ __forceinline__ void ldsm4(uint32_t* r, uint32_t addr) {
    asm volatile("ldmatrix.sync.aligned.m8n8.x4.shared.b16 {%0,%1,%2,%3}, [%4];"
        : "=r"(r[0]), "=r"(r[1]), "=r"(r[2]), "=r"(r[3]) : "r"(addr));
}
__device__ __forceinline__ void mma_f16(float* d, const uint32_t* a, const uint32_t* b) {
    asm volatile("mma.sync.aligned.m16n8k16.row.col.f32.f16.f16.f32 "
        "{%0,%1,%2,%3}, {%4,%5,%6,%7}, {%8,%9}, {%0,%1,%2,%3};"
        : "+f"(d[0]), "+f"(d[1]), "+f"(d[2]), "+f"(d[3])
        : "r"(a[0]), "r"(a[1]), "r"(a[2]), "r"(a[3]), "r"(b[0]), "r"(b[1]));
}

__device__ __forceinline__ void load_slab(uint32_t sbase, const __half* __restrict__ g,
                                          int row0, int lda, int k0, int tid, int limit)
{
#pragma unroll
    for (int i = 0; i < 4; i++) {
        int c = tid + i * 256;
        int r = c >> 3, c16 = c & 7;
        uint32_t boff = (uint32_t)(r * 128 + c16 * 16);
        uint32_t dst = sbase + (boff ^ ((boff >> 3) & 0x70));
        uint32_t sz = (row0 + r < limit) ? 16u : 0u;
        cpa16z(dst, g + (size_t)(row0 + r) * lda + k0 + c16 * 8, sz);
    }
}

template <int NPASS>
__global__ __launch_bounds__(256, 1)
void gemm_f16(const __half* __restrict__ Ah, const __half* __restrict__ Al,
              const __half* __restrict__ B, const float* __restrict__ bias,
              float* __restrict__ Cf, __half* __restrict__ Chf,
              int M, int N, int K, int lda, int ldc, int act)
{
    constexpr int STB = (NPASS + 1) * SLAB_BYTES;
    extern __shared__ char dsm[];
    const int tid  = threadIdx.x;
    const int wid  = tid >> 5;
    const int lane = tid & 31;
    const int warp_m = wid & 1;
    const int warp_n = wid >> 1;
    uint32_t base = (smem_u32(dsm) + 1023u) & ~1023u;

    const int arow = blockIdx.y * 128;
    const int brow = blockIdx.x * 128;
    const int nch  = K >> 6;

    uint32_t aro[4], asx[4];
#pragma unroll
    for (int mt = 0; mt < 4; mt++) {
        int r = warp_m * 64 + mt * 16 + (lane & 15);
        aro[mt] = (uint32_t)(r * 128);
        asx[mt] = (uint32_t)((r & 7) << 4);
    }
    uint32_t akh = (uint32_t)((lane >> 4) * 16);
    uint32_t bro[2], bsx[2];
#pragma unroll
    for (int p = 0; p < 2; p++) {
        int r = warp_n * 32 + p * 16 + (lane & 7) + ((lane >> 4) << 3);
        bro[p] = (uint32_t)(r * 128);
        bsx[p] = (uint32_t)((r & 7) << 4);
    }
    uint32_t bkh = (uint32_t)(((lane >> 3) & 1) * 16);

    float acc[4][4][4];
#pragma unroll
    for (int i = 0; i < 4; i++)
#pragma unroll
        for (int j = 0; j < 4; j++)
#pragma unroll
            for (int q = 0; q < 4; q++) acc[i][j][q] = 0.f;

    {
        int pre = (nch < NSTAGE) ? nch : NSTAGE;
        for (int i = 0; i < pre; i++) {
            uint32_t st = base + i * STB;
            load_slab(st, Ah, arow, lda, i * 64, tid, M);
            if (NPASS == 2) load_slab(st + SLAB_BYTES, Al, arow, lda, i * 64, tid, M);
            load_slab(st + NPASS * SLAB_BYTES, B, brow, K, i * 64, tid, N);
            asm volatile("cp.async.commit_group;" ::: "memory");
        }
    }

    for (int i = 0; i < nch; i++) {
        int committed = (nch < i + NSTAGE) ? nch : (i + NSTAGE);
        int pending = committed - i - 1;
        if (pending >= 3)      asm volatile("cp.async.wait_group 3;" ::: "memory");
        else if (pending == 2) asm volatile("cp.async.wait_group 2;" ::: "memory");
        else if (pending == 1) asm volatile("cp.async.wait_group 1;" ::: "memory");
        else                   asm volatile("cp.async.wait_group 0;" ::: "memory");
        __syncthreads();

        uint32_t st = base + (uint32_t)(i % NSTAGE) * STB;
        uint32_t aH = st, bB = st + NPASS * SLAB_BYTES;
#pragma unroll
        for (int ks = 0; ks < 4; ks++) {
            uint32_t ka = (uint32_t)(ks * 32) + akh;
            uint32_t kb = (uint32_t)(ks * 32) + bkh;
            uint32_t ah[4][4], b[2][4];
#pragma unroll
            for (int mt = 0; mt < 4; mt++) ldsm4(ah[mt], aH + aro[mt] + (ka ^ asx[mt]));
#pragma unroll
            for (int p = 0; p < 2; p++)    ldsm4(b[p], bB + bro[p] + (kb ^ bsx[p]));
#pragma unroll
            for (int mt = 0; mt < 4; mt++)
#pragma unroll
                for (int nt = 0; nt < 4; nt++)
                    mma_f16(acc[mt][nt], ah[mt], &b[nt >> 1][(nt & 1) * 2]);
            if (NPASS == 2) {
                uint32_t al[4][4];
                uint32_t aL = st + SLAB_BYTES;
#pragma unroll
                for (int mt = 0; mt < 4; mt++) ldsm4(al[mt], aL + aro[mt] + (ka ^ asx[mt]));
#pragma unroll
                for (int mt = 0; mt < 4; mt++)
#pragma unroll
                    for (int nt = 0; nt < 4; nt++)
                        mma_f16(acc[mt][nt], al[mt], &b[nt >> 1][(nt & 1) * 2]);
            }
        }

        __syncthreads();
        if (i + NSTAGE < nch) {
            int j = i + NSTAGE;
            load_slab(st, Ah, arow, lda, j * 64, tid, M);
            if (NPASS == 2) load_slab(st + SLAB_BYTES, Al, arow, lda, j * 64, tid, M);
            load_slab(st + NPASS * SLAB_BYTES, B, brow, K, j * 64, tid, N);
            asm volatile("cp.async.commit_group;" ::: "memory");
        }
    }

    const int qrow = lane >> 2;
    const int qcol = (lane & 3) * 2;
#pragma unroll
    for (int mt = 0; mt < 4; mt++) {
        int m0 = arow + warp_m * 64 + mt * 16 + qrow;
#pragma unroll
        for (int nt = 0; nt < 4; nt++) {
            int n0 = brow + warp_n * 32 + nt * 8 + qcol;
            float b0 = (n0 < N) ? bias[n0] : 0.f;
            float b1 = (n0 + 1 < N) ? bias[n0 + 1] : 0.f;
            float v00 = acc[mt][nt][0] + b0, v01 = acc[mt][nt][1] + b1;
            float v10 = acc[mt][nt][2] + b0, v11 = acc[mt][nt][3] + b1;
            if (act) {
                v00 = fmaxf(v00, 0.f); v01 = fmaxf(v01, 0.f);
                v10 = fmaxf(v10, 0.f); v11 = fmaxf(v11, 0.f);
            }
            if (Cf) {
                if (n0 < N) {
                    Cf[(size_t)m0 * ldc + n0] = v00;
                    Cf[(size_t)(m0 + 8) * ldc + n0] = v10;
                }
                if (n0 + 1 < N) {
                    Cf[(size_t)m0 * ldc + n0 + 1] = v01;
                    Cf[(size_t)(m0 + 8) * ldc + n0 + 1] = v11;
                }
            } else {
                *(__half2*)(Chf + (size_t)m0 * ldc + n0)       = __floats2half2_rn(v00, v01);
                *(__half2*)(Chf + (size_t)(m0 + 8) * ldc + n0) = __floats2half2_rn(v10, v11);
            }
        }
    }
}

// ======================= GRU elementwise =====================================
__device__ __forceinline__ float sigm(float x) { return 1.f / (1.f + __expf(-x)); }
__device__ __forceinline__ float tanh_f(float x) { return 2.f * sigm(2.f * x) - 1.f; }

__device__ __forceinline__ float4 ld4h(const __half* p) {
    __half2 a = *(const __half2*)p;
    __half2 b = *(const __half2*)(p + 2);
    float2 fa = __half22float2(a), fb = __half22float2(b);
    return make_float4(fa.x, fa.y, fb.x, fb.y);
}
__device__ __forceinline__ void st4h(float4 v, __half* p) {
    *(__half2*)p       = __floats2half2_rn(v.x, v.y);
    *(__half2*)(p + 2) = __floats2half2_rn(v.z, v.w);
}

// loop combine: rz [m*1024 + j]=r, [+512]=z; ihn [m*1024+j]=in, [+512]=hn
// plane = state-half base (already offset by 512), stride 1024.
__global__ void gru_rz4(const __half* __restrict__ rz, const __half* __restrict__ ihn,
                        const float* __restrict__ h, float* __restrict__ out,
                        __half* __restrict__ plane, int n4)
{
    int i4 = blockIdx.x * blockDim.x + threadIdx.x;
    if (i4 >= n4) return;
    int idx = i4 * 4;
    int m = idx >> 9, j = idx & (H - 1);
    size_t rb = (size_t)m * EW + j;
    float4 rr = ld4h(rz + rb);
    float4 zz = ld4h(rz + rb + 512);
    float4 in_ = ld4h(ihn + rb);
    float4 hn = ld4h(ihn + rb + 512);
    float4 hv = *(const float4*)(h + idx);
    float4 o;
    { float r = sigm(rr.x), z = sigm(zz.x);
      o.x = (1.f - z) * tanh_f(in_.x + r * hn.x) + z * hv.x; }
    { float r = sigm(rr.y), z = sigm(zz.y);
      o.y = (1.f - z) * tanh_f(in_.y + r * hn.y) + z * hv.y; }
    { float r = sigm(rr.z), z = sigm(zz.z);
      o.z = (1.f - z) * tanh_f(in_.z + r * hn.z) + z * hv.z; }
    { float r = sigm(rr.w), z = sigm(zz.w);
      o.w = (1.f - z) * tanh_f(in_.w + r * hn.w) + z * hv.w; }
    *(float4*)(out + idx) = o;
    st4h(o, plane + (size_t)m * EW + j);
}

// init combine (h = 0): gi dense [m*1536 + {j, 512+j, 1024+j}], gh = b_hh
__global__ void gru_h04(const __half* __restrict__ gi, const float* __restrict__ b_hh,
                        float* __restrict__ out, __half* __restrict__ plane, int n4)
{
    int i4 = blockIdx.x * blockDim.x + threadIdx.x;
    if (i4 >= n4) return;
    int idx = i4 * 4;
    int m = idx >> 9, j = idx & (H - 1);
    const __half* gib = gi + (size_t)m * (3 * H);
    float4 ir = ld4h(gib + j);
    float4 iz = ld4h(gib + H + j);
    float4 in_ = ld4h(gib + 2 * H + j);
    float4 hr = *(const float4*)(b_hh + j);
    float4 hz = *(const float4*)(b_hh + H + j);
    float4 hn = *(const float4*)(b_hh + 2 * H + j);
    float4 o;
    { float r = sigm(ir.x + hr.x), z = sigm(iz.x + hz.x);
      o.x = (1.f - z) * tanh_f(in_.x + r * hn.x); }
    { float r = sigm(ir.y + hr.y), z = sigm(iz.y + hz.y);
      o.y = (1.f - z) * tanh_f(in_.y + r * hn.y); }
    { float r = sigm(ir.z + hr.z), z = sigm(iz.z + hz.z);
      o.z = (1.f - z) * tanh_f(in_.z + r * hn.z); }
    { float r = sigm(ir.w + hr.w), z = sigm(iz.w + hz.w);
      o.w = (1.f - z) * tanh_f(in_.w + r * hn.w); }
    *(float4*)(out + idx) = o;
    st4h(o, plane + (size_t)m * EW + j);
}

// ======================= fused relation kernel ===============================
__device__ __forceinline__ float dot4(float4 a, float4 b) {
    return a.x * b.x + a.y * b.y + a.z * b.z + a.w * b.w;
}

__global__ __launch_bounds__(128)
void relation_kernel(const float* __restrict__ vert, const float* __restrict__ edge,
                     const int* __restrict__ sub_idx, const int* __restrict__ obj_idx,
                     const float* __restrict__ w_sub, const float* __restrict__ b_sub,
                     const float* __restrict__ w_obj, const float* __restrict__ b_obj,
                     const float* __restrict__ w_out, const float* __restrict__ b_out,
                     const float* __restrict__ w_in,  const float* __restrict__ b_in,
                     __half* __restrict__ msg, float* __restrict__ vctx)
{
    const int t = threadIdx.x;
    const int warp = t >> 5, lane = t & 31;

    float4 ws1 = ((const float4*)w_sub)[t];
    float4 ws2 = ((const float4*)(w_sub + H))[t];
    float4 wo1 = ((const float4*)w_obj)[t];
    float4 wo2 = ((const float4*)(w_obj + H))[t];
    float4 wu1 = ((const float4*)w_out)[t];
    float4 wu2 = ((const float4*)(w_out + H))[t];
    float4 wi1 = ((const float4*)w_in)[t];
    float4 wi2 = ((const float4*)(w_in + H))[t];
    float bb4 = (t == 0) ? b_sub[0] : (t == 1) ? b_obj[0] : (t == 2) ? b_out[0] :
                (t == 3) ? b_in[0] : 0.f;

    __shared__ float red[4][4];
    __shared__ float gates[4];

    const int rbase = blockIdx.x * RPB;
#pragma unroll 1
    for (int rr = 0; rr < RPB; rr++) {
        const int r = rbase + rr;
        const int si = sub_idx[r];
        const int oi = obj_idx[r];

        float4 s4 = ((const float4*)(vert + (size_t)si * H))[t];
        float4 o4 = ((const float4*)(vert + (size_t)oi * H))[t];
        float4 e4 = ((const float4*)(edge + (size_t)r * H))[t];

        float d0 = dot4(s4, ws1) + dot4(e4, ws2);
        float d1 = dot4(o4, wo1) + dot4(e4, wo2);
        float d2 = dot4(s4, wu1) + dot4(e4, wu2);
        float d3 = dot4(o4, wi1) + dot4(e4, wi2);

#pragma unroll
        for (int off = 16; off > 0; off >>= 1) {
            d0 += __shfl_down_sync(0xFFFFFFFFu, d0, off);
            d1 += __shfl_down_sync(0xFFFFFFFFu, d1, off);
            d2 += __shfl_down_sync(0xFFFFFFFFu, d2, off);
            d3 += __shfl_down_sync(0xFFFFFFFFu, d3, off);
        }
        if (lane == 0) {
            red[warp][0] = d0; red[warp][1] = d1; red[warp][2] = d2; red[warp][3] = d3;
        }
        __syncthreads();
        if (t < 4) {
            float v = red[0][t] + red[1][t] + red[2][t] + red[3][t];
            gates[t] = sigm(v + bb4);
        }
        __syncthreads();

        float gs = gates[0], go = gates[1], gu = gates[2], gn = gates[3];
        __syncthreads();

        float4 m4;
        m4.x = gs * s4.x + go * o4.x;
        m4.y = gs * s4.y + go * o4.y;
        m4.z = gs * s4.z + go * o4.z;
        m4.w = gs * s4.w + go * o4.w;
        st4h(m4, msg + (size_t)r * EW + t * 4);

        float* vs = vctx + (size_t)si * H + t * 4;
        atomicAdd(vs + 0, gu * e4.x);
        atomicAdd(vs + 1, gu * e4.y);
        atomicAdd(vs + 2, gu * e4.z);
        atomicAdd(vs + 3, gu * e4.w);
        float* vo = vctx + (size_t)oi * H + t * 4;
        atomicAdd(vo + 0, gn * e4.x);
        atomicAdd(vo + 1, gn * e4.y);
        atomicAdd(vo + 2, gn * e4.z);
        atomicAdd(vo + 3, gn * e4.w);
    }
}

// ======================= host orchestration ==================================
template <typename T>
static T* symaddr(const T* sym) {
    void* p = nullptr;
    cudaGetSymbolAddress(&p, (const void*)sym);
    return (T*)p;
}

#define SMEM1 (NSTAGE * 2 * SLAB_BYTES + 1024)
#define SMEM2 (NSTAGE * 3 * SLAB_BYTES + 1024)

static void gemm1(cudaStream_t s, const __half* A, const __half* B, const float* bias,
                  float* Cf, __half* Chf, int M, int N, int K, int lda, int ldc, int act)
{
    dim3 grid((N + 127) / 128, M / 128);
    gemm_f16<1><<<grid, 256, SMEM1, s>>>(A, nullptr, B, bias, Cf, Chf, M, N, K, lda, ldc, act);
}
static void gemm2s(cudaStream_t s, const __half* Ah, const __half* Al, const __half* B,
                   const float* bias, __half* Chf, int M, int N, int K, int lda, int ldc, int act)
{
    dim3 grid((N + 127) / 128, M / 128);
    gemm_f16<2><<<grid, 256, SMEM2, s>>>(Ah, Al, B, bias, nullptr, Chf, M, N, K, lda, ldc, act);
}
static void split2(cudaStream_t s, const float* in, __half* hi, __half* lo, long long n) {
    long long n4 = n >> 2;
    split2_fp16<<<(unsigned)((n4 + 255) / 256), 256, 0, s>>>(in, hi, lo, n4);
}
static void cvt(cudaStream_t s, const float* in, __half* out, long long n) {
    long long n4 = n >> 2;
    cvt_fp16<<<(unsigned)((n4 + 255) / 256), 256, 0, s>>>(in, out, n4);
}

extern "C" void kernel_launch(void* const* d_in, const int* in_sizes, int n_in,
                              void* d_out, int out_size)
{
    const float* x            = (const float*)d_in[0];
    const float* union_feat   = (const float*)d_in[1];
    const int*   sub_idx      = (const int*)d_in[2];
    const int*   obj_idx      = (const int*)d_in[3];
    const float* w_obj_unary  = (const float*)d_in[4];
    const float* b_obj_unary  = (const float*)d_in[5];
    const float* w_edge_unary = (const float*)d_in[6];
    const float* b_edge_unary = (const float*)d_in[7];
    const float* node_w_ih    = (const float*)d_in[8];
    const float* node_w_hh    = (const float*)d_in[9];
    const float* node_b_ih    = (const float*)d_in[10];
    const float* node_b_hh    = (const float*)d_in[11];
    const float* edge_w_ih    = (const float*)d_in[12];
    const float* edge_w_hh    = (const float*)d_in[13];
    const float* edge_b_ih    = (const float*)d_in[14];
    const float* edge_b_hh    = (const float*)d_in[15];
    const float* w_sub_g      = (const float*)d_in[16];
    const float* b_sub_g      = (const float*)d_in[17];
    const float* w_obj_g      = (const float*)d_in[18];
    const float* b_obj_g      = (const float*)d_in[19];
    const float* w_out_g      = (const float*)d_in[20];
    const float* b_out_g      = (const float*)d_in[21];
    const float* w_in_g       = (const float*)d_in[22];
    const float* b_in_g       = (const float*)d_in[23];
    const float* w_obj_fc     = (const float*)d_in[24];
    const float* b_obj_fc     = (const float*)d_in[25];
    const float* w_rel_fc     = (const float*)d_in[26];
    const float* b_rel_fc     = (const float*)d_in[27];

    static int inited = 0;
    static cudaStream_t s2;
    static cudaEvent_t evStart, evWeih, evInit2, evRel, evNode;
    if (!inited) {
        cudaFuncSetAttribute(gemm_f16<1>, cudaFuncAttributeMaxDynamicSharedMemorySize, SMEM1);
        cudaFuncSetAttribute(gemm_f16<2>, cudaFuncAttributeMaxDynamicSharedMemorySize, SMEM2);
        cudaStreamCreateWithFlags(&s2, cudaStreamNonBlocking);
        cudaEventCreateWithFlags(&evStart, cudaEventDisableTiming);
        cudaEventCreateWithFlags(&evWeih, cudaEventDisableTiming);
        cudaEventCreateWithFlags(&evInit2, cudaEventDisableTiming);
        cudaEventCreateWithFlags(&evRel, cudaEventDisableTiming);
        cudaEventCreateWithFlags(&evNode, cudaEventDisableTiming);
        inited = 1;
    }
    cudaStream_t s0 = 0;

    float* vert = symaddr(g_vert);
    float* eA   = symaddr(g_edgeA);
    float* eB   = symaddr(g_edgeB);
    float* vctx = symaddr(g_vctx);
    __half* EA  = symaddr(g_EA);
    __half* EBv = symaddr(g_EB);
    __half* EN  = symaddr(g_EN);
    __half* rz  = symaddr(g_rz);
    __half* ihn = symaddr(g_ihn);
    __half* rzN = symaddr(g_rzN);
    __half* ihnN = symaddr(g_ihnN);
    __half* gi  = symaddr(g_gi);
    __half* giN = symaddr(g_giN);
    __half* uh = symaddr(g_uh);
    __half* xh = symaddr(g_xh);  __half* xl = symaddr(g_xl);
    __half* weu = symaddr(g_weu);
    __half* wou = symaddr(g_wou);
    __half* wnih = symaddr(g_wnih);
    __half* wnhh = symaddr(g_wnhh);
    __half* weih = symaddr(g_weih);
    __half* wehh = symaddr(g_wehh);
    __half* werz = symaddr(g_werz);
    __half* wnrz = symaddr(g_wnrz);
    float* brz_e = symaddr(g_brz_e);
    float* brz_n = symaddr(g_brz_n);
    __half* wof = symaddr(g_wof);
    __half* wrf = symaddr(g_wrf);

    const int TPB = 256;
    const int nObjH = N_OBJ * H;
    const int nRelH = N_REL * H;

    // ---------------- setup: fork s2 ----------------
    cudaEventRecord(evStart, s0);
    cudaStreamWaitEvent(s2, evStart, 0);

    // s0: union projection chain
    cvt(s0, union_feat, uh, (long long)N_REL * POOL);
    cvt(s0, w_edge_unary, weu, (long long)H * POOL);
    gemm1(s0, uh, weu, b_edge_unary, nullptr, EA, N_REL, H, POOL, POOL, EW, 1);

    // s2: obj-side + weight prep (overlaps union GEMM)
    split2(s2, x, xh, xl, (long long)N_OBJ * IN_DIM);
    cvt(s2, w_obj_unary, wou, (long long)H * IN_DIM);
    cvt(s2, edge_w_ih, weih, 3 * H * H);
    cudaEventRecord(evWeih, s2);
    gemm2s(s2, xh, xl, wou, b_obj_unary, EN, N_OBJ, H, IN_DIM, IN_DIM, EW, 0);
    cvt(s2, edge_w_hh, wehh, 3 * H * H);
    cvt(s2, node_w_ih, wnih, 3 * H * H);
    cvt(s2, node_w_hh, wnhh, 3 * H * H);
    pack_rz<<<4096, 256, 0, s2>>>(edge_w_ih, edge_w_hh, edge_b_ih, edge_b_hh, werz, brz_e);
    pack_rz<<<4096, 256, 0, s2>>>(node_w_ih, node_w_hh, node_b_ih, node_b_hh, wnrz, brz_n);
    cvt(s2, w_obj_fc, wof, (long long)OBJ_CLS * H);
    cvt(s2, w_rel_fc, wrf, (long long)REL_CLS * H);
    // s2: init node GRU (h=0)
    gemm1(s2, EN, wnih, node_b_ih, nullptr, giN, N_OBJ, 3 * H, H, EW, 3 * H, 0);
    gru_h04<<<(nObjH / 4 + TPB - 1) / TPB, TPB, 0, s2>>>(giN, node_b_hh, vert, EN + 512, nObjH / 4);
    cudaEventRecord(evInit2, s2);

    // s0: init edge GRU (h=0) — needs weih from s2
    cudaStreamWaitEvent(s0, evWeih, 0);
    gemm1(s0, EA, weih, edge_b_ih, nullptr, gi, N_REL, 3 * H, H, EW, 3 * H, 0);
    gru_h04<<<(nRelH / 4 + TPB - 1) / TPB, TPB, 0, s0>>>(gi, edge_b_hh, eA, EA + 512, nRelH / 4);

    cudaStreamWaitEvent(s0, evInit2, 0);

    __half* Ecur = EA;
    __half* Enxt = EBv;

    for (int it = 0; it < NUM_ITER; it++) {
        if (it > 0) cudaStreamWaitEvent(s0, evNode, 0);
        cudaMemsetAsync(vctx, 0, (size_t)nObjH * sizeof(float), s0);
        relation_kernel<<<N_REL / RPB, 128, 0, s0>>>(vert, eA, sub_idx, obj_idx,
                                                     w_sub_g, b_sub_g, w_obj_g, b_obj_g,
                                                     w_out_g, b_out_g, w_in_g, b_in_g,
                                                     Ecur, vctx);
        cudaEventRecord(evRel, s0);

        // s0: edge GRU (fused rz + in + hn)
        gemm1(s0, Ecur, werz, brz_e, nullptr, rz, N_REL, EW, EW, EW, EW, 0);
        gemm1(s0, Ecur, weih + (size_t)1024 * H, edge_b_ih + 1024, nullptr, ihn,
              N_REL, H, H, EW, EW, 0);
        gemm1(s0, Ecur + 512, wehh + (size_t)1024 * H, edge_b_hh + 1024, nullptr, ihn + 512,
              N_REL, H, H, EW, EW, 0);
        gru_rz4<<<(nRelH / 4 + TPB - 1) / TPB, TPB, 0, s0>>>(rz, ihn, eA, eB, Enxt + 512, nRelH / 4);

        // s2: node GRU (overlaps edge GEMMs)
        cudaStreamWaitEvent(s2, evRel, 0);
        cvt_plane<<<(nObjH / 4 + TPB - 1) / TPB, TPB, 0, s2>>>(vctx, EN, nObjH / 4);
        gemm1(s2, EN, wnrz, brz_n, nullptr, rzN, N_OBJ, EW, EW, EW, EW, 0);
        gemm1(s2, EN, wnih + (size_t)1024 * H, node_b_ih + 1024, nullptr, ihnN,
              N_OBJ, H, H, EW, EW, 0);
        gemm1(s2, EN + 512, wnhh + (size_t)1024 * H, node_b_hh + 1024, nullptr, ihnN + 512,
              N_OBJ, H, H, EW, EW, 0);
        gru_rz4<<<(nObjH / 4 + TPB - 1) / TPB, TPB, 0, s2>>>(rzN, ihnN, vert, vert, EN + 512, nObjH / 4);
        cudaEventRecord(evNode, s2);

        { float* t1 = eA; eA = eB; eB = t1; }
        { __half* t2 = Ecur; Ecur = Enxt; Enxt = t2; }
    }
    cudaStreamWaitEvent(s0, evNode, 0);

    // ---- output heads (fp32 out) ----
    float* out = (float*)d_out;
    gemm1(s0, EN + 512, wof, b_obj_fc, out, nullptr, N_OBJ, OBJ_CLS, H, EW, OBJ_CLS, 0);
    gemm1(s0, Ecur + 512, wrf, b_rel_fc, out + (size_t)N_OBJ * OBJ_CLS, nullptr,
          N_REL, REL_CLS, H, EW, REL_CLS, 0);
}